// round 1
// baseline (speedup 1.0000x reference)
#include <cuda_runtime.h>
#include <math_constants.h>
#include <cstddef>

#define Bn   2
#define Sn   2048
#define Hn   16
#define DKn  64
#define Dm   1024
#define QR   6
#define RK   2
#define Mrows (Bn*Sn)

// ---------------- scratch (static device allocations) ----------------
__device__ float g_Aq[Mrows*Hn*QR];     // (B*S, 96)
__device__ float g_Ak[Mrows*Hn*RK];     // (B*S, 32)
__device__ float g_Av[Mrows*Hn*RK];     // (B*S, 32)
__device__ float g_Bq[Mrows*QR*DKn];    // (B*S, 384)
__device__ float g_Bk[Mrows*RK*DKn];    // (B*S, 128)
__device__ float g_Bv[Mrows*RK*DKn];    // (B*S, 128)
__device__ float g_qh[Bn*Hn*Sn*DKn];    // (B,H,S,D) scaled by 1/QR
__device__ float g_kh[Bn*Hn*Sn*DKn];    // (B,H,S,D) scaled by 1/RK
__device__ float g_vh[Bn*Hn*Sn*DKn];    // (B,H,S,D) scaled by 1/RK
__device__ float g_att[Mrows*Dm];       // (B*S, 1024) attention output pre-Wo

// ---------------- generic fp32 tiled GEMM: C = A(MxK) @ B(KxN) ----------------
__global__ __launch_bounds__(256) void gemm_kernel(
    const float* __restrict__ A, const float* __restrict__ Bw,
    float* __restrict__ C, int M, int N, int K)
{
    __shared__ float As[16][65];   // [k][m] transposed
    __shared__ float Bs[16][64];   // [k][n]

    const int t  = threadIdx.x;
    const int tx = t % 16, ty = t / 16;
    const int n0 = blockIdx.x * 64, m0 = blockIdx.y * 64;

    const int a_col = t % 16;   // k offset
    const int a_row = t / 16;   // m offset base
    const int b_col = t % 64;   // n offset
    const int b_row = t / 64;   // k offset base

    float acc[4][4] = {};

    for (int k0 = 0; k0 < K; k0 += 16) {
        #pragma unroll
        for (int i = 0; i < 4; i++) {
            As[a_col][a_row + 16*i] =
                A[(size_t)(m0 + a_row + 16*i) * K + k0 + a_col];
        }
        const int n = n0 + b_col;
        #pragma unroll
        for (int i = 0; i < 4; i++) {
            Bs[b_row + 4*i][b_col] =
                (n < N) ? Bw[(size_t)(k0 + b_row + 4*i) * N + n] : 0.f;
        }
        __syncthreads();

        #pragma unroll
        for (int kk = 0; kk < 16; kk++) {
            float a[4], bb[4];
            #pragma unroll
            for (int i = 0; i < 4; i++) a[i]  = As[kk][ty*4 + i];
            #pragma unroll
            for (int j = 0; j < 4; j++) bb[j] = Bs[kk][tx*4 + j];
            #pragma unroll
            for (int i = 0; i < 4; i++)
                #pragma unroll
                for (int j = 0; j < 4; j++)
                    acc[i][j] += a[i] * bb[j];
        }
        __syncthreads();
    }

    #pragma unroll
    for (int i = 0; i < 4; i++) {
        const int m = m0 + ty*4 + i;
        #pragma unroll
        for (int j = 0; j < 4; j++) {
            const int n = n0 + tx*4 + j;
            if (n < N) C[(size_t)m * N + n] = acc[i][j];
        }
    }
}

// ---------------- rank contraction + rotary + scaling ----------------
// qh[b,h,s,d] = rot( sum_r A_q[b,s,h,r] * B_q[b,s,r,d] ) / QR, etc.
// (rotary commutes with the r-contraction: same cos/sin for all r)
__global__ __launch_bounds__(256) void combine_kernel()
{
    const int m = blockIdx.x;            // b*S + s
    const int b = m / Sn, s = m % Sn;
    const int t = threadIdx.x;

    __shared__ float sAq[Hn*QR], sAk[Hn*RK], sAv[Hn*RK];
    __shared__ float sBq[QR*DKn], sBk[RK*DKn], sBv[RK*DKn];
    __shared__ float sCos[32], sSin[32];

    for (int i = t; i < Hn*QR;  i += 256) sAq[i] = g_Aq[m*Hn*QR  + i];
    for (int i = t; i < Hn*RK;  i += 256) sAk[i] = g_Ak[m*Hn*RK  + i];
    for (int i = t; i < Hn*RK;  i += 256) sAv[i] = g_Av[m*Hn*RK  + i];
    for (int i = t; i < QR*DKn; i += 256) sBq[i] = g_Bq[m*QR*DKn + i];
    for (int i = t; i < RK*DKn; i += 256) sBk[i] = g_Bk[m*RK*DKn + i];
    for (int i = t; i < RK*DKn; i += 256) sBv[i] = g_Bv[m*RK*DKn + i];
    if (t < 32) {
        // inv_freq = 10000^(-(2t)/64)
        float inv = expf(-((float)(2*t) / 64.f) * logf(10000.0f));
        float fr  = (float)s * inv;
        sCos[t] = cosf(fr);
        sSin[t] = sinf(fr);
    }
    __syncthreads();

    for (int idx = t; idx < Hn*DKn; idx += 256) {
        const int h = idx >> 6, d = idx & 63, dl = d & 31;
        const float c = sCos[dl], sn = sSin[dl];
        const size_t obase = ((size_t)(b*Hn + h) * Sn + s) * 64 + d;

        // q path (rank 6)
        float r1 = 0.f, r2 = 0.f;
        #pragma unroll
        for (int r = 0; r < QR; r++) {
            const float a = sAq[h*QR + r];
            r1 += a * sBq[r*64 + dl];
            r2 += a * sBq[r*64 + dl + 32];
        }
        float vq = (d < 32) ? (r1*c + r2*sn) : (-r1*sn + r2*c);
        g_qh[obase] = vq * (1.0f / QR);

        // k path (rank 2)
        r1 = 0.f; r2 = 0.f;
        #pragma unroll
        for (int r = 0; r < RK; r++) {
            const float a = sAk[h*RK + r];
            r1 += a * sBk[r*64 + dl];
            r2 += a * sBk[r*64 + dl + 32];
        }
        float vk = (d < 32) ? (r1*c + r2*sn) : (-r1*sn + r2*c);
        g_kh[obase] = vk * 0.5f;

        // v path (rank 2, no rotary)
        float vv = 0.f;
        #pragma unroll
        for (int r = 0; r < RK; r++)
            vv += sAv[h*RK + r] * sBv[r*64 + d];
        g_vh[obase] = vv * 0.5f;
    }
}

// ---------------- causal flash attention (fp32) ----------------
// grid: (S/64, H, B), block: 256
// Br=64 queries, Bc=32 keys per tile. Thread t: row r=t/4, score cols
// c0=(t%4)*8..+7, output dims d0=(t%4)*16..+15. Row quad = 4 adjacent lanes.
__global__ __launch_bounds__(256) void flash_kernel()
{
    const int qt = blockIdx.x, h = blockIdx.y, b = blockIdx.z;
    const int q0 = qt * 64;

    const float* Qp = g_qh + (size_t)(b*Hn + h) * Sn * 64;
    const float* Kp = g_kh + (size_t)(b*Hn + h) * Sn * 64;
    const float* Vp = g_vh + (size_t)(b*Hn + h) * Sn * 64;

    __shared__ float Qs[64][65];
    __shared__ float Ks[32][65];
    __shared__ float Vs[32][65];
    __shared__ float Ps[64][33];

    const int t  = threadIdx.x;
    const int r  = t / 4;
    const int cg = t % 4;
    const int c0 = cg * 8;
    const int d0 = cg * 16;

    for (int i = t; i < 64*64; i += 256)
        Qs[i >> 6][i & 63] = Qp[q0*64 + i];

    float O[16] = {};
    float mrow = -CUDART_INF_F, l = 0.f;

    const int nk = 2*qt + 2;   // key tiles of 32 covering [0, q0+64)
    const int qi = q0 + r;
    const float scale = 1.0f / (float)DKn;

    for (int kt = 0; kt < nk; kt++) {
        const int k0 = kt * 32;
        __syncthreads();   // protect Qs (1st iter) and Ks/Vs reuse
        for (int i = t; i < 32*64; i += 256) {
            Ks[i >> 6][i & 63] = Kp[k0*64 + i];
            Vs[i >> 6][i & 63] = Vp[k0*64 + i];
        }
        __syncthreads();

        // S tile: 8 scores per thread
        float sv[8] = {};
        for (int d = 0; d < 64; d++) {
            const float qv = Qs[r][d];
            #pragma unroll
            for (int j = 0; j < 8; j++)
                sv[j] += qv * Ks[c0 + j][d];
        }
        #pragma unroll
        for (int j = 0; j < 8; j++) {
            const int kj = k0 + c0 + j;
            sv[j] = (kj <= qi) ? sv[j] * scale : -CUDART_INF_F;
        }

        // row max over the quad
        float mloc = sv[0];
        #pragma unroll
        for (int j = 1; j < 8; j++) mloc = fmaxf(mloc, sv[j]);
        mloc = fmaxf(mloc, __shfl_xor_sync(0xffffffffu, mloc, 1));
        mloc = fmaxf(mloc, __shfl_xor_sync(0xffffffffu, mloc, 2));
        const float mnew  = fmaxf(mrow, mloc);
        const float alpha = __expf(mrow - mnew);

        float psum = 0.f;
        #pragma unroll
        for (int j = 0; j < 8; j++) {
            const float p = __expf(sv[j] - mnew);
            Ps[r][c0 + j] = p;
            psum += p;
        }
        psum += __shfl_xor_sync(0xffffffffu, psum, 1);
        psum += __shfl_xor_sync(0xffffffffu, psum, 2);
        l = l * alpha + psum;
        mrow = mnew;

        #pragma unroll
        for (int j = 0; j < 16; j++) O[j] *= alpha;

        __syncwarp();  // Ps written/read within the same warp rows
        for (int c = 0; c < 32; c++) {
            const float p = Ps[r][c];
            #pragma unroll
            for (int j = 0; j < 16; j++)
                O[j] += p * Vs[c][d0 + j];
        }
    }

    const float inv_l = 1.0f / l;
    float* outp = g_att + (size_t)(b*Sn + q0 + r) * Dm + h*64 + d0;
    #pragma unroll
    for (int j = 0; j < 16; j++)
        outp[j] = O[j] * inv_l;
}

// ---------------- launch ----------------
extern "C" void kernel_launch(void* const* d_in, const int* in_sizes, int n_in,
                              void* d_out, int out_size)
{
    const float* q    = (const float*)d_in[0];
    const float* k    = (const float*)d_in[1];
    const float* v    = (const float*)d_in[2];
    // d_in[3] = mask (causal tril, statically known -> unused)
    const float* W_Aq = (const float*)d_in[4];
    const float* W_Ak = (const float*)d_in[5];
    const float* W_Av = (const float*)d_in[6];
    const float* W_Bq = (const float*)d_in[7];
    const float* W_Bk = (const float*)d_in[8];
    const float* W_Bv = (const float*)d_in[9];
    const float* Wo   = (const float*)d_in[10];
    float* out = (float*)d_out;

    float *pAq, *pAk, *pAv, *pBq, *pBk, *pBv, *pAtt;
    cudaGetSymbolAddress((void**)&pAq,  g_Aq);
    cudaGetSymbolAddress((void**)&pAk,  g_Ak);
    cudaGetSymbolAddress((void**)&pAv,  g_Av);
    cudaGetSymbolAddress((void**)&pBq,  g_Bq);
    cudaGetSymbolAddress((void**)&pBk,  g_Bk);
    cudaGetSymbolAddress((void**)&pBv,  g_Bv);
    cudaGetSymbolAddress((void**)&pAtt, g_att);

    const int M = Mrows;   // 4096
    const int K = Dm;      // 1024
    dim3 blk(256);

    auto grid_for = [](int N) { return dim3((N + 63) / 64, Mrows / 64); };

    gemm_kernel<<<grid_for(Hn*QR),  blk>>>(q, W_Aq, pAq, M, Hn*QR,  K);   // 96
    gemm_kernel<<<grid_for(QR*DKn), blk>>>(q, W_Bq, pBq, M, QR*DKn, K);   // 384
    gemm_kernel<<<grid_for(Hn*RK),  blk>>>(k, W_Ak, pAk, M, Hn*RK,  K);   // 32
    gemm_kernel<<<grid_for(RK*DKn), blk>>>(k, W_Bk, pBk, M, RK*DKn, K);   // 128
    gemm_kernel<<<grid_for(Hn*RK),  blk>>>(v, W_Av, pAv, M, Hn*RK,  K);   // 32
    gemm_kernel<<<grid_for(RK*DKn), blk>>>(v, W_Bv, pBv, M, RK*DKn, K);   // 128

    combine_kernel<<<Mrows, blk>>>();

    flash_kernel<<<dim3(Sn/64, Hn, Bn), blk>>>();

    gemm_kernel<<<grid_for(Dm), blk>>>(pAtt, Wo, out, M, Dm, K);
}

// round 2
// speedup vs baseline: 1.7941x; 1.7941x over previous
#include <cuda_runtime.h>
#include <math_constants.h>
#include <mma.h>
#include <cstddef>

using namespace nvcuda;

#define Bn   2
#define Sn   2048
#define Hn   16
#define DKn  64
#define Dm   1024
#define QR   6
#define RK   2
#define Mrows (Bn*Sn)

// ---------------- scratch ----------------
__device__ float g_Aq[Mrows*Hn*QR];
__device__ float g_Ak[Mrows*Hn*RK];
__device__ float g_Av[Mrows*Hn*RK];
__device__ float g_Bq[Mrows*QR*DKn];
__device__ float g_Bk[Mrows*RK*DKn];
__device__ float g_Bv[Mrows*RK*DKn];
__device__ float g_qh[Bn*Hn*Sn*DKn];
__device__ float g_kh[Bn*Hn*Sn*DKn];
__device__ float g_vh[Bn*Hn*Sn*DKn];
__device__ float g_att[Mrows*Dm];

// ---------------- split-tf32 GEMM (fp32-accurate): C = A(MxK) @ B(KxN) ----------------
// BM=64, BN=64, BK=16. 8 warps, warp tile 16x32 (4x2 warp grid), 2 wmma C frags/warp.
// A,B split into tf32 hi + fp32 residual lo; C = Ah*Bh + Ah*Bl + Al*Bh.
#define ALD 20
#define BLD 68

__global__ __launch_bounds__(256) void gemm_tf32(
    const float* __restrict__ A, const float* __restrict__ Bw,
    float* __restrict__ C, int M, int N, int K)
{
    __shared__ float Ah[64][ALD], Al[64][ALD];
    __shared__ float Bh[16][BLD], Bl[16][BLD];
    __shared__ float Cs[64][BLD];

    const int t = threadIdx.x, wid = t >> 5;
    const int wm = wid >> 1, wn = wid & 1;
    const int m0 = blockIdx.y * 64, n0 = blockIdx.x * 64;

    wmma::fragment<wmma::accumulator,16,16,8,float> c[2];
    wmma::fill_fragment(c[0], 0.f);
    wmma::fill_fragment(c[1], 0.f);

    const int ar = t >> 2, ac4 = (t & 3) * 4;       // A: 64 rows x 4 f4
    const int br = t >> 4, bc4 = (t & 15) * 4;      // B: 16 rows x 16 f4
    const int bn = n0 + bc4;

    for (int k0 = 0; k0 < K; k0 += 16) {
        float4 av = *(const float4*)&A[(size_t)(m0 + ar) * K + k0 + ac4];
        float4 bv = (bn < N) ? *(const float4*)&Bw[(size_t)(k0 + br) * N + bn]
                             : make_float4(0.f,0.f,0.f,0.f);
        {
            float x[4] = {av.x, av.y, av.z, av.w};
            #pragma unroll
            for (int i = 0; i < 4; i++) {
                float hi = wmma::__float_to_tf32(x[i]);
                Ah[ar][ac4+i] = hi;
                Al[ar][ac4+i] = x[i] - hi;
            }
            float y[4] = {bv.x, bv.y, bv.z, bv.w};
            #pragma unroll
            for (int i = 0; i < 4; i++) {
                float hi = wmma::__float_to_tf32(y[i]);
                Bh[br][bc4+i] = hi;
                Bl[br][bc4+i] = y[i] - hi;
            }
        }
        __syncthreads();

        #pragma unroll
        for (int kk = 0; kk < 16; kk += 8) {
            wmma::fragment<wmma::matrix_a,16,16,8,wmma::precision::tf32,wmma::row_major> ah, al;
            wmma::load_matrix_sync(ah, &Ah[wm*16][kk], ALD);
            wmma::load_matrix_sync(al, &Al[wm*16][kk], ALD);
            #pragma unroll
            for (int j = 0; j < 2; j++) {
                wmma::fragment<wmma::matrix_b,16,16,8,wmma::precision::tf32,wmma::row_major> bh, bl;
                wmma::load_matrix_sync(bh, &Bh[kk][wn*32 + j*16], BLD);
                wmma::load_matrix_sync(bl, &Bl[kk][wn*32 + j*16], BLD);
                wmma::mma_sync(c[j], ah, bh, c[j]);
                wmma::mma_sync(c[j], ah, bl, c[j]);
                wmma::mma_sync(c[j], al, bh, c[j]);
            }
        }
        __syncthreads();
    }

    wmma::store_matrix_sync(&Cs[wm*16][wn*32],      c[0], BLD, wmma::mem_row_major);
    wmma::store_matrix_sync(&Cs[wm*16][wn*32 + 16], c[1], BLD, wmma::mem_row_major);
    __syncthreads();

    #pragma unroll
    for (int i = 0; i < 4; i++) {
        const int idx = t + i*256;
        const int row = idx >> 4, col4 = (idx & 15) * 4;
        const int n = n0 + col4;
        if (n < N)
            *(float4*)&C[(size_t)(m0 + row) * N + n] = *(const float4*)&Cs[row][col4];
    }
}

// ---------------- rank contraction + rotary + scaling ----------------
__global__ __launch_bounds__(256) void combine_kernel()
{
    const int m = blockIdx.x;
    const int b = m / Sn, s = m % Sn;
    const int t = threadIdx.x;

    __shared__ float sAq[Hn*QR], sAk[Hn*RK], sAv[Hn*RK];
    __shared__ float sBq[QR*DKn], sBk[RK*DKn], sBv[RK*DKn];
    __shared__ float sCos[32], sSin[32];

    for (int i = t; i < Hn*QR;  i += 256) sAq[i] = g_Aq[m*Hn*QR  + i];
    for (int i = t; i < Hn*RK;  i += 256) sAk[i] = g_Ak[m*Hn*RK  + i];
    for (int i = t; i < Hn*RK;  i += 256) sAv[i] = g_Av[m*Hn*RK  + i];
    for (int i = t; i < QR*DKn; i += 256) sBq[i] = g_Bq[m*QR*DKn + i];
    for (int i = t; i < RK*DKn; i += 256) sBk[i] = g_Bk[m*RK*DKn + i];
    for (int i = t; i < RK*DKn; i += 256) sBv[i] = g_Bv[m*RK*DKn + i];
    if (t < 32) {
        float inv = expf(-((float)(2*t) / 64.f) * logf(10000.0f));
        float fr  = (float)s * inv;
        sCos[t] = cosf(fr);
        sSin[t] = sinf(fr);
    }
    __syncthreads();

    for (int idx = t; idx < Hn*DKn; idx += 256) {
        const int h = idx >> 6, d = idx & 63, dl = d & 31;
        const float c = sCos[dl], sn = sSin[dl];
        const size_t obase = ((size_t)(b*Hn + h) * Sn + s) * 64 + d;

        float r1 = 0.f, r2 = 0.f;
        #pragma unroll
        for (int r = 0; r < QR; r++) {
            const float a = sAq[h*QR + r];
            r1 += a * sBq[r*64 + dl];
            r2 += a * sBq[r*64 + dl + 32];
        }
        float vq = (d < 32) ? (r1*c + r2*sn) : (-r1*sn + r2*c);
        g_qh[obase] = vq * (1.0f / QR);

        r1 = 0.f; r2 = 0.f;
        #pragma unroll
        for (int r = 0; r < RK; r++) {
            const float a = sAk[h*RK + r];
            r1 += a * sBk[r*64 + dl];
            r2 += a * sBk[r*64 + dl + 32];
        }
        float vk = (d < 32) ? (r1*c + r2*sn) : (-r1*sn + r2*c);
        g_kh[obase] = vk * 0.5f;

        float vv = 0.f;
        #pragma unroll
        for (int r = 0; r < RK; r++)
            vv += sAv[h*RK + r] * sBv[r*64 + d];
        g_vh[obase] = vv * 0.5f;
    }
}

// ---------------- tf32 flash attention ----------------
// Block 256 (8 warps). Q tile 64x64 (frags in regs), K tile 64. Warp grid 4(m)x2(n),
// warp tile 16x32. KV buffer holds K then V per tile; Ss holds S -> P -> PV partial.
#define FLD 68

__global__ __launch_bounds__(256) void flash_tf32()
{
    const int qt = (gridDim.x - 1) - blockIdx.x;   // heavy tiles first
    const int h = blockIdx.y, b = blockIdx.z;
    const int q0 = qt * 64;

    const float* Qp = g_qh + (size_t)(b*Hn + h) * Sn * 64;
    const float* Kp = g_kh + (size_t)(b*Hn + h) * Sn * 64;
    const float* Vp = g_vh + (size_t)(b*Hn + h) * Sn * 64;

    __shared__ float KV[64][FLD];
    __shared__ float Ss[64][FLD];

    const int t = threadIdx.x, wid = t >> 5;
    const int wm = wid >> 1, wn = wid & 1;
    const int r  = t >> 2;            // softmax/O row 0..63
    const int cg = t & 3;
    const int c0 = cg * 16;           // score cols / O dims

    // ---- load Q tile, build register A-fragments ----
    {
        #pragma unroll
        for (int i = 0; i < 4; i++) {
            const int idx = t + i*256;
            const int row = idx >> 4, col4 = (idx & 15) * 4;
            *(float4*)&KV[row][col4] = *(const float4*)&Qp[(size_t)(q0 + row)*64 + col4];
        }
    }
    __syncthreads();

    wmma::fragment<wmma::matrix_a,16,16,8,wmma::precision::tf32,wmma::row_major> qf[8];
    #pragma unroll
    for (int kk = 0; kk < 8; kk++) {
        wmma::load_matrix_sync(qf[kk], &KV[wm*16][kk*8], FLD);
        #pragma unroll
        for (int e = 0; e < qf[kk].num_elements; e++)
            qf[kk].x[e] = wmma::__float_to_tf32(qf[kk].x[e]);
    }

    float O[16] = {};
    float mrow = -CUDART_INF_F, l = 0.f;
    const int qi = q0 + r;
    const float scale = 1.0f / (float)DKn;
    const int nk = qt + 1;

    for (int kt = 0; kt < nk; kt++) {
        const int k0 = kt * 64;
        __syncthreads();                                   // KV free
        #pragma unroll
        for (int i = 0; i < 4; i++) {
            const int idx = t + i*256;
            const int row = idx >> 4, col4 = (idx & 15) * 4;
            *(float4*)&KV[row][col4] = *(const float4*)&Kp[(size_t)(k0 + row)*64 + col4];
        }
        __syncthreads();                                   // K ready

        // ---- S = Q @ K^T ----
        wmma::fragment<wmma::accumulator,16,16,8,float> sf[2];
        wmma::fill_fragment(sf[0], 0.f);
        wmma::fill_fragment(sf[1], 0.f);
        #pragma unroll
        for (int kk = 0; kk < 8; kk++) {
            #pragma unroll
            for (int j = 0; j < 2; j++) {
                wmma::fragment<wmma::matrix_b,16,16,8,wmma::precision::tf32,wmma::col_major> bf;
                wmma::load_matrix_sync(bf, &KV[wn*32 + j*16][kk*8], FLD);
                #pragma unroll
                for (int e = 0; e < bf.num_elements; e++)
                    bf.x[e] = wmma::__float_to_tf32(bf.x[e]);
                wmma::mma_sync(sf[j], qf[kk], bf, sf[j]);
            }
        }
        __syncthreads();                                   // Ss free (merge reads done)
        wmma::store_matrix_sync(&Ss[wm*16][wn*32],      sf[0], FLD, wmma::mem_row_major);
        wmma::store_matrix_sync(&Ss[wm*16][wn*32 + 16], sf[1], FLD, wmma::mem_row_major);
        __syncthreads();                                   // S ready

        // ---- online softmax (thread owns row r, cols c0..c0+15) ----
        float sv[16];
        #pragma unroll
        for (int j = 0; j < 16; j++) {
            const int kj = k0 + c0 + j;
            float x = Ss[r][c0 + j] * scale;
            sv[j] = (kj <= qi) ? x : -CUDART_INF_F;
        }
        float mloc = sv[0];
        #pragma unroll
        for (int j = 1; j < 16; j++) mloc = fmaxf(mloc, sv[j]);
        mloc = fmaxf(mloc, __shfl_xor_sync(0xffffffffu, mloc, 1));
        mloc = fmaxf(mloc, __shfl_xor_sync(0xffffffffu, mloc, 2));
        const float mnew  = fmaxf(mrow, mloc);
        const float alpha = __expf(mrow - mnew);
        float psum = 0.f;
        #pragma unroll
        for (int j = 0; j < 16; j++) {
            const float p = __expf(sv[j] - mnew);
            Ss[r][c0 + j] = p;
            psum += p;
        }
        psum += __shfl_xor_sync(0xffffffffu, psum, 1);
        psum += __shfl_xor_sync(0xffffffffu, psum, 2);
        l = l * alpha + psum;
        mrow = mnew;

        // ---- load V into KV (K reads finished at "Ss free" sync) ----
        #pragma unroll
        for (int i = 0; i < 4; i++) {
            const int idx = t + i*256;
            const int row = idx >> 4, col4 = (idx & 15) * 4;
            *(float4*)&KV[row][col4] = *(const float4*)&Vp[(size_t)(k0 + row)*64 + col4];
        }
        __syncthreads();                                   // P + V ready

        // ---- U = P @ V ----
        wmma::fragment<wmma::accumulator,16,16,8,float> uf[2];
        wmma::fill_fragment(uf[0], 0.f);
        wmma::fill_fragment(uf[1], 0.f);
        #pragma unroll
        for (int kk = 0; kk < 8; kk++) {
            wmma::fragment<wmma::matrix_a,16,16,8,wmma::precision::tf32,wmma::row_major> pf;
            wmma::load_matrix_sync(pf, &Ss[wm*16][kk*8], FLD);
            #pragma unroll
            for (int e = 0; e < pf.num_elements; e++)
                pf.x[e] = wmma::__float_to_tf32(pf.x[e]);
            #pragma unroll
            for (int j = 0; j < 2; j++) {
                wmma::fragment<wmma::matrix_b,16,16,8,wmma::precision::tf32,wmma::row_major> vf;
                wmma::load_matrix_sync(vf, &KV[kk*8][wn*32 + j*16], FLD);
                #pragma unroll
                for (int e = 0; e < vf.num_elements; e++)
                    vf.x[e] = wmma::__float_to_tf32(vf.x[e]);
                wmma::mma_sync(uf[j], pf, vf, uf[j]);
            }
        }
        __syncthreads();                                   // P reads done -> Ss writable
        wmma::store_matrix_sync(&Ss[wm*16][wn*32],      uf[0], FLD, wmma::mem_row_major);
        wmma::store_matrix_sync(&Ss[wm*16][wn*32 + 16], uf[1], FLD, wmma::mem_row_major);
        __syncthreads();                                   // U ready

        // ---- merge into O registers ----
        #pragma unroll
        for (int j = 0; j < 16; j++)
            O[j] = O[j] * alpha + Ss[r][c0 + j];
    }

    const float inv_l = 1.0f / l;
    float* outp = g_att + (size_t)(b*Sn + q0 + r) * Dm + h*64 + c0;
    #pragma unroll
    for (int j = 0; j < 16; j++)
        outp[j] = O[j] * inv_l;
}

// ---------------- launch ----------------
extern "C" void kernel_launch(void* const* d_in, const int* in_sizes, int n_in,
                              void* d_out, int out_size)
{
    const float* q    = (const float*)d_in[0];
    const float* k    = (const float*)d_in[1];
    const float* v    = (const float*)d_in[2];
    const float* W_Aq = (const float*)d_in[4];
    const float* W_Ak = (const float*)d_in[5];
    const float* W_Av = (const float*)d_in[6];
    const float* W_Bq = (const float*)d_in[7];
    const float* W_Bk = (const float*)d_in[8];
    const float* W_Bv = (const float*)d_in[9];
    const float* Wo   = (const float*)d_in[10];
    float* out = (float*)d_out;

    float *pAq, *pAk, *pAv, *pBq, *pBk, *pBv, *pAtt;
    cudaGetSymbolAddress((void**)&pAq,  g_Aq);
    cudaGetSymbolAddress((void**)&pAk,  g_Ak);
    cudaGetSymbolAddress((void**)&pAv,  g_Av);
    cudaGetSymbolAddress((void**)&pBq,  g_Bq);
    cudaGetSymbolAddress((void**)&pBk,  g_Bk);
    cudaGetSymbolAddress((void**)&pBv,  g_Bv);
    cudaGetSymbolAddress((void**)&pAtt, g_att);

    const int M = Mrows, K = Dm;
    dim3 blk(256);
    auto grid_for = [](int N) { return dim3((N + 63) / 64, Mrows / 64); };

    gemm_tf32<<<grid_for(Hn*QR),  blk>>>(q, W_Aq, pAq, M, Hn*QR,  K);
    gemm_tf32<<<grid_for(QR*DKn), blk>>>(q, W_Bq, pBq, M, QR*DKn, K);
    gemm_tf32<<<grid_for(Hn*RK),  blk>>>(k, W_Ak, pAk, M, Hn*RK,  K);
    gemm_tf32<<<grid_for(RK*DKn), blk>>>(k, W_Bk, pBk, M, RK*DKn, K);
    gemm_tf32<<<grid_for(Hn*RK),  blk>>>(v, W_Av, pAv, M, Hn*RK,  K);
    gemm_tf32<<<grid_for(RK*DKn), blk>>>(v, W_Bv, pBv, M, RK*DKn, K);

    combine_kernel<<<Mrows, blk>>>();

    flash_tf32<<<dim3(Sn/64, Hn, Bn), blk>>>();

    gemm_tf32<<<grid_for(Dm), blk>>>(pAtt, Wo, out, M, Dm, K);
}

// round 3
// speedup vs baseline: 2.2433x; 1.2504x over previous
#include <cuda_runtime.h>
#include <cuda_bf16.h>
#include <math_constants.h>
#include <mma.h>
#include <cstddef>

using namespace nvcuda;

#define Bn   2
#define Sn   2048
#define Hn   16
#define DKn  64
#define Dm   1024
#define QR   6
#define RK   2
#define Mrows (Bn*Sn)

// ---------------- scratch ----------------
__device__ float g_Aq[Mrows*Hn*QR];
__device__ float g_Ak[Mrows*Hn*RK];
__device__ float g_Av[Mrows*Hn*RK];
__device__ float g_Bq[Mrows*QR*DKn];
__device__ float g_Bk[Mrows*RK*DKn];
__device__ float g_Bv[Mrows*RK*DKn];
__device__ float g_qh[Bn*Hn*Sn*DKn];
__device__ float g_kh[Bn*Hn*Sn*DKn];
__device__ float g_vh[Bn*Hn*Sn*DKn];
__device__ float g_att[Mrows*Dm];

__device__ __forceinline__ void split2(float x, __nv_bfloat16& h, __nv_bfloat16& l)
{
    h = __float2bfloat16(x);
    l = __float2bfloat16(x - __bfloat162float(h));
}

using FragA  = wmma::fragment<wmma::matrix_a,16,16,16,__nv_bfloat16,wmma::row_major>;
using FragBr = wmma::fragment<wmma::matrix_b,16,16,16,__nv_bfloat16,wmma::row_major>;
using FragBc = wmma::fragment<wmma::matrix_b,16,16,16,__nv_bfloat16,wmma::col_major>;
using FragC  = wmma::fragment<wmma::accumulator,16,16,16,float>;

// ---------------- split-bf16 GEMM tile: C[128x64] += A(128xK) @ W(KxN) ----------------
// 8 warps: 4(m) x 2(n), warp tile 32x32, K=1024, BK=32, reg-prefetch double buffer.
__device__ __forceinline__ void gemm_tile(
    const float* __restrict__ A, const float* __restrict__ W,
    float* __restrict__ C, int N, int n0, int m0)
{
    __shared__ __nv_bfloat16 AH[128*40], AL[128*40];
    __shared__ __nv_bfloat16 BH[32*72],  BL[32*72];

    const int t = threadIdx.x, wid = t >> 5;
    const int wm = wid >> 1, wn = wid & 1;
    const int ar = t >> 1, ac = (t & 1) * 16;     // A: row, 16-float chunk
    const int br = t >> 3, bc = (t & 7) * 8;      // B: row, 8-float chunk

    FragC c[2][2];
    #pragma unroll
    for (int i = 0; i < 2; i++)
        #pragma unroll
        for (int j = 0; j < 2; j++)
            wmma::fill_fragment(c[i][j], 0.f);

    float4 ra[4], rb[2];
    const float4 z4 = make_float4(0.f,0.f,0.f,0.f);

    // initial load (k0 = 0)
    {
        const float* ap = A + (size_t)(m0 + ar) * 1024 + ac;
        #pragma unroll
        for (int i = 0; i < 4; i++) ra[i] = *(const float4*)(ap + i*4);
        #pragma unroll
        for (int i = 0; i < 2; i++) {
            const int n = n0 + bc + i*4;
            rb[i] = (n + 4 <= N) ? *(const float4*)&W[(size_t)br * N + n] : z4;
        }
    }

    for (int k0 = 0; k0 < 1024; k0 += 32) {
        // store current regs -> smem (split)
        #pragma unroll
        for (int i = 0; i < 4; i++) {
            float xs[4] = {ra[i].x, ra[i].y, ra[i].z, ra[i].w};
            #pragma unroll
            for (int e = 0; e < 4; e++)
                split2(xs[e], AH[ar*40 + ac + i*4 + e], AL[ar*40 + ac + i*4 + e]);
        }
        #pragma unroll
        for (int i = 0; i < 2; i++) {
            float ys[4] = {rb[i].x, rb[i].y, rb[i].z, rb[i].w};
            #pragma unroll
            for (int e = 0; e < 4; e++)
                split2(ys[e], BH[br*72 + bc + i*4 + e], BL[br*72 + bc + i*4 + e]);
        }
        __syncthreads();

        // prefetch next stage
        if (k0 + 32 < 1024) {
            const float* ap = A + (size_t)(m0 + ar) * 1024 + k0 + 32 + ac;
            #pragma unroll
            for (int i = 0; i < 4; i++) ra[i] = *(const float4*)(ap + i*4);
            #pragma unroll
            for (int i = 0; i < 2; i++) {
                const int n = n0 + bc + i*4;
                rb[i] = (n + 4 <= N) ? *(const float4*)&W[(size_t)(k0 + 32 + br) * N + n] : z4;
            }
        }

        // compute 2 k16 steps
        #pragma unroll
        for (int ks = 0; ks < 2; ks++) {
            FragA ah[2], al[2];
            FragBr bh[2], bl[2];
            #pragma unroll
            for (int i = 0; i < 2; i++) {
                wmma::load_matrix_sync(ah[i], &AH[(wm*32 + i*16)*40 + ks*16], 40);
                wmma::load_matrix_sync(al[i], &AL[(wm*32 + i*16)*40 + ks*16], 40);
            }
            #pragma unroll
            for (int j = 0; j < 2; j++) {
                wmma::load_matrix_sync(bh[j], &BH[(ks*16)*72 + wn*32 + j*16], 72);
                wmma::load_matrix_sync(bl[j], &BL[(ks*16)*72 + wn*32 + j*16], 72);
            }
            #pragma unroll
            for (int i = 0; i < 2; i++)
                #pragma unroll
                for (int j = 0; j < 2; j++) {
                    wmma::mma_sync(c[i][j], ah[i], bh[j], c[i][j]);
                    wmma::mma_sync(c[i][j], ah[i], bl[j], c[i][j]);
                    wmma::mma_sync(c[i][j], al[i], bh[j], c[i][j]);
                }
        }
        __syncthreads();
    }

    // store C (per-fragment predicated, direct to global)
    #pragma unroll
    for (int i = 0; i < 2; i++)
        #pragma unroll
        for (int j = 0; j < 2; j++) {
            const int co = n0 + wn*32 + j*16;
            if (co + 16 <= N)
                wmma::store_matrix_sync(&C[(size_t)(m0 + wm*32 + i*16) * N + co],
                                        c[i][j], N, wmma::mem_row_major);
        }
}

// fused projections: 14 column tiles across 6 GEMMs
__global__ __launch_bounds__(256,2) void proj_fused(
    const float* __restrict__ q, const float* __restrict__ k, const float* __restrict__ v,
    const float* __restrict__ WAq, const float* __restrict__ WBq,
    const float* __restrict__ WAk, const float* __restrict__ WBk,
    const float* __restrict__ WAv, const float* __restrict__ WBv)
{
    const int tix = blockIdx.x, m0 = blockIdx.y * 128;
    const float *A, *W; float* C; int N, n0;
    if      (tix < 2)  { A=q; W=WAq; C=g_Aq; N=96;  n0=tix*64; }
    else if (tix < 8)  { A=q; W=WBq; C=g_Bq; N=384; n0=(tix-2)*64; }
    else if (tix == 8) { A=k; W=WAk; C=g_Ak; N=32;  n0=0; }
    else if (tix < 11) { A=k; W=WBk; C=g_Bk; N=128; n0=(tix-9)*64; }
    else if (tix == 11){ A=v; W=WAv; C=g_Av; N=32;  n0=0; }
    else               { A=v; W=WBv; C=g_Bv; N=128; n0=(tix-12)*64; }
    gemm_tile(A, W, C, N, n0, m0);
}

__global__ __launch_bounds__(256,2) void gemm_generic(
    const float* __restrict__ A, const float* __restrict__ W,
    float* __restrict__ C, int N)
{
    gemm_tile(A, W, C, N, blockIdx.x * 64, blockIdx.y * 128);
}

// ---------------- rank contraction + rotary + scaling ----------------
__global__ __launch_bounds__(256) void combine_kernel()
{
    const int m = blockIdx.x;
    const int b = m / Sn, s = m % Sn;
    const int t = threadIdx.x;

    __shared__ float sAq[Hn*QR], sAk[Hn*RK], sAv[Hn*RK];
    __shared__ float sBq[QR*DKn], sBk[RK*DKn], sBv[RK*DKn];
    __shared__ float sCos[32], sSin[32];

    for (int i = t; i < Hn*QR;  i += 256) sAq[i] = g_Aq[m*Hn*QR  + i];
    for (int i = t; i < Hn*RK;  i += 256) sAk[i] = g_Ak[m*Hn*RK  + i];
    for (int i = t; i < Hn*RK;  i += 256) sAv[i] = g_Av[m*Hn*RK  + i];
    for (int i = t; i < QR*DKn; i += 256) sBq[i] = g_Bq[m*QR*DKn + i];
    for (int i = t; i < RK*DKn; i += 256) sBk[i] = g_Bk[m*RK*DKn + i];
    for (int i = t; i < RK*DKn; i += 256) sBv[i] = g_Bv[m*RK*DKn + i];
    if (t < 32) {
        float inv = expf(-((float)(2*t) / 64.f) * logf(10000.0f));
        float fr  = (float)s * inv;
        sCos[t] = cosf(fr);
        sSin[t] = sinf(fr);
    }
    __syncthreads();

    for (int idx = t; idx < Hn*DKn; idx += 256) {
        const int h = idx >> 6, d = idx & 63, dl = d & 31;
        const float c = sCos[dl], sn = sSin[dl];
        const size_t obase = ((size_t)(b*Hn + h) * Sn + s) * 64 + d;

        float r1 = 0.f, r2 = 0.f;
        #pragma unroll
        for (int r = 0; r < QR; r++) {
            const float a = sAq[h*QR + r];
            r1 += a * sBq[r*64 + dl];
            r2 += a * sBq[r*64 + dl + 32];
        }
        float vq = (d < 32) ? (r1*c + r2*sn) : (-r1*sn + r2*c);
        g_qh[obase] = vq * (1.0f / QR);

        r1 = 0.f; r2 = 0.f;
        #pragma unroll
        for (int r = 0; r < RK; r++) {
            const float a = sAk[h*RK + r];
            r1 += a * sBk[r*64 + dl];
            r2 += a * sBk[r*64 + dl + 32];
        }
        float vk = (d < 32) ? (r1*c + r2*sn) : (-r1*sn + r2*c);
        g_kh[obase] = vk * 0.5f;

        float vv = 0.f;
        #pragma unroll
        for (int r = 0; r < RK; r++)
            vv += sAv[h*RK + r] * sBv[r*64 + d];
        g_vh[obase] = vv * 0.5f;
    }
}

// ---------------- split-bf16 flash attention: Br=128, Bc=64 ----------------
#define FB 72
#define SLD 68
#define FLASH_SMEM ((2*128*FB + 2*64*FB + 2*128*FB) * 2 + 128*SLD*4)

__global__ __launch_bounds__(256,1) void flash_bf16s()
{
    extern __shared__ char smraw[];
    __nv_bfloat16* QH = (__nv_bfloat16*)smraw;
    __nv_bfloat16* QL = QH + 128*FB;
    __nv_bfloat16* KH = QL + 128*FB;
    __nv_bfloat16* KL = KH + 64*FB;
    __nv_bfloat16* PH = KL + 64*FB;
    __nv_bfloat16* PL = PH + 128*FB;
    float*         Ss = (float*)(PL + 128*FB);

    const int qt = (gridDim.x - 1) - blockIdx.x;   // heavy tiles first
    const int h = blockIdx.y, b = blockIdx.z;
    const int q0 = qt * 128;

    const float* Qp = g_qh + (size_t)(b*Hn + h) * Sn * 64;
    const float* Kp = g_kh + (size_t)(b*Hn + h) * Sn * 64;
    const float* Vp = g_vh + (size_t)(b*Hn + h) * Sn * 64;

    const int t = threadIdx.x, wid = t >> 5;
    const int wm = wid >> 1, wn = wid & 1;
    const int r  = t >> 1;             // row 0..127
    const int ch = (t & 1) * 32;       // 32-col group
    const int kr = t >> 2, kc = (t & 3) * 16;   // K/V load mapping

    // load + split Q
    {
        const float* qp = Qp + (size_t)(q0 + r) * 64 + ch;
        #pragma unroll
        for (int i = 0; i < 8; i++) {
            float4 f = *(const float4*)(qp + i*4);
            float xs[4] = {f.x, f.y, f.z, f.w};
            #pragma unroll
            for (int e = 0; e < 4; e++)
                split2(xs[e], QH[r*FB + ch + i*4 + e], QL[r*FB + ch + i*4 + e]);
        }
    }

    float O[32] = {};
    float mrow = -CUDART_INF_F, l = 0.f;
    const int qi = q0 + r;
    const float scale = 1.0f / (float)DKn;
    const int nk = 2*qt + 2;

    for (int kt = 0; kt < nk; kt++) {
        const int k0 = kt * 64;
        __syncthreads();                               // A: prev PV/merge done (Q too)
        {
            const float* kp = Kp + (size_t)(k0 + kr) * 64 + kc;
            #pragma unroll
            for (int i = 0; i < 4; i++) {
                float4 f = *(const float4*)(kp + i*4);
                float xs[4] = {f.x, f.y, f.z, f.w};
                #pragma unroll
                for (int e = 0; e < 4; e++)
                    split2(xs[e], KH[kr*FB + kc + i*4 + e], KL[kr*FB + kc + i*4 + e]);
            }
        }
        __syncthreads();                               // B: K (and Q) ready

        // ---- S = Q @ K^T ----
        {
            FragC sf[2][2];
            #pragma unroll
            for (int i = 0; i < 2; i++)
                #pragma unroll
                for (int j = 0; j < 2; j++)
                    wmma::fill_fragment(sf[i][j], 0.f);
            #pragma unroll
            for (int ks = 0; ks < 4; ks++) {
                FragA ah[2], al[2];
                FragBc bh[2], bl[2];
                #pragma unroll
                for (int i = 0; i < 2; i++) {
                    wmma::load_matrix_sync(ah[i], &QH[(wm*32 + i*16)*FB + ks*16], FB);
                    wmma::load_matrix_sync(al[i], &QL[(wm*32 + i*16)*FB + ks*16], FB);
                }
                #pragma unroll
                for (int j = 0; j < 2; j++) {
                    wmma::load_matrix_sync(bh[j], &KH[(wn*32 + j*16)*FB + ks*16], FB);
                    wmma::load_matrix_sync(bl[j], &KL[(wn*32 + j*16)*FB + ks*16], FB);
                }
                #pragma unroll
                for (int i = 0; i < 2; i++)
                    #pragma unroll
                    for (int j = 0; j < 2; j++) {
                        wmma::mma_sync(sf[i][j], ah[i], bh[j], sf[i][j]);
                        wmma::mma_sync(sf[i][j], ah[i], bl[j], sf[i][j]);
                        wmma::mma_sync(sf[i][j], al[i], bh[j], sf[i][j]);
                    }
            }
            #pragma unroll
            for (int i = 0; i < 2; i++)
                #pragma unroll
                for (int j = 0; j < 2; j++)
                    wmma::store_matrix_sync(&Ss[(wm*32 + i*16)*SLD + wn*32 + j*16],
                                            sf[i][j], SLD, wmma::mem_row_major);
        }
        __syncthreads();                               // C: S visible

        // ---- online softmax + V load ----
        {
            float sv[32];
            float mloc = -CUDART_INF_F;
            #pragma unroll
            for (int j = 0; j < 32; j++) {
                const int kj = k0 + ch + j;
                float x = Ss[r*SLD + ch + j] * scale;
                x = (kj <= qi) ? x : -CUDART_INF_F;
                sv[j] = x;
                mloc = fmaxf(mloc, x);
            }
            mloc = fmaxf(mloc, __shfl_xor_sync(0xffffffffu, mloc, 1));
            const float mnew  = fmaxf(mrow, mloc);
            const float alpha = __expf(mrow - mnew);
            float ps = 0.f;
            #pragma unroll
            for (int j = 0; j < 32; j++) {
                const float p = __expf(sv[j] - mnew);
                split2(p, PH[r*FB + ch + j], PL[r*FB + ch + j]);
                ps += p;
            }
            ps += __shfl_xor_sync(0xffffffffu, ps, 1);
            l = l * alpha + ps;
            mrow = mnew;
            #pragma unroll
            for (int j = 0; j < 32; j++) O[j] *= alpha;

            // V -> KH/KL (K reads complete at sync C)
            const float* vp = Vp + (size_t)(k0 + kr) * 64 + kc;
            #pragma unroll
            for (int i = 0; i < 4; i++) {
                float4 f = *(const float4*)(vp + i*4);
                float xs[4] = {f.x, f.y, f.z, f.w};
                #pragma unroll
                for (int e = 0; e < 4; e++)
                    split2(xs[e], KH[kr*FB + kc + i*4 + e], KL[kr*FB + kc + i*4 + e]);
            }
        }
        __syncthreads();                               // D: P + V ready

        // ---- U = P @ V ----
        {
            FragC uf[2][2];
            #pragma unroll
            for (int i = 0; i < 2; i++)
                #pragma unroll
                for (int j = 0; j < 2; j++)
                    wmma::fill_fragment(uf[i][j], 0.f);
            #pragma unroll
            for (int ks = 0; ks < 4; ks++) {
                FragA ph[2], pl[2];
                FragBr vh[2], vl[2];
                #pragma unroll
                for (int i = 0; i < 2; i++) {
                    wmma::load_matrix_sync(ph[i], &PH[(wm*32 + i*16)*FB + ks*16], FB);
                    wmma::load_matrix_sync(pl[i], &PL[(wm*32 + i*16)*FB + ks*16], FB);
                }
                #pragma unroll
                for (int j = 0; j < 2; j++) {
                    wmma::load_matrix_sync(vh[j], &KH[(ks*16)*FB + wn*32 + j*16], FB);
                    wmma::load_matrix_sync(vl[j], &KL[(ks*16)*FB + wn*32 + j*16], FB);
                }
                #pragma unroll
                for (int i = 0; i < 2; i++)
                    #pragma unroll
                    for (int j = 0; j < 2; j++) {
                        wmma::mma_sync(uf[i][j], ph[i], vh[j], uf[i][j]);
                        wmma::mma_sync(uf[i][j], ph[i], vl[j], uf[i][j]);
                        wmma::mma_sync(uf[i][j], pl[i], vh[j], uf[i][j]);
                    }
            }
            #pragma unroll
            for (int i = 0; i < 2; i++)
                #pragma unroll
                for (int j = 0; j < 2; j++)
                    wmma::store_matrix_sync(&Ss[(wm*32 + i*16)*SLD + wn*32 + j*16],
                                            uf[i][j], SLD, wmma::mem_row_major);
        }
        __syncthreads();                               // E: U visible

        #pragma unroll
        for (int j = 0; j < 32; j++)
            O[j] += Ss[r*SLD + ch + j];
    }

    const float inv_l = 1.0f / l;
    float* outp = g_att + (size_t)(b*Sn + q0 + r) * Dm + h*64 + ch;
    #pragma unroll
    for (int j = 0; j < 32; j += 4) {
        float4 o = make_float4(O[j]*inv_l, O[j+1]*inv_l, O[j+2]*inv_l, O[j+3]*inv_l);
        *(float4*)(outp + j) = o;
    }
}

// ---------------- launch ----------------
extern "C" void kernel_launch(void* const* d_in, const int* in_sizes, int n_in,
                              void* d_out, int out_size)
{
    const float* q    = (const float*)d_in[0];
    const float* k    = (const float*)d_in[1];
    const float* v    = (const float*)d_in[2];
    const float* W_Aq = (const float*)d_in[4];
    const float* W_Ak = (const float*)d_in[5];
    const float* W_Av = (const float*)d_in[6];
    const float* W_Bq = (const float*)d_in[7];
    const float* W_Bk = (const float*)d_in[8];
    const float* W_Bv = (const float*)d_in[9];
    const float* Wo   = (const float*)d_in[10];
    float* out = (float*)d_out;

    float* pAtt;
    cudaGetSymbolAddress((void**)&pAtt, g_att);

    cudaFuncSetAttribute(flash_bf16s,
                         cudaFuncAttributeMaxDynamicSharedMemorySize, FLASH_SMEM);

    dim3 blk(256);

    proj_fused<<<dim3(14, Mrows/128), blk>>>(q, k, v, W_Aq, W_Bq, W_Ak, W_Bk, W_Av, W_Bv);

    combine_kernel<<<Mrows, blk>>>();

    flash_bf16s<<<dim3(Sn/128, Hn, Bn), blk, FLASH_SMEM>>>();

    gemm_generic<<<dim3(Dm/64, Mrows/128), blk>>>(pAtt, Wo, out, Dm);
}

// round 4
// speedup vs baseline: 5.7969x; 2.5842x over previous
#include <cuda_runtime.h>
#include <cuda_bf16.h>
#include <math_constants.h>
#include <mma.h>
#include <cstddef>
#include <cstdint>

using namespace nvcuda;
using bf16 = __nv_bfloat16;

#define Bn   2
#define Sn   2048
#define Hn   16
#define DKn  64
#define Dm   1024
#define QR   6
#define RK   2
#define Mrows (Bn*Sn)

// ---------------- global scratch ----------------
__device__ bf16 g_xqH[Mrows*Dm], g_xqL[Mrows*Dm];
__device__ bf16 g_xkH[Mrows*Dm], g_xkL[Mrows*Dm];
__device__ bf16 g_xvH[Mrows*Dm], g_xvL[Mrows*Dm];
__device__ bf16 g_wH [Dm*Dm],   g_wL [Dm*Dm];     // packed proj weights (padded cols)
__device__ bf16 g_woH[Dm*Dm],   g_woL[Dm*Dm];
__device__ float g_proj[Mrows*Dm];                 // packed projection outputs
__device__ bf16 g_qhH[Bn*Hn*Sn*DKn], g_qhL[Bn*Hn*Sn*DKn];
__device__ bf16 g_khH[Bn*Hn*Sn*DKn], g_khL[Bn*Hn*Sn*DKn];
__device__ bf16 g_vhH[Bn*Hn*Sn*DKn], g_vhL[Bn*Hn*Sn*DKn];
__device__ bf16 g_attH[Mrows*Dm], g_attL[Mrows*Dm];

// ---------------- helpers ----------------
__device__ __forceinline__ void split2(float x, bf16& h, bf16& l)
{
    h = __float2bfloat16(x);
    l = __float2bfloat16(x - __bfloat162float(h));
}
__device__ __forceinline__ unsigned sm_u32(const void* p)
{
    return (unsigned)__cvta_generic_to_shared(p);
}
__device__ __forceinline__ void ldsm4(unsigned r[4], unsigned a)
{
    asm volatile("ldmatrix.sync.aligned.m8n8.x4.shared.b16 {%0,%1,%2,%3}, [%4];"
        : "=r"(r[0]), "=r"(r[1]), "=r"(r[2]), "=r"(r[3]) : "r"(a));
}
__device__ __forceinline__ void ldsm4t(unsigned r[4], unsigned a)
{
    asm volatile("ldmatrix.sync.aligned.m8n8.x4.trans.shared.b16 {%0,%1,%2,%3}, [%4];"
        : "=r"(r[0]), "=r"(r[1]), "=r"(r[2]), "=r"(r[3]) : "r"(a));
}
__device__ __forceinline__ void mma16816(float c[4], const unsigned a[4], const unsigned b[2])
{
    asm volatile(
        "mma.sync.aligned.m16n8k16.row.col.f32.bf16.bf16.f32 "
        "{%0,%1,%2,%3},{%4,%5,%6,%7},{%8,%9},{%0,%1,%2,%3};"
        : "+f"(c[0]), "+f"(c[1]), "+f"(c[2]), "+f"(c[3])
        : "r"(a[0]), "r"(a[1]), "r"(a[2]), "r"(a[3]), "r"(b[0]), "r"(b[1]));
}
__device__ __forceinline__ unsigned packbf(float lo, float hi)
{
    unsigned r;
    asm("cvt.rn.bf16x2.f32 %0, %1, %2;" : "=r"(r) : "f"(hi), "f"(lo));
    return r;
}
__device__ __forceinline__ unsigned pack_us(bf16 lo, bf16 hi)
{
    return ((unsigned)__bfloat16_as_ushort(hi) << 16) | (unsigned)__bfloat16_as_ushort(lo);
}
#define CPA16(dst, src) \
    asm volatile("cp.async.cg.shared.global [%0], [%1], 16;" :: "r"(dst), "l"(src))
#define CPA_COMMIT() asm volatile("cp.async.commit_group;")
#define CPA_WAIT1()  asm volatile("cp.async.wait_group 1;")

// ---------------- presplit kernels ----------------
__global__ __launch_bounds__(256) void split_kernel(
    const float* __restrict__ src, bf16* __restrict__ dh, bf16* __restrict__ dl, int n4)
{
    int i = blockIdx.x * 256 + threadIdx.x;
    if (i >= n4) return;
    float4 f = ((const float4*)src)[i];
    bf16 h0,l0,h1,l1,h2,l2,h3,l3;
    split2(f.x,h0,l0); split2(f.y,h1,l1); split2(f.z,h2,l2); split2(f.w,h3,l3);
    __nv_bfloat162 a; a.x=h0; a.y=h1;
    __nv_bfloat162 b; b.x=h2; b.y=h3;
    ((__nv_bfloat162*)dh)[i*2]   = a;
    ((__nv_bfloat162*)dh)[i*2+1] = b;
    a.x=l0; a.y=l1; b.x=l2; b.y=l3;
    ((__nv_bfloat162*)dl)[i*2]   = a;
    ((__nv_bfloat162*)dl)[i*2+1] = b;
}

// pack weights into [1024][1024]: Aq@0(96/128) Bq@128(384) Ak@512(32/128) Bk@640 Av@768(32/128) Bv@896
__global__ __launch_bounds__(256) void wpack_kernel(
    const float* __restrict__ WAq, const float* __restrict__ WBq,
    const float* __restrict__ WAk, const float* __restrict__ WBk,
    const float* __restrict__ WAv, const float* __restrict__ WBv)
{
    int i = blockIdx.x * 256 + threadIdx.x;      // over 1024*1024
    int row = i >> 10, c = i & 1023;
    const float* src; int lc, N;
    if      (c < 128) { src = WAq; lc = c;       N = 96;  }
    else if (c < 512) { src = WBq; lc = c - 128; N = 384; }
    else if (c < 640) { src = WAk; lc = c - 512; N = 32;  }
    else if (c < 768) { src = WBk; lc = c - 640; N = 128; }
    else if (c < 896) { src = WAv; lc = c - 768; N = 32;  }
    else              { src = WBv; lc = c - 896; N = 128; }
    float v = (lc < N) ? src[(size_t)row * N + lc] : 0.f;
    split2(v, g_wH[i], g_wL[i]);
}

// ---------------- split-bf16 GEMM 128x128, BK=32, cp.async x2 stages ----------------
#define G_OA_H 0
#define G_OA_L (128*40)
#define G_OB_H (256*40)
#define G_OB_L (256*40 + 32*136)
#define G_STG  (256*40 + 64*136)     // 18944 elems per stage
#define GSMEM  (2*G_STG*2)           // bytes = 75776

using GFA = wmma::fragment<wmma::matrix_a,16,16,16,bf16,wmma::row_major>;
using GFB = wmma::fragment<wmma::matrix_b,16,16,16,bf16,wmma::row_major>;
using GFC = wmma::fragment<wmma::accumulator,16,16,16,float>;

__device__ __forceinline__ void gemm_issue(
    bf16* smbase, int stage, int t,
    const bf16* AH, const bf16* AL, const bf16* BH, const bf16* BL,
    int m0, int n0, int k0)
{
    unsigned s0 = sm_u32(smbase) + stage * G_STG * 2;
    #pragma unroll
    for (int rep = 0; rep < 2; rep++) {
        int id  = t + rep * 256;
        int ar  = id >> 2, ac = (id & 3) * 8;
        unsigned da = s0 + (ar*40 + ac) * 2;
        const bf16* sa = AH + (size_t)(m0 + ar) * 1024 + k0 + ac;
        CPA16(da + G_OA_H*2, sa);
        CPA16(da + G_OA_L*2, AL + (size_t)(m0 + ar) * 1024 + k0 + ac);
        int brr = id >> 4, bc = (id & 15) * 8;
        unsigned db = s0 + (brr*136 + bc) * 2;
        CPA16(db + G_OB_H*2, BH + (size_t)(k0 + brr) * 1024 + n0 + bc);
        CPA16(db + G_OB_L*2, BL + (size_t)(k0 + brr) * 1024 + n0 + bc);
    }
}

__device__ __forceinline__ void gemm_body(
    const bf16* __restrict__ AH, const bf16* __restrict__ AL,
    const bf16* __restrict__ BH, const bf16* __restrict__ BL,
    float* __restrict__ C, int m0, int n0)
{
    extern __shared__ __align__(16) char gsm[];
    bf16* smb = (bf16*)gsm;

    const int t = threadIdx.x, wid = t >> 5;
    const int wm = wid >> 2, wn = wid & 3;     // 2 x 4 warps, warp tile 64x32

    GFC c[4][2];
    #pragma unroll
    for (int i = 0; i < 4; i++)
        #pragma unroll
        for (int j = 0; j < 2; j++)
            wmma::fill_fragment(c[i][j], 0.f);

    gemm_issue(smb, 0, t, AH, AL, BH, BL, m0, n0, 0);
    CPA_COMMIT();
    gemm_issue(smb, 1, t, AH, AL, BH, BL, m0, n0, 32);
    CPA_COMMIT();

    for (int it = 0; it < 32; it++) {
        CPA_WAIT1();
        __syncthreads();
        const int st = it & 1;
        const bf16* AHs = smb + st*G_STG + G_OA_H;
        const bf16* ALs = smb + st*G_STG + G_OA_L;
        const bf16* BHs = smb + st*G_STG + G_OB_H;
        const bf16* BLs = smb + st*G_STG + G_OB_L;

        #pragma unroll
        for (int ks = 0; ks < 2; ks++) {
            GFA ah[4], al[4];
            GFB bh[2], bl[2];
            #pragma unroll
            for (int i = 0; i < 4; i++) {
                wmma::load_matrix_sync(ah[i], AHs + (wm*64 + i*16)*40 + ks*16, 40);
                wmma::load_matrix_sync(al[i], ALs + (wm*64 + i*16)*40 + ks*16, 40);
            }
            #pragma unroll
            for (int j = 0; j < 2; j++) {
                wmma::load_matrix_sync(bh[j], BHs + (ks*16)*136 + wn*32 + j*16, 136);
                wmma::load_matrix_sync(bl[j], BLs + (ks*16)*136 + wn*32 + j*16, 136);
            }
            #pragma unroll
            for (int i = 0; i < 4; i++)
                #pragma unroll
                for (int j = 0; j < 2; j++) {
                    wmma::mma_sync(c[i][j], ah[i], bh[j], c[i][j]);
                    wmma::mma_sync(c[i][j], ah[i], bl[j], c[i][j]);
                    wmma::mma_sync(c[i][j], al[i], bh[j], c[i][j]);
                }
        }
        __syncthreads();
        int kn = (it + 2) * 32;
        if (kn < 1024)
            gemm_issue(smb, st, t, AH, AL, BH, BL, m0, n0, kn);
        CPA_COMMIT();
    }

    #pragma unroll
    for (int i = 0; i < 4; i++)
        #pragma unroll
        for (int j = 0; j < 2; j++)
            wmma::store_matrix_sync(C + (size_t)(m0 + wm*64 + i*16) * 1024 + n0 + wn*32 + j*16,
                                    c[i][j], 1024, wmma::mem_row_major);
}

__global__ __launch_bounds__(256) void proj_k()
{
    const int x = blockIdx.x;
    const bf16 *AH, *AL;
    if      (x < 4) { AH = g_xqH; AL = g_xqL; }
    else if (x < 6) { AH = g_xkH; AL = g_xkL; }
    else            { AH = g_xvH; AL = g_xvL; }
    gemm_body(AH, AL, g_wH, g_wL, g_proj, blockIdx.y * 128, x * 128);
}

__global__ __launch_bounds__(256) void gemm_wo_k(float* __restrict__ C)
{
    gemm_body(g_attH, g_attL, g_woH, g_woL, C, blockIdx.y * 128, blockIdx.x * 128);
}

// ---------------- combine: rank contraction + rotary + scales -> split bf16 ----------------
__global__ __launch_bounds__(256) void combine_kernel()
{
    const int m = blockIdx.x;
    const int b = m / Sn, s = m % Sn;
    const int t = threadIdx.x;

    __shared__ float rowp[1024];
    __shared__ float sCos[32], sSin[32];

    #pragma unroll
    for (int i = 0; i < 1; i++)
        ((float4*)rowp)[t] = ((const float4*)(g_proj + (size_t)m * 1024))[t];
    if (t < 32) {
        float inv = expf(-((float)(2*t) / 64.f) * logf(10000.0f));
        float fr  = (float)s * inv;
        sCos[t] = cosf(fr);
        sSin[t] = sinf(fr);
    }
    __syncthreads();

    const float qscale = (1.0f / QR) * (1.0f / (float)DKn);

    for (int pi = t; pi < Hn*DKn/2; pi += 256) {
        const int h = pi >> 5, dp = pi & 31, d0 = dp * 2;
        const size_t ob = ((size_t)(b*Hn + h) * Sn + s) * 64 + d0;

        float qv[2], kv[2], vv[2];
        #pragma unroll
        for (int e = 0; e < 2; e++) {
            const int d = d0 + e, dl = d & 31;
            const float cc = sCos[dl], sn = sSin[dl];
            float r1 = 0.f, r2 = 0.f;
            #pragma unroll
            for (int r = 0; r < QR; r++) {
                const float a = rowp[h*QR + r];
                r1 += a * rowp[128 + r*64 + dl];
                r2 += a * rowp[128 + r*64 + dl + 32];
            }
            qv[e] = ((d < 32) ? (r1*cc + r2*sn) : (-r1*sn + r2*cc)) * qscale;

            r1 = 0.f; r2 = 0.f;
            #pragma unroll
            for (int r = 0; r < RK; r++) {
                const float a = rowp[512 + h*RK + r];
                r1 += a * rowp[640 + r*64 + dl];
                r2 += a * rowp[640 + r*64 + dl + 32];
            }
            kv[e] = ((d < 32) ? (r1*cc + r2*sn) : (-r1*sn + r2*cc)) * 0.5f;

            float vs = 0.f;
            #pragma unroll
            for (int r = 0; r < RK; r++)
                vs += rowp[768 + h*RK + r] * rowp[896 + r*64 + d];
            vv[e] = vs * 0.5f;
        }
        __nv_bfloat162 hh, ll;
        bf16 h0,l0,h1,l1;
        split2(qv[0],h0,l0); split2(qv[1],h1,l1);
        hh.x=h0; hh.y=h1; ll.x=l0; ll.y=l1;
        *(__nv_bfloat162*)(g_qhH + ob) = hh; *(__nv_bfloat162*)(g_qhL + ob) = ll;
        split2(kv[0],h0,l0); split2(kv[1],h1,l1);
        hh.x=h0; hh.y=h1; ll.x=l0; ll.y=l1;
        *(__nv_bfloat162*)(g_khH + ob) = hh; *(__nv_bfloat162*)(g_khL + ob) = ll;
        split2(vv[0],h0,l0); split2(vv[1],h1,l1);
        hh.x=h0; hh.y=h1; ll.x=l0; ll.y=l1;
        *(__nv_bfloat162*)(g_vhH + ob) = hh; *(__nv_bfloat162*)(g_vhL + ob) = ll;
    }
}

// ---------------- flash attention on raw mma.m16n8k16 ----------------
// Br=128 (8 warps x 16 rows), Bc=64 per tile. Per warp: 16 x 64 scores,
// Q frags persistent in regs, softmax in regs, P->bf16x2 direct.
#define F_QH 0
#define F_QL (128*72)
#define F_KH (2*128*72)
#define F_KL (2*128*72 + 64*72)
#define F_VH (2*128*72 + 2*64*72)
#define F_VL (2*128*72 + 3*64*72)
#define FSMEM ((2*128*72 + 4*64*72) * 2)     // 73728 bytes

__global__ __launch_bounds__(256) void flash_mma()
{
    extern __shared__ __align__(16) char fsm[];
    bf16* smb = (bf16*)fsm;

    const int qt = (gridDim.x - 1) - blockIdx.x;  // heavy first
    const int h = blockIdx.y, b = blockIdx.z;
    const int q0 = qt * 128;

    const size_t hb = (size_t)(b*Hn + h) * Sn * 64;
    const bf16* QHg = g_qhH + hb; const bf16* QLg = g_qhL + hb;
    const bf16* KHg = g_khH + hb; const bf16* KLg = g_khL + hb;
    const bf16* VHg = g_vhH + hb; const bf16* VLg = g_vhL + hb;

    const int t = threadIdx.x, w = t >> 5, lane = t & 31;
    const int sub = lane >> 3, r8 = lane & 7;

    // stage Q (hi/lo) into smem
    {
        const int row = t >> 1, half = (t & 1) * 32;
        const uint4* sh = (const uint4*)(QHg + (size_t)(q0 + row) * 64 + half);
        const uint4* sl = (const uint4*)(QLg + (size_t)(q0 + row) * 64 + half);
        uint4* dh = (uint4*)(smb + F_QH + row*72 + half);
        uint4* dl = (uint4*)(smb + F_QL + row*72 + half);
        #pragma unroll
        for (int i = 0; i < 4; i++) { dh[i] = sh[i]; dl[i] = sl[i]; }
    }
    __syncthreads();

    // persistent Q fragments
    unsigned qa[4][4], ql[4][4];
    {
        const unsigned qoff = ((w*16 + (sub & 1)*8 + r8) * 72 + (sub >> 1) * 8);
        #pragma unroll
        for (int ks = 0; ks < 4; ks++) {
            ldsm4(qa[ks], sm_u32(smb + F_QH + qoff + ks*16));
            ldsm4(ql[ks], sm_u32(smb + F_QL + qoff + ks*16));
        }
    }

    float o[8][4];
    #pragma unroll
    for (int g = 0; g < 8; g++)
        #pragma unroll
        for (int e = 0; e < 4; e++) o[g][e] = 0.f;
    float m0s = -CUDART_INF_F, m1s = -CUDART_INF_F, l0s = 0.f, l1s = 0.f;

    const int nk = 2*qt + 2;
    const int krow = t >> 2, kcoff = (t & 3) * 16;

    for (int kt = 0; kt < nk; kt++) {
        const int k0 = kt * 64;
        __syncthreads();
        {
            const size_t so = (size_t)(k0 + krow) * 64 + kcoff;
            uint4* dKH = (uint4*)(smb + F_KH + krow*72 + kcoff);
            uint4* dKL = (uint4*)(smb + F_KL + krow*72 + kcoff);
            uint4* dVH = (uint4*)(smb + F_VH + krow*72 + kcoff);
            uint4* dVL = (uint4*)(smb + F_VL + krow*72 + kcoff);
            #pragma unroll
            for (int i = 0; i < 2; i++) {
                dKH[i] = ((const uint4*)(KHg + so))[i];
                dKL[i] = ((const uint4*)(KLg + so))[i];
                dVH[i] = ((const uint4*)(VHg + so))[i];
                dVL[i] = ((const uint4*)(VLg + so))[i];
            }
        }
        __syncthreads();

        if (k0 <= q0 + w*16 + 15) {       // warp has unmasked rows
            float s[8][4];
            #pragma unroll
            for (int g = 0; g < 8; g++)
                #pragma unroll
                for (int e = 0; e < 4; e++) s[g][e] = 0.f;

            // S = Q K^T
            #pragma unroll
            for (int ks = 0; ks < 4; ks++) {
                #pragma unroll
                for (int jp = 0; jp < 4; jp++) {
                    unsigned koff = ((2*jp*8 + (sub>>1)*8 + r8) * 72 + ks*16 + (sub & 1)*8);
                    unsigned bh[4], bl[4];
                    ldsm4(bh, sm_u32(smb + F_KH + koff));
                    ldsm4(bl, sm_u32(smb + F_KL + koff));
                    mma16816(s[2*jp],   qa[ks], bh);
                    mma16816(s[2*jp],   qa[ks], bl);
                    mma16816(s[2*jp],   ql[ks], bh);
                    mma16816(s[2*jp+1], qa[ks], bh + 2);
                    mma16816(s[2*jp+1], qa[ks], bl + 2);
                    mma16816(s[2*jp+1], ql[ks], bh + 2);
                }
            }

            // causal mask (only last two tiles)
            if (kt >= 2*qt) {
                const int row0 = q0 + w*16 + (lane >> 2);
                #pragma unroll
                for (int g = 0; g < 8; g++) {
                    const int col = k0 + g*8 + ((lane & 3) << 1);
                    if (col     > row0)     s[g][0] = -CUDART_INF_F;
                    if (col + 1 > row0)     s[g][1] = -CUDART_INF_F;
                    if (col     > row0 + 8) s[g][2] = -CUDART_INF_F;
                    if (col + 1 > row0 + 8) s[g][3] = -CUDART_INF_F;
                }
            }

            // online softmax (rows r0, r0+8)
            float ml0 = -CUDART_INF_F, ml1 = -CUDART_INF_F;
            #pragma unroll
            for (int g = 0; g < 8; g++) {
                ml0 = fmaxf(ml0, fmaxf(s[g][0], s[g][1]));
                ml1 = fmaxf(ml1, fmaxf(s[g][2], s[g][3]));
            }
            ml0 = fmaxf(ml0, __shfl_xor_sync(0xffffffffu, ml0, 1));
            ml0 = fmaxf(ml0, __shfl_xor_sync(0xffffffffu, ml0, 2));
            ml1 = fmaxf(ml1, __shfl_xor_sync(0xffffffffu, ml1, 1));
            ml1 = fmaxf(ml1, __shfl_xor_sync(0xffffffffu, ml1, 2));
            const float mn0 = fmaxf(m0s, ml0), mn1 = fmaxf(m1s, ml1);
            const float a0 = __expf(m0s - mn0), a1 = __expf(m1s - mn1);
            m0s = mn0; m1s = mn1;
            float ps0 = 0.f, ps1 = 0.f;
            #pragma unroll
            for (int g = 0; g < 8; g++) {
                s[g][0] = __expf(s[g][0] - mn0); ps0 += s[g][0];
                s[g][1] = __expf(s[g][1] - mn0); ps0 += s[g][1];
                s[g][2] = __expf(s[g][2] - mn1); ps1 += s[g][2];
                s[g][3] = __expf(s[g][3] - mn1); ps1 += s[g][3];
            }
            ps0 += __shfl_xor_sync(0xffffffffu, ps0, 1);
            ps0 += __shfl_xor_sync(0xffffffffu, ps0, 2);
            ps1 += __shfl_xor_sync(0xffffffffu, ps1, 1);
            ps1 += __shfl_xor_sync(0xffffffffu, ps1, 2);
            l0s = l0s * a0 + ps0;
            l1s = l1s * a1 + ps1;
            #pragma unroll
            for (int g = 0; g < 8; g++) {
                o[g][0] *= a0; o[g][1] *= a0;
                o[g][2] *= a1; o[g][3] *= a1;
            }

            // U += P V (P split to bf16 hi/lo in regs)
            #pragma unroll
            for (int ksv = 0; ksv < 4; ksv++) {
                const int gA = 2*ksv, gB = gA + 1;
                bf16 hA0 = __float2bfloat16(s[gA][0]); float rA0 = s[gA][0] - __bfloat162float(hA0);
                bf16 hA1 = __float2bfloat16(s[gA][1]); float rA1 = s[gA][1] - __bfloat162float(hA1);
                bf16 hA2 = __float2bfloat16(s[gA][2]); float rA2 = s[gA][2] - __bfloat162float(hA2);
                bf16 hA3 = __float2bfloat16(s[gA][3]); float rA3 = s[gA][3] - __bfloat162float(hA3);
                bf16 hB0 = __float2bfloat16(s[gB][0]); float rB0 = s[gB][0] - __bfloat162float(hB0);
                bf16 hB1 = __float2bfloat16(s[gB][1]); float rB1 = s[gB][1] - __bfloat162float(hB1);
                bf16 hB2 = __float2bfloat16(s[gB][2]); float rB2 = s[gB][2] - __bfloat162float(hB2);
                bf16 hB3 = __float2bfloat16(s[gB][3]); float rB3 = s[gB][3] - __bfloat162float(hB3);
                unsigned pah[4] = { pack_us(hA0,hA1), pack_us(hA2,hA3),
                                    pack_us(hB0,hB1), pack_us(hB2,hB3) };
                unsigned pal[4] = { packbf(rA0,rA1), packbf(rA2,rA3),
                                    packbf(rB0,rB1), packbf(rB2,rB3) };
                #pragma unroll
                for (int jp = 0; jp < 4; jp++) {
                    unsigned voff = ((ksv*16 + (sub & 1)*8 + r8) * 72 + (2*jp + (sub >> 1)) * 8);
                    unsigned vh[4], vl[4];
                    ldsm4t(vh, sm_u32(smb + F_VH + voff));
                    ldsm4t(vl, sm_u32(smb + F_VL + voff));
                    mma16816(o[2*jp],   pah, vh);
                    mma16816(o[2*jp],   pah, vl);
                    mma16816(o[2*jp],   pal, vh);
                    mma16816(o[2*jp+1], pah, vh + 2);
                    mma16816(o[2*jp+1], pah, vl + 2);
                    mma16816(o[2*jp+1], pal, vh + 2);
                }
            }
        }
    }

    // epilogue: normalize, split, store
    const float il0 = 1.0f / l0s, il1 = 1.0f / l1s;
    const int row0 = q0 + w*16 + (lane >> 2);
    #pragma unroll
    for (int g = 0; g < 8; g++) {
        const size_t cb = (size_t)h*64 + g*8 + ((lane & 3) << 1);
        {
            float x0 = o[g][0] * il0, x1 = o[g][1] * il0;
            bf16 h0,l0,h1,l1;
            split2(x0,h0,l0); split2(x1,h1,l1);
            __nv_bfloat162 hh; hh.x=h0; hh.y=h1;
            __nv_bfloat162 ll; ll.x=l0; ll.y=l1;
            const size_t off = (size_t)(b*Sn + row0) * 1024 + cb;
            *(__nv_bfloat162*)(g_attH + off) = hh;
            *(__nv_bfloat162*)(g_attL + off) = ll;
        }
        {
            float x0 = o[g][2] * il1, x1 = o[g][3] * il1;
            bf16 h0,l0,h1,l1;
            split2(x0,h0,l0); split2(x1,h1,l1);
            __nv_bfloat162 hh; hh.x=h0; hh.y=h1;
            __nv_bfloat162 ll; ll.x=l0; ll.y=l1;
            const size_t off = (size_t)(b*Sn + row0 + 8) * 1024 + cb;
            *(__nv_bfloat162*)(g_attH + off) = hh;
            *(__nv_bfloat162*)(g_attL + off) = ll;
        }
    }
}

// ---------------- launch ----------------
extern "C" void kernel_launch(void* const* d_in, const int* in_sizes, int n_in,
                              void* d_out, int out_size)
{
    const float* q    = (const float*)d_in[0];
    const float* k    = (const float*)d_in[1];
    const float* v    = (const float*)d_in[2];
    const float* W_Aq = (const float*)d_in[4];
    const float* W_Ak = (const float*)d_in[5];
    const float* W_Av = (const float*)d_in[6];
    const float* W_Bq = (const float*)d_in[7];
    const float* W_Bk = (const float*)d_in[8];
    const float* W_Bv = (const float*)d_in[9];
    const float* Wo   = (const float*)d_in[10];
    float* out = (float*)d_out;

    bf16 *pqH,*pqL,*pkH,*pkL,*pvH,*pvL,*pwoH,*pwoL;
    cudaGetSymbolAddress((void**)&pqH,  g_xqH); cudaGetSymbolAddress((void**)&pqL,  g_xqL);
    cudaGetSymbolAddress((void**)&pkH,  g_xkH); cudaGetSymbolAddress((void**)&pkL,  g_xkL);
    cudaGetSymbolAddress((void**)&pvH,  g_xvH); cudaGetSymbolAddress((void**)&pvL,  g_xvL);
    cudaGetSymbolAddress((void**)&pwoH, g_woH); cudaGetSymbolAddress((void**)&pwoL, g_woL);

    cudaFuncSetAttribute(proj_k,    cudaFuncAttributeMaxDynamicSharedMemorySize, GSMEM);
    cudaFuncSetAttribute(gemm_wo_k, cudaFuncAttributeMaxDynamicSharedMemorySize, GSMEM);
    cudaFuncSetAttribute(flash_mma, cudaFuncAttributeMaxDynamicSharedMemorySize, FSMEM);

    split_kernel<<<Mrows*Dm/4/256, 256>>>(q,  pqH,  pqL,  Mrows*Dm/4);
    split_kernel<<<Mrows*Dm/4/256, 256>>>(k,  pkH,  pkL,  Mrows*Dm/4);
    split_kernel<<<Mrows*Dm/4/256, 256>>>(v,  pvH,  pvL,  Mrows*Dm/4);
    split_kernel<<<Dm*Dm/4/256,    256>>>(Wo, pwoH, pwoL, Dm*Dm/4);
    wpack_kernel<<<Dm*Dm/256, 256>>>(W_Aq, W_Bq, W_Ak, W_Bk, W_Av, W_Bv);

    proj_k<<<dim3(8, Mrows/128), 256, GSMEM>>>();

    combine_kernel<<<Mrows, 256>>>();

    flash_mma<<<dim3(Sn/128, Hn, Bn), 256, FSMEM>>>();

    gemm_wo_k<<<dim3(8, Mrows/128), 256, GSMEM>>>(out);
}

// round 6
// speedup vs baseline: 5.9144x; 1.0203x over previous
#include <cuda_runtime.h>
#include <cuda_bf16.h>
#include <math_constants.h>
#include <mma.h>
#include <cstddef>
#include <cstdint>

using namespace nvcuda;
using bf16 = __nv_bfloat16;

#define Bn   2
#define Sn   2048
#define Hn   16
#define DKn  64
#define Dm   1024
#define QR   6
#define RK   2
#define Mrows (Bn*Sn)

// ---------------- global scratch ----------------
__device__ bf16 g_xqH[Mrows*Dm], g_xqL[Mrows*Dm];
__device__ bf16 g_xkH[Mrows*Dm], g_xkL[Mrows*Dm];
__device__ bf16 g_xvH[Mrows*Dm], g_xvL[Mrows*Dm];
__device__ bf16 g_wH [Dm*Dm],   g_wL [Dm*Dm];     // packed proj weights [k][n-packed]
__device__ bf16 g_woH[Dm*Dm],   g_woL[Dm*Dm];     // Wo [k][n]
__device__ float g_proj[Mrows*Dm];
__device__ bf16 g_qhH[Bn*Hn*Sn*DKn], g_qhL[Bn*Hn*Sn*DKn];
__device__ bf16 g_khH[Bn*Hn*Sn*DKn], g_khL[Bn*Hn*Sn*DKn];
__device__ bf16 g_vhH[Bn*Hn*Sn*DKn], g_vhL[Bn*Hn*Sn*DKn];
__device__ bf16 g_attH[Mrows*Dm], g_attL[Mrows*Dm];

// ---------------- helpers ----------------
__device__ __forceinline__ void split2(float x, bf16& h, bf16& l)
{
    h = __float2bfloat16(x);
    l = __float2bfloat16(x - __bfloat162float(h));
}
__device__ __forceinline__ unsigned sm_u32(const void* p)
{
    return (unsigned)__cvta_generic_to_shared(p);
}
__device__ __forceinline__ void ldsm4(unsigned r[4], unsigned a)
{
    asm volatile("ldmatrix.sync.aligned.m8n8.x4.shared.b16 {%0,%1,%2,%3}, [%4];"
        : "=r"(r[0]), "=r"(r[1]), "=r"(r[2]), "=r"(r[3]) : "r"(a));
}
__device__ __forceinline__ void ldsm4t(unsigned r[4], unsigned a)
{
    asm volatile("ldmatrix.sync.aligned.m8n8.x4.trans.shared.b16 {%0,%1,%2,%3}, [%4];"
        : "=r"(r[0]), "=r"(r[1]), "=r"(r[2]), "=r"(r[3]) : "r"(a));
}
__device__ __forceinline__ void mma16816(float c[4], const unsigned a[4], const unsigned b[2])
{
    asm volatile(
        "mma.sync.aligned.m16n8k16.row.col.f32.bf16.bf16.f32 "
        "{%0,%1,%2,%3},{%4,%5,%6,%7},{%8,%9},{%0,%1,%2,%3};"
        : "+f"(c[0]), "+f"(c[1]), "+f"(c[2]), "+f"(c[3])
        : "r"(a[0]), "r"(a[1]), "r"(a[2]), "r"(a[3]), "r"(b[0]), "r"(b[1]));
}
__device__ __forceinline__ unsigned packbf(float lo, float hi)
{
    unsigned r;
    asm("cvt.rn.bf16x2.f32 %0, %1, %2;" : "=r"(r) : "f"(hi), "f"(lo));
    return r;
}
__device__ __forceinline__ unsigned pack_us(bf16 lo, bf16 hi)
{
    return ((unsigned)__bfloat16_as_ushort(hi) << 16) | (unsigned)__bfloat16_as_ushort(lo);
}
#define CPA16(dst, src) \
    asm volatile("cp.async.cg.shared.global [%0], [%1], 16;" :: "r"(dst), "l"(src))
#define CPA_COMMIT() asm volatile("cp.async.commit_group;")
#define CPA_WAIT1()  asm volatile("cp.async.wait_group 1;")
#define CPA_WAIT0()  asm volatile("cp.async.wait_group 0;")

// ---------------- presplit kernels ----------------
__global__ __launch_bounds__(256) void split_kernel(
    const float* __restrict__ src, bf16* __restrict__ dh, bf16* __restrict__ dl, int n4)
{
    int i = blockIdx.x * 256 + threadIdx.x;
    if (i >= n4) return;
    float4 f = ((const float4*)src)[i];
    bf16 h0,l0,h1,l1,h2,l2,h3,l3;
    split2(f.x,h0,l0); split2(f.y,h1,l1); split2(f.z,h2,l2); split2(f.w,h3,l3);
    __nv_bfloat162 a; a.x=h0; a.y=h1;
    __nv_bfloat162 b; b.x=h2; b.y=h3;
    ((__nv_bfloat162*)dh)[i*2]   = a;
    ((__nv_bfloat162*)dh)[i*2+1] = b;
    a.x=l0; a.y=l1; b.x=l2; b.y=l3;
    ((__nv_bfloat162*)dl)[i*2]   = a;
    ((__nv_bfloat162*)dl)[i*2+1] = b;
}

// pack weights into [1024][1024]: Aq@0(96/128) Bq@128(384) Ak@512(32/128) Bk@640 Av@768(32/128) Bv@896
__global__ __launch_bounds__(256) void wpack_kernel(
    const float* __restrict__ WAq, const float* __restrict__ WBq,
    const float* __restrict__ WAk, const float* __restrict__ WBk,
    const float* __restrict__ WAv, const float* __restrict__ WBv)
{
    int i = blockIdx.x * 256 + threadIdx.x;
    int row = i >> 10, c = i & 1023;
    const float* src; int lc, N;
    if      (c < 128) { src = WAq; lc = c;       N = 96;  }
    else if (c < 512) { src = WBq; lc = c - 128; N = 384; }
    else if (c < 640) { src = WAk; lc = c - 512; N = 32;  }
    else if (c < 768) { src = WBk; lc = c - 640; N = 128; }
    else if (c < 896) { src = WAv; lc = c - 768; N = 32;  }
    else              { src = WBv; lc = c - 896; N = 128; }
    float v = (lc < N) ? src[(size_t)row * N + lc] : 0.f;
    split2(v, g_wH[i], g_wL[i]);
}

// ---------------- split-bf16 GEMM: CTA 128x256, warp 64x64, BK=32, 2-stage cp.async ----------------
#define GA_H 0
#define GA_L (128*40)
#define GB_H (2*128*40)
#define GB_L (2*128*40 + 32*264)
#define G_STG (2*128*40 + 2*32*264)   // 27136 elems / stage
#define GSMEM (2*G_STG*2)             // 108544 bytes

using GFA = wmma::fragment<wmma::matrix_a,16,16,16,bf16,wmma::row_major>;
using GFB = wmma::fragment<wmma::matrix_b,16,16,16,bf16,wmma::row_major>;
using GFC = wmma::fragment<wmma::accumulator,16,16,16,float>;

__device__ __forceinline__ void gemm_issue(
    bf16* smbase, int stage, int t,
    const bf16* AH, const bf16* AL, const bf16* BH, const bf16* BL,
    int m0, int n0, int k0)
{
    unsigned s0 = sm_u32(smbase) + stage * G_STG * 2;
    #pragma unroll
    for (int rep = 0; rep < 2; rep++) {
        const int id = t + rep * 256;          // 512 chunks for A (128r x 32k)
        const int ar = id >> 2, ac = (id & 3) * 8;
        const size_t go = (size_t)(m0 + ar) * 1024 + k0 + ac;
        unsigned d = s0 + (ar*40 + ac) * 2;
        CPA16(d + GA_H*2, AH + go);
        CPA16(d + GA_L*2, AL + go);
    }
    #pragma unroll
    for (int rep = 0; rep < 4; rep++) {
        const int id = t + rep * 256;          // 1024 chunks for B (32k x 256n)
        const int kr = id >> 5, nc = (id & 31) * 8;
        const size_t go = (size_t)(k0 + kr) * 1024 + n0 + nc;
        unsigned d = s0 + (kr*264 + nc) * 2;
        CPA16(d + GB_H*2, BH + go);
        CPA16(d + GB_L*2, BL + go);
    }
}

__device__ __forceinline__ void gemm_body(
    const bf16* __restrict__ AH, const bf16* __restrict__ AL,
    const bf16* __restrict__ BH, const bf16* __restrict__ BL,
    float* __restrict__ C, int m0, int n0)
{
    extern __shared__ __align__(16) char gsm[];
    bf16* smb = (bf16*)gsm;

    const int t = threadIdx.x, wid = t >> 5;
    const int wm = wid >> 2, wn = wid & 3;     // 2 x 4 warps, warp tile 64x64

    GFC c[4][4];
    #pragma unroll
    for (int i = 0; i < 4; i++)
        #pragma unroll
        for (int j = 0; j < 4; j++)
            wmma::fill_fragment(c[i][j], 0.f);

    gemm_issue(smb, 0, t, AH, AL, BH, BL, m0, n0, 0);
    CPA_COMMIT();
    gemm_issue(smb, 1, t, AH, AL, BH, BL, m0, n0, 32);
    CPA_COMMIT();

    for (int it = 0; it < 32; it++) {
        CPA_WAIT1();
        __syncthreads();
        const int st = it & 1;
        const bf16* AHs = smb + st*G_STG + GA_H;
        const bf16* ALs = smb + st*G_STG + GA_L;
        const bf16* BHs = smb + st*G_STG + GB_H;
        const bf16* BLs = smb + st*G_STG + GB_L;

        #pragma unroll
        for (int ks = 0; ks < 2; ks++) {
            GFA ah[4], al[4];
            #pragma unroll
            for (int i = 0; i < 4; i++) {
                wmma::load_matrix_sync(ah[i], AHs + (wm*64 + i*16)*40 + ks*16, 40);
                wmma::load_matrix_sync(al[i], ALs + (wm*64 + i*16)*40 + ks*16, 40);
            }
            #pragma unroll
            for (int j = 0; j < 4; j++) {
                GFB bh, bl;
                wmma::load_matrix_sync(bh, BHs + (ks*16)*264 + wn*64 + j*16, 264);
                wmma::load_matrix_sync(bl, BLs + (ks*16)*264 + wn*64 + j*16, 264);
                #pragma unroll
                for (int i = 0; i < 4; i++) {
                    wmma::mma_sync(c[i][j], ah[i], bh, c[i][j]);
                    wmma::mma_sync(c[i][j], ah[i], bl, c[i][j]);
                    wmma::mma_sync(c[i][j], al[i], bh, c[i][j]);
                }
            }
        }
        __syncthreads();
        const int kn = (it + 2) * 32;
        if (kn < 1024)
            gemm_issue(smb, st, t, AH, AL, BH, BL, m0, n0, kn);
        CPA_COMMIT();
    }

    #pragma unroll
    for (int i = 0; i < 4; i++)
        #pragma unroll
        for (int j = 0; j < 4; j++)
            wmma::store_matrix_sync(C + (size_t)(m0 + wm*64 + i*16) * 1024 + n0 + wn*64 + j*16,
                                    c[i][j], 1024, wmma::mem_row_major);
}

__global__ __launch_bounds__(256) void proj_k()
{
    const int x = blockIdx.x;            // n-tile of 256
    const bf16 *AH, *AL;
    if      (x < 2)  { AH = g_xqH; AL = g_xqL; }
    else if (x == 2) { AH = g_xkH; AL = g_xkL; }
    else             { AH = g_xvH; AL = g_xvL; }
    gemm_body(AH, AL, g_wH, g_wL, g_proj, blockIdx.y * 128, x * 256);
}

__global__ __launch_bounds__(256) void gemm_wo_k(float* __restrict__ C)
{
    gemm_body(g_attH, g_attL, g_woH, g_woL, C, blockIdx.y * 128, blockIdx.x * 256);
}

// ---------------- combine: rank contraction + rotary + scales -> split bf16 ----------------
__global__ __launch_bounds__(256) void combine_kernel()
{
    const int m = blockIdx.x;
    const int b = m / Sn, s = m % Sn;
    const int t = threadIdx.x;

    __shared__ float rowp[1024];
    __shared__ float sCos[32], sSin[32];

    ((float4*)rowp)[t] = ((const float4*)(g_proj + (size_t)m * 1024))[t];
    if (t < 32) {
        float inv = expf(-((float)(2*t) / 64.f) * logf(10000.0f));
        float fr  = (float)s * inv;
        sCos[t] = cosf(fr);
        sSin[t] = sinf(fr);
    }
    __syncthreads();

    const float qscale = (1.0f / QR) * (1.0f / (float)DKn);

    for (int pi = t; pi < Hn*DKn/2; pi += 256) {
        const int h = pi >> 5, dp = pi & 31, d0 = dp * 2;
        const size_t ob = ((size_t)(b*Hn + h) * Sn + s) * 64 + d0;

        float qv[2], kv[2], vv[2];
        #pragma unroll
        for (int e = 0; e < 2; e++) {
            const int d = d0 + e, dl = d & 31;
            const float cc = sCos[dl], sn = sSin[dl];
            float r1 = 0.f, r2 = 0.f;
            #pragma unroll
            for (int r = 0; r < QR; r++) {
                const float a = rowp[h*QR + r];
                r1 += a * rowp[128 + r*64 + dl];
                r2 += a * rowp[128 + r*64 + dl + 32];
            }
            qv[e] = ((d < 32) ? (r1*cc + r2*sn) : (-r1*sn + r2*cc)) * qscale;

            r1 = 0.f; r2 = 0.f;
            #pragma unroll
            for (int r = 0; r < RK; r++) {
                const float a = rowp[512 + h*RK + r];
                r1 += a * rowp[640 + r*64 + dl];
                r2 += a * rowp[640 + r*64 + dl + 32];
            }
            kv[e] = ((d < 32) ? (r1*cc + r2*sn) : (-r1*sn + r2*cc)) * 0.5f;

            float vs = 0.f;
            #pragma unroll
            for (int r = 0; r < RK; r++)
                vs += rowp[768 + h*RK + r] * rowp[896 + r*64 + d];
            vv[e] = vs * 0.5f;
        }
        __nv_bfloat162 hh, ll;
        bf16 h0,l0,h1,l1;
        split2(qv[0],h0,l0); split2(qv[1],h1,l1);
        hh.x=h0; hh.y=h1; ll.x=l0; ll.y=l1;
        *(__nv_bfloat162*)(g_qhH + ob) = hh; *(__nv_bfloat162*)(g_qhL + ob) = ll;
        split2(kv[0],h0,l0); split2(kv[1],h1,l1);
        hh.x=h0; hh.y=h1; ll.x=l0; ll.y=l1;
        *(__nv_bfloat162*)(g_khH + ob) = hh; *(__nv_bfloat162*)(g_khL + ob) = ll;
        split2(vv[0],h0,l0); split2(vv[1],h1,l1);
        hh.x=h0; hh.y=h1; ll.x=l0; ll.y=l1;
        *(__nv_bfloat162*)(g_vhH + ob) = hh; *(__nv_bfloat162*)(g_vhL + ob) = ll;
    }
}

// ---------------- flash attention: Br=256 (32 rows/warp), Bc=64, raw mma ----------------
// Q staged into smem then held in regs; same smem reused for K/V hi+lo tiles.
#define FQ_H 0
#define FQ_L (256*72)
#define F_KH 0
#define F_KL (64*72)
#define F_VH (2*64*72)
#define F_VL (3*64*72)
#define FSMEM (2*256*72*2)    // 73728 bytes (Q stage) >= KV (36864)

__global__ __launch_bounds__(256) void flash_mma()
{
    extern __shared__ __align__(16) char fsm[];
    bf16* smb = (bf16*)fsm;

    const int qt = (gridDim.x - 1) - blockIdx.x;   // heavy tiles first
    const int h = blockIdx.y, b = blockIdx.z;
    const int q0 = qt * 256;

    const size_t hb = (size_t)(b*Hn + h) * Sn * 64;
    const bf16* QHg = g_qhH + hb; const bf16* QLg = g_qhL + hb;
    const bf16* KHg = g_khH + hb; const bf16* KLg = g_khL + hb;
    const bf16* VHg = g_vhH + hb; const bf16* VLg = g_vhL + hb;

    const int t = threadIdx.x, w = t >> 5, lane = t & 31;
    const int sub = lane >> 3, r8 = lane & 7;

    // stage Q (hi/lo): thread t loads row t (64 bf16 = 8 uint4 per half)
    {
        const uint4* sh = (const uint4*)(QHg + (size_t)(q0 + t) * 64);
        const uint4* sl = (const uint4*)(QLg + (size_t)(q0 + t) * 64);
        uint4* dh = (uint4*)(smb + FQ_H + t*72);
        uint4* dl = (uint4*)(smb + FQ_L + t*72);
        #pragma unroll
        for (int i = 0; i < 8; i++) { dh[i] = sh[i]; dl[i] = sl[i]; }
    }
    __syncthreads();

    // persistent Q fragments: 2 row-blocks of 16 per warp
    unsigned qa[2][4][4], ql[2][4][4];
    #pragma unroll
    for (int blk = 0; blk < 2; blk++) {
        const unsigned qoff = ((w*32 + blk*16 + (sub & 1)*8 + r8) * 72 + (sub >> 1) * 8);
        #pragma unroll
        for (int ks = 0; ks < 4; ks++) {
            ldsm4(qa[blk][ks], sm_u32(smb + FQ_H + qoff + ks*16));
            ldsm4(ql[blk][ks], sm_u32(smb + FQ_L + qoff + ks*16));
        }
    }
    __syncthreads();   // Q consumed -> smem reusable for KV

    float o[2][8][4];
    #pragma unroll
    for (int blk = 0; blk < 2; blk++)
        #pragma unroll
        for (int g = 0; g < 8; g++)
            #pragma unroll
            for (int e = 0; e < 4; e++) o[blk][g][e] = 0.f;
    float ms[2][2], ls[2][2];
    #pragma unroll
    for (int blk = 0; blk < 2; blk++) {
        ms[blk][0] = ms[blk][1] = -CUDART_INF_F;
        ls[blk][0] = ls[blk][1] = 0.f;
    }

    const int nk = 4*qt + 4;
    const int krow = t >> 2, kcoff = (t & 3) * 16;

    for (int kt = 0; kt < nk; kt++) {
        const int k0 = kt * 64;
        __syncthreads();
        {
            const size_t so = (size_t)(k0 + krow) * 64 + kcoff;
            uint4* dKH = (uint4*)(smb + F_KH + krow*72 + kcoff);
            uint4* dKL = (uint4*)(smb + F_KL + krow*72 + kcoff);
            uint4* dVH = (uint4*)(smb + F_VH + krow*72 + kcoff);
            uint4* dVL = (uint4*)(smb + F_VL + krow*72 + kcoff);
            #pragma unroll
            for (int i = 0; i < 2; i++) {
                dKH[i] = ((const uint4*)(KHg + so))[i];
                dKL[i] = ((const uint4*)(KLg + so))[i];
                dVH[i] = ((const uint4*)(VHg + so))[i];
                dVL[i] = ((const uint4*)(VLg + so))[i];
            }
        }
        __syncthreads();

        if (k0 <= q0 + w*32 + 31) {        // warp has unmasked rows
            float s[2][8][4];
            #pragma unroll
            for (int blk = 0; blk < 2; blk++)
                #pragma unroll
                for (int g = 0; g < 8; g++)
                    #pragma unroll
                    for (int e = 0; e < 4; e++) s[blk][g][e] = 0.f;

            // S = Q K^T — each K fragment feeds both row blocks
            #pragma unroll
            for (int ks = 0; ks < 4; ks++) {
                #pragma unroll
                for (int jp = 0; jp < 4; jp++) {
                    const unsigned koff = ((jp*16 + (sub>>1)*8 + r8) * 72 + ks*16 + (sub & 1)*8);
                    unsigned bh[4], bl[4];
                    ldsm4(bh, sm_u32(smb + F_KH + koff));
                    ldsm4(bl, sm_u32(smb + F_KL + koff));
                    #pragma unroll
                    for (int blk = 0; blk < 2; blk++) {
                        mma16816(s[blk][2*jp],   qa[blk][ks], bh);
                        mma16816(s[blk][2*jp],   qa[blk][ks], bl);
                        mma16816(s[blk][2*jp],   ql[blk][ks], bh);
                        mma16816(s[blk][2*jp+1], qa[blk][ks], bh + 2);
                        mma16816(s[blk][2*jp+1], qa[blk][ks], bl + 2);
                        mma16816(s[blk][2*jp+1], ql[blk][ks], bh + 2);
                    }
                }
            }

            // causal mask
            if (k0 + 63 > q0 + w*32) {
                #pragma unroll
                for (int blk = 0; blk < 2; blk++) {
                    const int row0 = q0 + w*32 + blk*16 + (lane >> 2);
                    #pragma unroll
                    for (int g = 0; g < 8; g++) {
                        const int col = k0 + g*8 + ((lane & 3) << 1);
                        if (col     > row0)     s[blk][g][0] = -CUDART_INF_F;
                        if (col + 1 > row0)     s[blk][g][1] = -CUDART_INF_F;
                        if (col     > row0 + 8) s[blk][g][2] = -CUDART_INF_F;
                        if (col + 1 > row0 + 8) s[blk][g][3] = -CUDART_INF_F;
                    }
                }
            }

            // online softmax per row block
            #pragma unroll
            for (int blk = 0; blk < 2; blk++) {
                float ml0 = -CUDART_INF_F, ml1 = -CUDART_INF_F;
                #pragma unroll
                for (int g = 0; g < 8; g++) {
                    ml0 = fmaxf(ml0, fmaxf(s[blk][g][0], s[blk][g][1]));
                    ml1 = fmaxf(ml1, fmaxf(s[blk][g][2], s[blk][g][3]));
                }
                ml0 = fmaxf(ml0, __shfl_xor_sync(0xffffffffu, ml0, 1));
                ml0 = fmaxf(ml0, __shfl_xor_sync(0xffffffffu, ml0, 2));
                ml1 = fmaxf(ml1, __shfl_xor_sync(0xffffffffu, ml1, 1));
                ml1 = fmaxf(ml1, __shfl_xor_sync(0xffffffffu, ml1, 2));
                const float mn0 = fmaxf(ms[blk][0], ml0), mn1 = fmaxf(ms[blk][1], ml1);
                const float a0 = __expf(ms[blk][0] - mn0), a1 = __expf(ms[blk][1] - mn1);
                ms[blk][0] = mn0; ms[blk][1] = mn1;
                float ps0 = 0.f, ps1 = 0.f;
                #pragma unroll
                for (int g = 0; g < 8; g++) {
                    s[blk][g][0] = __expf(s[blk][g][0] - mn0); ps0 += s[blk][g][0];
                    s[blk][g][1] = __expf(s[blk][g][1] - mn0); ps0 += s[blk][g][1];
                    s[blk][g][2] = __expf(s[blk][g][2] - mn1); ps1 += s[blk][g][2];
                    s[blk][g][3] = __expf(s[blk][g][3] - mn1); ps1 += s[blk][g][3];
                }
                ps0 += __shfl_xor_sync(0xffffffffu, ps0, 1);
                ps0 += __shfl_xor_sync(0xffffffffu, ps0, 2);
                ps1 += __shfl_xor_sync(0xffffffffu, ps1, 1);
                ps1 += __shfl_xor_sync(0xffffffffu, ps1, 2);
                ls[blk][0] = ls[blk][0] * a0 + ps0;
                ls[blk][1] = ls[blk][1] * a1 + ps1;
                #pragma unroll
                for (int g = 0; g < 8; g++) {
                    o[blk][g][0] *= a0; o[blk][g][1] *= a0;
                    o[blk][g][2] *= a1; o[blk][g][3] *= a1;
                }
            }

            // U += P V — each V fragment feeds both row blocks
            #pragma unroll
            for (int ksv = 0; ksv < 4; ksv++) {
                unsigned pah[2][4], pal[2][4];
                #pragma unroll
                for (int blk = 0; blk < 2; blk++) {
                    const int gA = 2*ksv, gB = gA + 1;
                    bf16 hA0 = __float2bfloat16(s[blk][gA][0]); float rA0 = s[blk][gA][0] - __bfloat162float(hA0);
                    bf16 hA1 = __float2bfloat16(s[blk][gA][1]); float rA1 = s[blk][gA][1] - __bfloat162float(hA1);
                    bf16 hA2 = __float2bfloat16(s[blk][gA][2]); float rA2 = s[blk][gA][2] - __bfloat162float(hA2);
                    bf16 hA3 = __float2bfloat16(s[blk][gA][3]); float rA3 = s[blk][gA][3] - __bfloat162float(hA3);
                    bf16 hB0 = __float2bfloat16(s[blk][gB][0]); float rB0 = s[blk][gB][0] - __bfloat162float(hB0);
                    bf16 hB1 = __float2bfloat16(s[blk][gB][1]); float rB1 = s[blk][gB][1] - __bfloat162float(hB1);
                    bf16 hB2 = __float2bfloat16(s[blk][gB][2]); float rB2 = s[blk][gB][2] - __bfloat162float(hB2);
                    bf16 hB3 = __float2bfloat16(s[blk][gB][3]); float rB3 = s[blk][gB][3] - __bfloat162float(hB3);
                    pah[blk][0] = pack_us(hA0,hA1); pah[blk][1] = pack_us(hA2,hA3);
                    pah[blk][2] = pack_us(hB0,hB1); pah[blk][3] = pack_us(hB2,hB3);
                    pal[blk][0] = packbf(rA0,rA1);  pal[blk][1] = packbf(rA2,rA3);
                    pal[blk][2] = packbf(rB0,rB1);  pal[blk][3] = packbf(rB2,rB3);
                }
                #pragma unroll
                for (int jp = 0; jp < 4; jp++) {
                    const unsigned voff = ((ksv*16 + (sub & 1)*8 + r8) * 72 + (2*jp + (sub >> 1)) * 8);
                    unsigned vh[4], vl[4];
                    ldsm4t(vh, sm_u32(smb + F_VH + voff));
                    ldsm4t(vl, sm_u32(smb + F_VL + voff));
                    #pragma unroll
                    for (int blk = 0; blk < 2; blk++) {
                        mma16816(o[blk][2*jp],   pah[blk], vh);
                        mma16816(o[blk][2*jp],   pah[blk], vl);
                        mma16816(o[blk][2*jp],   pal[blk], vh);
                        mma16816(o[blk][2*jp+1], pah[blk], vh + 2);
                        mma16816(o[blk][2*jp+1], pah[blk], vl + 2);
                        mma16816(o[blk][2*jp+1], pal[blk], vh + 2);
                    }
                }
            }
        }
    }

    // epilogue
    #pragma unroll
    for (int blk = 0; blk < 2; blk++) {
        const float il0 = 1.0f / ls[blk][0], il1 = 1.0f / ls[blk][1];
        const int row0 = q0 + w*32 + blk*16 + (lane >> 2);
        #pragma unroll
        for (int g = 0; g < 8; g++) {
            const size_t cb = (size_t)h*64 + g*8 + ((lane & 3) << 1);
            {
                float x0 = o[blk][g][0] * il0, x1 = o[blk][g][1] * il0;
                bf16 h0,l0,h1,l1;
                split2(x0,h0,l0); split2(x1,h1,l1);
                __nv_bfloat162 hh; hh.x=h0; hh.y=h1;
                __nv_bfloat162 ll; ll.x=l0; ll.y=l1;
                const size_t off = (size_t)(b*Sn + row0) * 1024 + cb;
                *(__nv_bfloat162*)(g_attH + off) = hh;
                *(__nv_bfloat162*)(g_attL + off) = ll;
            }
            {
                float x0 = o[blk][g][2] * il1, x1 = o[blk][g][3] * il1;
                bf16 h0,l0,h1,l1;
                split2(x0,h0,l0); split2(x1,h1,l1);
                __nv_bfloat162 hh; hh.x=h0; hh.y=h1;
                __nv_bfloat162 ll; ll.x=l0; ll.y=l1;
                const size_t off = (size_t)(b*Sn + row0 + 8) * 1024 + cb;
                *(__nv_bfloat162*)(g_attH + off) = hh;
                *(__nv_bfloat162*)(g_attL + off) = ll;
            }
        }
    }
}

// ---------------- launch ----------------
extern "C" void kernel_launch(void* const* d_in, const int* in_sizes, int n_in,
                              void* d_out, int out_size)
{
    const float* q    = (const float*)d_in[0];
    const float* k    = (const float*)d_in[1];
    const float* v    = (const float*)d_in[2];
    const float* W_Aq = (const float*)d_in[4];
    const float* W_Ak = (const float*)d_in[5];
    const float* W_Av = (const float*)d_in[6];
    const float* W_Bq = (const float*)d_in[7];
    const float* W_Bk = (const float*)d_in[8];
    const float* W_Bv = (const float*)d_in[9];
    const float* Wo   = (const float*)d_in[10];
    float* out = (float*)d_out;

    bf16 *pqH,*pqL,*pkH,*pkL,*pvH,*pvL,*pwoH,*pwoL;
    cudaGetSymbolAddress((void**)&pqH,  g_xqH); cudaGetSymbolAddress((void**)&pqL,  g_xqL);
    cudaGetSymbolAddress((void**)&pkH,  g_xkH); cudaGetSymbolAddress((void**)&pkL,  g_xkL);
    cudaGetSymbolAddress((void**)&pvH,  g_xvH); cudaGetSymbolAddress((void**)&pvL,  g_xvL);
    cudaGetSymbolAddress((void**)&pwoH, g_woH); cudaGetSymbolAddress((void**)&pwoL, g_woL);

    cudaFuncSetAttribute(proj_k,    cudaFuncAttributeMaxDynamicSharedMemorySize, GSMEM);
    cudaFuncSetAttribute(gemm_wo_k, cudaFuncAttributeMaxDynamicSharedMemorySize, GSMEM);
    cudaFuncSetAttribute(flash_mma, cudaFuncAttributeMaxDynamicSharedMemorySize, FSMEM);

    split_kernel<<<Mrows*Dm/4/256, 256>>>(q,  pqH,  pqL,  Mrows*Dm/4);
    split_kernel<<<Mrows*Dm/4/256, 256>>>(k,  pkH,  pkL,  Mrows*Dm/4);
    split_kernel<<<Mrows*Dm/4/256, 256>>>(v,  pvH,  pvL,  Mrows*Dm/4);
    split_kernel<<<Dm*Dm/4/256,    256>>>(Wo, pwoH, pwoL, Dm*Dm/4);
    wpack_kernel<<<Dm*Dm/256, 256>>>(W_Aq, W_Bq, W_Ak, W_Bk, W_Av, W_Bv);

    proj_k<<<dim3(4, Mrows/128), 256, GSMEM>>>();

    combine_kernel<<<Mrows, 256>>>();

    flash_mma<<<dim3(Sn/256, Hn, Bn), 256, FSMEM>>>();

    gemm_wo_k<<<dim3(4, Mrows/128), 256, GSMEM>>>(out);
}

// round 7
// speedup vs baseline: 6.0415x; 1.0215x over previous
#include <cuda_runtime.h>
#include <cuda_bf16.h>
#include <math_constants.h>
#include <mma.h>
#include <cstddef>
#include <cstdint>

using namespace nvcuda;
using bf16 = __nv_bfloat16;

#define Bn   2
#define Sn   2048
#define Hn   16
#define DKn  64
#define Dm   1024
#define QR   6
#define RK   2
#define Mrows (Bn*Sn)

// ---------------- global scratch ----------------
__device__ bf16 g_xqH[Mrows*Dm], g_xqL[Mrows*Dm];
__device__ bf16 g_xkH[Mrows*Dm], g_xkL[Mrows*Dm];
__device__ bf16 g_xvH[Mrows*Dm], g_xvL[Mrows*Dm];
__device__ bf16 g_wH [Dm*Dm],   g_wL [Dm*Dm];     // packed proj weights [k][n-packed]
__device__ bf16 g_woH[Dm*Dm],   g_woL[Dm*Dm];     // Wo [k][n]
__device__ float g_proj[Mrows*Dm];
__device__ bf16 g_qhH[Bn*Hn*Sn*DKn], g_qhL[Bn*Hn*Sn*DKn];
__device__ bf16 g_khH[Bn*Hn*Sn*DKn], g_khL[Bn*Hn*Sn*DKn];
__device__ bf16 g_vhH[Bn*Hn*Sn*DKn], g_vhL[Bn*Hn*Sn*DKn];
__device__ bf16 g_attH[Mrows*Dm], g_attL[Mrows*Dm];

// ---------------- helpers ----------------
__device__ __forceinline__ void split2(float x, bf16& h, bf16& l)
{
    h = __float2bfloat16(x);
    l = __float2bfloat16(x - __bfloat162float(h));
}
__device__ __forceinline__ unsigned sm_u32(const void* p)
{
    return (unsigned)__cvta_generic_to_shared(p);
}
__device__ __forceinline__ void ldsm4(unsigned r[4], unsigned a)
{
    asm volatile("ldmatrix.sync.aligned.m8n8.x4.shared.b16 {%0,%1,%2,%3}, [%4];"
        : "=r"(r[0]), "=r"(r[1]), "=r"(r[2]), "=r"(r[3]) : "r"(a));
}
__device__ __forceinline__ void ldsm4t(unsigned r[4], unsigned a)
{
    asm volatile("ldmatrix.sync.aligned.m8n8.x4.trans.shared.b16 {%0,%1,%2,%3}, [%4];"
        : "=r"(r[0]), "=r"(r[1]), "=r"(r[2]), "=r"(r[3]) : "r"(a));
}
__device__ __forceinline__ void mma16816(float c[4], const unsigned a[4], const unsigned b[2])
{
    asm volatile(
        "mma.sync.aligned.m16n8k16.row.col.f32.bf16.bf16.f32 "
        "{%0,%1,%2,%3},{%4,%5,%6,%7},{%8,%9},{%0,%1,%2,%3};"
        : "+f"(c[0]), "+f"(c[1]), "+f"(c[2]), "+f"(c[3])
        : "r"(a[0]), "r"(a[1]), "r"(a[2]), "r"(a[3]), "r"(b[0]), "r"(b[1]));
}
__device__ __forceinline__ unsigned packbf(float lo, float hi)
{
    unsigned r;
    asm("cvt.rn.bf16x2.f32 %0, %1, %2;" : "=r"(r) : "f"(hi), "f"(lo));
    return r;
}
__device__ __forceinline__ unsigned pack_us(bf16 lo, bf16 hi)
{
    return ((unsigned)__bfloat16_as_ushort(hi) << 16) | (unsigned)__bfloat16_as_ushort(lo);
}
#define CPA16(dst, src) \
    asm volatile("cp.async.cg.shared.global [%0], [%1], 16;" :: "r"(dst), "l"(src))
#define CPA_COMMIT() asm volatile("cp.async.commit_group;")
#define CPA_WAIT1()  asm volatile("cp.async.wait_group 1;")
#define CPA_WAIT0()  asm volatile("cp.async.wait_group 0;")

// ---------------- presplit kernels ----------------
__global__ __launch_bounds__(256) void split_kernel(
    const float* __restrict__ src, bf16* __restrict__ dh, bf16* __restrict__ dl, int n4)
{
    int i = blockIdx.x * 256 + threadIdx.x;
    if (i >= n4) return;
    float4 f = ((const float4*)src)[i];
    bf16 h0,l0,h1,l1,h2,l2,h3,l3;
    split2(f.x,h0,l0); split2(f.y,h1,l1); split2(f.z,h2,l2); split2(f.w,h3,l3);
    __nv_bfloat162 a; a.x=h0; a.y=h1;
    __nv_bfloat162 b; b.x=h2; b.y=h3;
    ((__nv_bfloat162*)dh)[i*2]   = a;
    ((__nv_bfloat162*)dh)[i*2+1] = b;
    a.x=l0; a.y=l1; b.x=l2; b.y=l3;
    ((__nv_bfloat162*)dl)[i*2]   = a;
    ((__nv_bfloat162*)dl)[i*2+1] = b;
}

// pack weights into [1024][1024]: Aq@0(96/128) Bq@128(384) Ak@512(32/128) Bk@640 Av@768(32/128) Bv@896
__global__ __launch_bounds__(256) void wpack_kernel(
    const float* __restrict__ WAq, const float* __restrict__ WBq,
    const float* __restrict__ WAk, const float* __restrict__ WBk,
    const float* __restrict__ WAv, const float* __restrict__ WBv)
{
    int i = blockIdx.x * 256 + threadIdx.x;
    int row = i >> 10, c = i & 1023;
    const float* src; int lc, N;
    if      (c < 128) { src = WAq; lc = c;       N = 96;  }
    else if (c < 512) { src = WBq; lc = c - 128; N = 384; }
    else if (c < 640) { src = WAk; lc = c - 512; N = 32;  }
    else if (c < 768) { src = WBk; lc = c - 640; N = 128; }
    else if (c < 896) { src = WAv; lc = c - 768; N = 32;  }
    else              { src = WBv; lc = c - 896; N = 128; }
    float v = (lc < N) ? src[(size_t)row * N + lc] : 0.f;
    split2(v, g_wH[i], g_wL[i]);
}

// ---------------- split-bf16 GEMM: CTA 128x128, warp 64x32, BK=16, 2-stage, 2 CTAs/SM ----------------
#define GA_H 0
#define GA_L (128*24)
#define GB_H (2*128*24)
#define GB_L (2*128*24 + 16*136)
#define G_STG (2*128*24 + 2*16*136)   // 10496 elems / stage
#define GSMEM (2*G_STG*2)             // 41984 bytes

using GFA = wmma::fragment<wmma::matrix_a,16,16,16,bf16,wmma::row_major>;
using GFB = wmma::fragment<wmma::matrix_b,16,16,16,bf16,wmma::row_major>;
using GFC = wmma::fragment<wmma::accumulator,16,16,16,float>;

__device__ __forceinline__ void gemm_issue(
    bf16* smbase, int stage, int t,
    const bf16* AH, const bf16* AL, const bf16* BH, const bf16* BL,
    int m0, int n0, int k0)
{
    unsigned s0 = sm_u32(smbase) + stage * G_STG * 2;
    {
        const int ar = t >> 1, ac = (t & 1) * 8;   // 128 rows x 16 cols
        const size_t go = (size_t)(m0 + ar) * 1024 + k0 + ac;
        unsigned d = s0 + (ar*24 + ac) * 2;
        CPA16(d + GA_H*2, AH + go);
        CPA16(d + GA_L*2, AL + go);
    }
    {
        const int kr = t >> 4, nc = (t & 15) * 8;  // 16 rows x 128 cols
        const size_t go = (size_t)(k0 + kr) * 1024 + n0 + nc;
        unsigned d = s0 + (kr*136 + nc) * 2;
        CPA16(d + GB_H*2, BH + go);
        CPA16(d + GB_L*2, BL + go);
    }
}

__device__ __forceinline__ void gemm_body(
    const bf16* __restrict__ AH, const bf16* __restrict__ AL,
    const bf16* __restrict__ BH, const bf16* __restrict__ BL,
    float* __restrict__ C, int m0, int n0)
{
    extern __shared__ __align__(16) char gsm[];
    bf16* smb = (bf16*)gsm;

    const int t = threadIdx.x, wid = t >> 5;
    const int wm = wid >> 2, wn = wid & 3;     // 2 x 4 warps, warp tile 64x32

    GFC c[4][2];
    #pragma unroll
    for (int i = 0; i < 4; i++)
        #pragma unroll
        for (int j = 0; j < 2; j++)
            wmma::fill_fragment(c[i][j], 0.f);

    gemm_issue(smb, 0, t, AH, AL, BH, BL, m0, n0, 0);
    CPA_COMMIT();
    gemm_issue(smb, 1, t, AH, AL, BH, BL, m0, n0, 16);
    CPA_COMMIT();

    for (int it = 0; it < 64; it++) {
        CPA_WAIT1();
        __syncthreads();
        const int st = it & 1;
        const bf16* AHs = smb + st*G_STG + GA_H;
        const bf16* ALs = smb + st*G_STG + GA_L;
        const bf16* BHs = smb + st*G_STG + GB_H;
        const bf16* BLs = smb + st*G_STG + GB_L;

        GFB bh[2], bl[2];
        #pragma unroll
        for (int j = 0; j < 2; j++) {
            wmma::load_matrix_sync(bh[j], BHs + wn*32 + j*16, 136);
            wmma::load_matrix_sync(bl[j], BLs + wn*32 + j*16, 136);
        }
        #pragma unroll
        for (int i = 0; i < 4; i++) {
            GFA ah, al;
            wmma::load_matrix_sync(ah, AHs + (wm*64 + i*16)*24, 24);
            wmma::load_matrix_sync(al, ALs + (wm*64 + i*16)*24, 24);
            #pragma unroll
            for (int j = 0; j < 2; j++) {
                wmma::mma_sync(c[i][j], ah, bh[j], c[i][j]);
                wmma::mma_sync(c[i][j], ah, bl[j], c[i][j]);
                wmma::mma_sync(c[i][j], al, bh[j], c[i][j]);
            }
        }
        __syncthreads();
        const int kn = (it + 2) * 16;
        if (kn < 1024)
            gemm_issue(smb, st, t, AH, AL, BH, BL, m0, n0, kn);
        CPA_COMMIT();
    }

    #pragma unroll
    for (int i = 0; i < 4; i++)
        #pragma unroll
        for (int j = 0; j < 2; j++)
            wmma::store_matrix_sync(C + (size_t)(m0 + wm*64 + i*16) * 1024 + n0 + wn*32 + j*16,
                                    c[i][j], 1024, wmma::mem_row_major);
}

__global__ __launch_bounds__(256,2) void proj_k()
{
    const int x = blockIdx.x;            // n-tile of 128
    const bf16 *AH, *AL;
    if      (x < 4)  { AH = g_xqH; AL = g_xqL; }
    else if (x < 6)  { AH = g_xkH; AL = g_xkL; }
    else             { AH = g_xvH; AL = g_xvL; }
    gemm_body(AH, AL, g_wH, g_wL, g_proj, blockIdx.y * 128, x * 128);
}

__global__ __launch_bounds__(256,2) void gemm_wo_k(float* __restrict__ C)
{
    gemm_body(g_attH, g_attL, g_woH, g_woL, C, blockIdx.y * 128, blockIdx.x * 128);
}

// ---------------- combine: rank contraction + rotary + scales -> split bf16 ----------------
__global__ __launch_bounds__(256) void combine_kernel()
{
    const int m = blockIdx.x;
    const int b = m / Sn, s = m % Sn;
    const int t = threadIdx.x;

    __shared__ float rowp[1024];
    __shared__ float sCos[32], sSin[32];

    ((float4*)rowp)[t] = ((const float4*)(g_proj + (size_t)m * 1024))[t];
    if (t < 32) {
        float inv = expf(-((float)(2*t) / 64.f) * logf(10000.0f));
        float fr  = (float)s * inv;
        sCos[t] = cosf(fr);
        sSin[t] = sinf(fr);
    }
    __syncthreads();

    const float qscale = (1.0f / QR) * (1.0f / (float)DKn);

    for (int pi = t; pi < Hn*DKn/2; pi += 256) {
        const int h = pi >> 5, dp = pi & 31, d0 = dp * 2;
        const size_t ob = ((size_t)(b*Hn + h) * Sn + s) * 64 + d0;

        float qv[2], kv[2], vv[2];
        #pragma unroll
        for (int e = 0; e < 2; e++) {
            const int d = d0 + e, dl = d & 31;
            const float cc = sCos[dl], sn = sSin[dl];
            float r1 = 0.f, r2 = 0.f;
            #pragma unroll
            for (int r = 0; r < QR; r++) {
                const float a = rowp[h*QR + r];
                r1 += a * rowp[128 + r*64 + dl];
                r2 += a * rowp[128 + r*64 + dl + 32];
            }
            qv[e] = ((d < 32) ? (r1*cc + r2*sn) : (-r1*sn + r2*cc)) * qscale;

            r1 = 0.f; r2 = 0.f;
            #pragma unroll
            for (int r = 0; r < RK; r++) {
                const float a = rowp[512 + h*RK + r];
                r1 += a * rowp[640 + r*64 + dl];
                r2 += a * rowp[640 + r*64 + dl + 32];
            }
            kv[e] = ((d < 32) ? (r1*cc + r2*sn) : (-r1*sn + r2*cc)) * 0.5f;

            float vs = 0.f;
            #pragma unroll
            for (int r = 0; r < RK; r++)
                vs += rowp[768 + h*RK + r] * rowp[896 + r*64 + d];
            vv[e] = vs * 0.5f;
        }
        __nv_bfloat162 hh, ll;
        bf16 h0,l0,h1,l1;
        split2(qv[0],h0,l0); split2(qv[1],h1,l1);
        hh.x=h0; hh.y=h1; ll.x=l0; ll.y=l1;
        *(__nv_bfloat162*)(g_qhH + ob) = hh; *(__nv_bfloat162*)(g_qhL + ob) = ll;
        split2(kv[0],h0,l0); split2(kv[1],h1,l1);
        hh.x=h0; hh.y=h1; ll.x=l0; ll.y=l1;
        *(__nv_bfloat162*)(g_khH + ob) = hh; *(__nv_bfloat162*)(g_khL + ob) = ll;
        split2(vv[0],h0,l0); split2(vv[1],h1,l1);
        hh.x=h0; hh.y=h1; ll.x=l0; ll.y=l1;
        *(__nv_bfloat162*)(g_vhH + ob) = hh; *(__nv_bfloat162*)(g_vhL + ob) = ll;
    }
}

// ---------------- flash attention: Br=128 (16 rows/warp), Bc=64, 2 CTAs/SM ----------------
// Q staged into the same smem region later reused for K/V hi+lo tiles.
#define FQ_H 0
#define FQ_L (128*72)
#define F_KH 0
#define F_KL (64*72)
#define F_VH (2*64*72)
#define F_VL (3*64*72)
#define FSMEM (4*64*72*2)    // 36864 bytes

__global__ __launch_bounds__(256,2) void flash_mma()
{
    extern __shared__ __align__(16) char fsm[];
    bf16* smb = (bf16*)fsm;

    const int qt = (gridDim.x - 1) - blockIdx.x;   // heavy tiles first
    const int h = blockIdx.y, b = blockIdx.z;
    const int q0 = qt * 128;

    const size_t hb = (size_t)(b*Hn + h) * Sn * 64;
    const bf16* QHg = g_qhH + hb; const bf16* QLg = g_qhL + hb;
    const bf16* KHg = g_khH + hb; const bf16* KLg = g_khL + hb;
    const bf16* VHg = g_vhH + hb; const bf16* VLg = g_vhL + hb;

    const int t = threadIdx.x, w = t >> 5, lane = t & 31;
    const int sub = lane >> 3, r8 = lane & 7;

    // stage Q (hi/lo)
    {
        const int row = t >> 1, half = (t & 1) * 32;
        const uint4* sh = (const uint4*)(QHg + (size_t)(q0 + row) * 64 + half);
        const uint4* sl = (const uint4*)(QLg + (size_t)(q0 + row) * 64 + half);
        uint4* dh = (uint4*)(smb + FQ_H + row*72 + half);
        uint4* dl = (uint4*)(smb + FQ_L + row*72 + half);
        #pragma unroll
        for (int i = 0; i < 4; i++) { dh[i] = sh[i]; dl[i] = sl[i]; }
    }
    __syncthreads();

    // persistent Q fragments
    unsigned qa[4][4], ql[4][4];
    {
        const unsigned qoff = ((w*16 + (sub & 1)*8 + r8) * 72 + (sub >> 1) * 8);
        #pragma unroll
        for (int ks = 0; ks < 4; ks++) {
            ldsm4(qa[ks], sm_u32(smb + FQ_H + qoff + ks*16));
            ldsm4(ql[ks], sm_u32(smb + FQ_L + qoff + ks*16));
        }
    }
    __syncthreads();   // Q consumed -> smem reusable for KV

    float o[8][4];
    #pragma unroll
    for (int g = 0; g < 8; g++)
        #pragma unroll
        for (int e = 0; e < 4; e++) o[g][e] = 0.f;
    float m0s = -CUDART_INF_F, m1s = -CUDART_INF_F, l0s = 0.f, l1s = 0.f;

    const int nk = 2*qt + 2;
    const int krow = t >> 2, kcoff = (t & 3) * 16;

    for (int kt = 0; kt < nk; kt++) {
        const int k0 = kt * 64;
        __syncthreads();           // prev compute done -> KV buffers free
        {
            const size_t so = (size_t)(k0 + krow) * 64 + kcoff;
            const unsigned sb = sm_u32(smb) + (krow*72 + kcoff) * 2;
            #pragma unroll
            for (int i = 0; i < 2; i++) {
                CPA16(sb + F_KH*2 + i*16, KHg + so + i*8);
                CPA16(sb + F_KL*2 + i*16, KLg + so + i*8);
                CPA16(sb + F_VH*2 + i*16, VHg + so + i*8);
                CPA16(sb + F_VL*2 + i*16, VLg + so + i*8);
            }
        }
        CPA_COMMIT();
        CPA_WAIT0();
        __syncthreads();           // KV visible to all

        if (k0 <= q0 + w*16 + 15) {
            float s[8][4];
            #pragma unroll
            for (int g = 0; g < 8; g++)
                #pragma unroll
                for (int e = 0; e < 4; e++) s[g][e] = 0.f;

            // S = Q K^T
            #pragma unroll
            for (int ks = 0; ks < 4; ks++) {
                #pragma unroll
                for (int jp = 0; jp < 4; jp++) {
                    const unsigned koff = ((jp*16 + (sub>>1)*8 + r8) * 72 + ks*16 + (sub & 1)*8);
                    unsigned bh[4], bl[4];
                    ldsm4(bh, sm_u32(smb + F_KH + koff));
                    ldsm4(bl, sm_u32(smb + F_KL + koff));
                    mma16816(s[2*jp],   qa[ks], bh);
                    mma16816(s[2*jp],   qa[ks], bl);
                    mma16816(s[2*jp],   ql[ks], bh);
                    mma16816(s[2*jp+1], qa[ks], bh + 2);
                    mma16816(s[2*jp+1], qa[ks], bl + 2);
                    mma16816(s[2*jp+1], ql[ks], bh + 2);
                }
            }

            // causal mask (only the diagonal-adjacent tiles)
            if (kt >= 2*qt) {
                const int row0 = q0 + w*16 + (lane >> 2);
                #pragma unroll
                for (int g = 0; g < 8; g++) {
                    const int col = k0 + g*8 + ((lane & 3) << 1);
                    if (col     > row0)     s[g][0] = -CUDART_INF_F;
                    if (col + 1 > row0)     s[g][1] = -CUDART_INF_F;
                    if (col     > row0 + 8) s[g][2] = -CUDART_INF_F;
                    if (col + 1 > row0 + 8) s[g][3] = -CUDART_INF_F;
                }
            }

            // online softmax (rows r0, r0+8)
            float ml0 = -CUDART_INF_F, ml1 = -CUDART_INF_F;
            #pragma unroll
            for (int g = 0; g < 8; g++) {
                ml0 = fmaxf(ml0, fmaxf(s[g][0], s[g][1]));
                ml1 = fmaxf(ml1, fmaxf(s[g][2], s[g][3]));
            }
            ml0 = fmaxf(ml0, __shfl_xor_sync(0xffffffffu, ml0, 1));
            ml0 = fmaxf(ml0, __shfl_xor_sync(0xffffffffu, ml0, 2));
            ml1 = fmaxf(ml1, __shfl_xor_sync(0xffffffffu, ml1, 1));
            ml1 = fmaxf(ml1, __shfl_xor_sync(0xffffffffu, ml1, 2));
            const float mn0 = fmaxf(m0s, ml0), mn1 = fmaxf(m1s, ml1);
            const float a0 = __expf(m0s - mn0), a1 = __expf(m1s - mn1);
            m0s = mn0; m1s = mn1;
            float ps0 = 0.f, ps1 = 0.f;
            #pragma unroll
            for (int g = 0; g < 8; g++) {
                s[g][0] = __expf(s[g][0] - mn0); ps0 += s[g][0];
                s[g][1] = __expf(s[g][1] - mn0); ps0 += s[g][1];
                s[g][2] = __expf(s[g][2] - mn1); ps1 += s[g][2];
                s[g][3] = __expf(s[g][3] - mn1); ps1 += s[g][3];
            }
            ps0 += __shfl_xor_sync(0xffffffffu, ps0, 1);
            ps0 += __shfl_xor_sync(0xffffffffu, ps0, 2);
            ps1 += __shfl_xor_sync(0xffffffffu, ps1, 1);
            ps1 += __shfl_xor_sync(0xffffffffu, ps1, 2);
            l0s = l0s * a0 + ps0;
            l1s = l1s * a1 + ps1;
            #pragma unroll
            for (int g = 0; g < 8; g++) {
                o[g][0] *= a0; o[g][1] *= a0;
                o[g][2] *= a1; o[g][3] *= a1;
            }

            // U += P V (P split to bf16 hi/lo in regs)
            #pragma unroll
            for (int ksv = 0; ksv < 4; ksv++) {
                const int gA = 2*ksv, gB = gA + 1;
                bf16 hA0 = __float2bfloat16(s[gA][0]); float rA0 = s[gA][0] - __bfloat162float(hA0);
                bf16 hA1 = __float2bfloat16(s[gA][1]); float rA1 = s[gA][1] - __bfloat162float(hA1);
                bf16 hA2 = __float2bfloat16(s[gA][2]); float rA2 = s[gA][2] - __bfloat162float(hA2);
                bf16 hA3 = __float2bfloat16(s[gA][3]); float rA3 = s[gA][3] - __bfloat162float(hA3);
                bf16 hB0 = __float2bfloat16(s[gB][0]); float rB0 = s[gB][0] - __bfloat162float(hB0);
                bf16 hB1 = __float2bfloat16(s[gB][1]); float rB1 = s[gB][1] - __bfloat162float(hB1);
                bf16 hB2 = __float2bfloat16(s[gB][2]); float rB2 = s[gB][2] - __bfloat162float(hB2);
                bf16 hB3 = __float2bfloat16(s[gB][3]); float rB3 = s[gB][3] - __bfloat162float(hB3);
                unsigned pah[4] = { pack_us(hA0,hA1), pack_us(hA2,hA3),
                                    pack_us(hB0,hB1), pack_us(hB2,hB3) };
                unsigned pal[4] = { packbf(rA0,rA1), packbf(rA2,rA3),
                                    packbf(rB0,rB1), packbf(rB2,rB3) };
                #pragma unroll
                for (int jp = 0; jp < 4; jp++) {
                    const unsigned voff = ((ksv*16 + (sub & 1)*8 + r8) * 72 + (2*jp + (sub >> 1)) * 8);
                    unsigned vh[4], vl[4];
                    ldsm4t(vh, sm_u32(smb + F_VH + voff));
                    ldsm4t(vl, sm_u32(smb + F_VL + voff));
                    mma16816(o[2*jp],   pah, vh);
                    mma16816(o[2*jp],   pah, vl);
                    mma16816(o[2*jp],   pal, vh);
                    mma16816(o[2*jp+1], pah, vh + 2);
                    mma16816(o[2*jp+1], pah, vl + 2);
                    mma16816(o[2*jp+1], pal, vh + 2);
                }
            }
        }
    }

    // epilogue: normalize, split, store
    const float il0 = 1.0f / l0s, il1 = 1.0f / l1s;
    const int row0 = q0 + w*16 + (lane >> 2);
    #pragma unroll
    for (int g = 0; g < 8; g++) {
        const size_t cb = (size_t)h*64 + g*8 + ((lane & 3) << 1);
        {
            float x0 = o[g][0] * il0, x1 = o[g][1] * il0;
            bf16 h0,l0,h1,l1;
            split2(x0,h0,l0); split2(x1,h1,l1);
            __nv_bfloat162 hh; hh.x=h0; hh.y=h1;
            __nv_bfloat162 ll; ll.x=l0; ll.y=l1;
            const size_t off = (size_t)(b*Sn + row0) * 1024 + cb;
            *(__nv_bfloat162*)(g_attH + off) = hh;
            *(__nv_bfloat162*)(g_attL + off) = ll;
        }
        {
            float x0 = o[g][2] * il1, x1 = o[g][3] * il1;
            bf16 h0,l0,h1,l1;
            split2(x0,h0,l0); split2(x1,h1,l1);
            __nv_bfloat162 hh; hh.x=h0; hh.y=h1;
            __nv_bfloat162 ll; ll.x=l0; ll.y=l1;
            const size_t off = (size_t)(b*Sn + row0 + 8) * 1024 + cb;
            *(__nv_bfloat162*)(g_attH + off) = hh;
            *(__nv_bfloat162*)(g_attL + off) = ll;
        }
    }
}

// ---------------- launch ----------------
extern "C" void kernel_launch(void* const* d_in, const int* in_sizes, int n_in,
                              void* d_out, int out_size)
{
    const float* q    = (const float*)d_in[0];
    const float* k    = (const float*)d_in[1];
    const float* v    = (const float*)d_in[2];
    const float* W_Aq = (const float*)d_in[4];
    const float* W_Ak = (const float*)d_in[5];
    const float* W_Av = (const float*)d_in[6];
    const float* W_Bq = (const float*)d_in[7];
    const float* W_Bk = (const float*)d_in[8];
    const float* W_Bv = (const float*)d_in[9];
    const float* Wo   = (const float*)d_in[10];
    float* out = (float*)d_out;

    bf16 *pqH,*pqL,*pkH,*pkL,*pvH,*pvL,*pwoH,*pwoL;
    cudaGetSymbolAddress((void**)&pqH,  g_xqH); cudaGetSymbolAddress((void**)&pqL,  g_xqL);
    cudaGetSymbolAddress((void**)&pkH,  g_xkH); cudaGetSymbolAddress((void**)&pkL,  g_xkL);
    cudaGetSymbolAddress((void**)&pvH,  g_xvH); cudaGetSymbolAddress((void**)&pvL,  g_xvL);
    cudaGetSymbolAddress((void**)&pwoH, g_woH); cudaGetSymbolAddress((void**)&pwoL, g_woL);

    cudaFuncSetAttribute(proj_k,    cudaFuncAttributeMaxDynamicSharedMemorySize, GSMEM);
    cudaFuncSetAttribute(gemm_wo_k, cudaFuncAttributeMaxDynamicSharedMemorySize, GSMEM);
    cudaFuncSetAttribute(flash_mma, cudaFuncAttributeMaxDynamicSharedMemorySize, FSMEM);

    split_kernel<<<Mrows*Dm/4/256, 256>>>(q,  pqH,  pqL,  Mrows*Dm/4);
    split_kernel<<<Mrows*Dm/4/256, 256>>>(k,  pkH,  pkL,  Mrows*Dm/4);
    split_kernel<<<Mrows*Dm/4/256, 256>>>(v,  pvH,  pvL,  Mrows*Dm/4);
    split_kernel<<<Dm*Dm/4/256,    256>>>(Wo, pwoH, pwoL, Dm*Dm/4);
    wpack_kernel<<<Dm*Dm/256, 256>>>(W_Aq, W_Bq, W_Ak, W_Bk, W_Av, W_Bv);

    proj_k<<<dim3(8, Mrows/128), 256, GSMEM>>>();

    combine_kernel<<<Mrows, 256>>>();

    flash_mma<<<dim3(Sn/128, Hn, Bn), 256, FSMEM>>>();

    gemm_wo_k<<<dim3(8, Mrows/128), 256, GSMEM>>>(out);
}

// round 8
// speedup vs baseline: 8.2566x; 1.3666x over previous
#include <cuda_runtime.h>
#include <cuda_bf16.h>
#include <cuda_fp16.h>
#include <math_constants.h>
#include <mma.h>
#include <cstddef>
#include <cstdint>

using namespace nvcuda;
using bf16 = __nv_bfloat16;

#define Bn   2
#define Sn   2048
#define Hn   16
#define DKn  64
#define Dm   1024
#define QR   6
#define RK   2
#define Mrows (Bn*Sn)

// ---------------- global scratch ----------------
__device__ bf16 g_xqH[Mrows*Dm], g_xqL[Mrows*Dm];
__device__ bf16 g_xkH[Mrows*Dm], g_xkL[Mrows*Dm];
__device__ bf16 g_xvH[Mrows*Dm], g_xvL[Mrows*Dm];
__device__ bf16 g_wH [Dm*Dm],   g_wL [Dm*Dm];     // packed proj weights [k][n-packed]
__device__ bf16 g_woH[Dm*Dm],   g_woL[Dm*Dm];     // Wo [k][n]
__device__ float g_proj[Mrows*Dm];
__device__ __half g_qh16[Bn*Hn*Sn*DKn];
__device__ __half g_kh16[Bn*Hn*Sn*DKn];
__device__ __half g_vh16[Bn*Hn*Sn*DKn];
__device__ bf16 g_attH[Mrows*Dm], g_attL[Mrows*Dm];

// ---------------- helpers ----------------
__device__ __forceinline__ void split2(float x, bf16& h, bf16& l)
{
    h = __float2bfloat16(x);
    l = __float2bfloat16(x - __bfloat162float(h));
}
__device__ __forceinline__ unsigned sm_u32(const void* p)
{
    return (unsigned)__cvta_generic_to_shared(p);
}
__device__ __forceinline__ void ldsm4(unsigned r[4], unsigned a)
{
    asm volatile("ldmatrix.sync.aligned.m8n8.x4.shared.b16 {%0,%1,%2,%3}, [%4];"
        : "=r"(r[0]), "=r"(r[1]), "=r"(r[2]), "=r"(r[3]) : "r"(a));
}
__device__ __forceinline__ void ldsm4t(unsigned r[4], unsigned a)
{
    asm volatile("ldmatrix.sync.aligned.m8n8.x4.trans.shared.b16 {%0,%1,%2,%3}, [%4];"
        : "=r"(r[0]), "=r"(r[1]), "=r"(r[2]), "=r"(r[3]) : "r"(a));
}
__device__ __forceinline__ void mma16816(float c[4], const unsigned a[4], const unsigned b[2])
{
    asm volatile(
        "mma.sync.aligned.m16n8k16.row.col.f32.bf16.bf16.f32 "
        "{%0,%1,%2,%3},{%4,%5,%6,%7},{%8,%9},{%0,%1,%2,%3};"
        : "+f"(c[0]), "+f"(c[1]), "+f"(c[2]), "+f"(c[3])
        : "r"(a[0]), "r"(a[1]), "r"(a[2]), "r"(a[3]), "r"(b[0]), "r"(b[1]));
}
__device__ __forceinline__ void mma16816h(float c[4], const unsigned a[4], const unsigned b[2])
{
    asm volatile(
        "mma.sync.aligned.m16n8k16.row.col.f32.f16.f16.f32 "
        "{%0,%1,%2,%3},{%4,%5,%6,%7},{%8,%9},{%0,%1,%2,%3};"
        : "+f"(c[0]), "+f"(c[1]), "+f"(c[2]), "+f"(c[3])
        : "r"(a[0]), "r"(a[1]), "r"(a[2]), "r"(a[3]), "r"(b[0]), "r"(b[1]));
}
__device__ __forceinline__ unsigned pack_h(float lo, float hi)
{
    unsigned r;
    asm("cvt.rn.f16x2.f32 %0, %1, %2;" : "=r"(r) : "f"(hi), "f"(lo));
    return r;
}
#define CPA16(dst, src) \
    asm volatile("cp.async.cg.shared.global [%0], [%1], 16;" :: "r"(dst), "l"(src))
#define CPA_COMMIT() asm volatile("cp.async.commit_group;")
#define CPA_WAIT1()  asm volatile("cp.async.wait_group 1;")
#define CPA_WAIT0()  asm volatile("cp.async.wait_group 0;")

// ---------------- presplit kernels ----------------
__global__ __launch_bounds__(256) void split_kernel(
    const float* __restrict__ src, bf16* __restrict__ dh, bf16* __restrict__ dl, int n4)
{
    int i = blockIdx.x * 256 + threadIdx.x;
    if (i >= n4) return;
    float4 f = ((const float4*)src)[i];
    bf16 h0,l0,h1,l1,h2,l2,h3,l3;
    split2(f.x,h0,l0); split2(f.y,h1,l1); split2(f.z,h2,l2); split2(f.w,h3,l3);
    __nv_bfloat162 a; a.x=h0; a.y=h1;
    __nv_bfloat162 b; b.x=h2; b.y=h3;
    ((__nv_bfloat162*)dh)[i*2]   = a;
    ((__nv_bfloat162*)dh)[i*2+1] = b;
    a.x=l0; a.y=l1; b.x=l2; b.y=l3;
    ((__nv_bfloat162*)dl)[i*2]   = a;
    ((__nv_bfloat162*)dl)[i*2+1] = b;
}

// pack weights into [1024][1024]: Aq@0(96/128) Bq@128(384) Ak@512(32/128) Bk@640 Av@768(32/128) Bv@896
__global__ __launch_bounds__(256) void wpack_kernel(
    const float* __restrict__ WAq, const float* __restrict__ WBq,
    const float* __restrict__ WAk, const float* __restrict__ WBk,
    const float* __restrict__ WAv, const float* __restrict__ WBv)
{
    int i = blockIdx.x * 256 + threadIdx.x;
    int row = i >> 10, c = i & 1023;
    const float* src; int lc, N;
    if      (c < 128) { src = WAq; lc = c;       N = 96;  }
    else if (c < 512) { src = WBq; lc = c - 128; N = 384; }
    else if (c < 640) { src = WAk; lc = c - 512; N = 32;  }
    else if (c < 768) { src = WBk; lc = c - 640; N = 128; }
    else if (c < 896) { src = WAv; lc = c - 768; N = 32;  }
    else              { src = WBv; lc = c - 896; N = 128; }
    float v = (lc < N) ? src[(size_t)row * N + lc] : 0.f;
    split2(v, g_wH[i], g_wL[i]);
}

// ---------------- split-bf16 GEMM: CTA 128x128, warp 64x32, BK=16, 2-stage, 2 CTAs/SM ----------------
#define GA_H 0
#define GA_L (128*24)
#define GB_H (2*128*24)
#define GB_L (2*128*24 + 16*136)
#define G_STG (2*128*24 + 2*16*136)
#define GSMEM (2*G_STG*2)

using GFA = wmma::fragment<wmma::matrix_a,16,16,16,bf16,wmma::row_major>;
using GFB = wmma::fragment<wmma::matrix_b,16,16,16,bf16,wmma::row_major>;
using GFC = wmma::fragment<wmma::accumulator,16,16,16,float>;

__device__ __forceinline__ void gemm_issue(
    bf16* smbase, int stage, int t,
    const bf16* AH, const bf16* AL, const bf16* BH, const bf16* BL,
    int m0, int n0, int k0)
{
    unsigned s0 = sm_u32(smbase) + stage * G_STG * 2;
    {
        const int ar = t >> 1, ac = (t & 1) * 8;
        const size_t go = (size_t)(m0 + ar) * 1024 + k0 + ac;
        unsigned d = s0 + (ar*24 + ac) * 2;
        CPA16(d + GA_H*2, AH + go);
        CPA16(d + GA_L*2, AL + go);
    }
    {
        const int kr = t >> 4, nc = (t & 15) * 8;
        const size_t go = (size_t)(k0 + kr) * 1024 + n0 + nc;
        unsigned d = s0 + (kr*136 + nc) * 2;
        CPA16(d + GB_H*2, BH + go);
        CPA16(d + GB_L*2, BL + go);
    }
}

__device__ __forceinline__ void gemm_body(
    const bf16* __restrict__ AH, const bf16* __restrict__ AL,
    const bf16* __restrict__ BH, const bf16* __restrict__ BL,
    float* __restrict__ C, int m0, int n0)
{
    extern __shared__ __align__(16) char gsm[];
    bf16* smb = (bf16*)gsm;

    const int t = threadIdx.x, wid = t >> 5;
    const int wm = wid >> 2, wn = wid & 3;

    GFC c[4][2];
    #pragma unroll
    for (int i = 0; i < 4; i++)
        #pragma unroll
        for (int j = 0; j < 2; j++)
            wmma::fill_fragment(c[i][j], 0.f);

    gemm_issue(smb, 0, t, AH, AL, BH, BL, m0, n0, 0);
    CPA_COMMIT();
    gemm_issue(smb, 1, t, AH, AL, BH, BL, m0, n0, 16);
    CPA_COMMIT();

    for (int it = 0; it < 64; it++) {
        CPA_WAIT1();
        __syncthreads();
        const int st = it & 1;
        const bf16* AHs = smb + st*G_STG + GA_H;
        const bf16* ALs = smb + st*G_STG + GA_L;
        const bf16* BHs = smb + st*G_STG + GB_H;
        const bf16* BLs = smb + st*G_STG + GB_L;

        GFB bh[2], bl[2];
        #pragma unroll
        for (int j = 0; j < 2; j++) {
            wmma::load_matrix_sync(bh[j], BHs + wn*32 + j*16, 136);
            wmma::load_matrix_sync(bl[j], BLs + wn*32 + j*16, 136);
        }
        #pragma unroll
        for (int i = 0; i < 4; i++) {
            GFA ah, al;
            wmma::load_matrix_sync(ah, AHs + (wm*64 + i*16)*24, 24);
            wmma::load_matrix_sync(al, ALs + (wm*64 + i*16)*24, 24);
            #pragma unroll
            for (int j = 0; j < 2; j++) {
                wmma::mma_sync(c[i][j], ah, bh[j], c[i][j]);
                wmma::mma_sync(c[i][j], ah, bl[j], c[i][j]);
                wmma::mma_sync(c[i][j], al, bh[j], c[i][j]);
            }
        }
        __syncthreads();
        const int kn = (it + 2) * 16;
        if (kn < 1024)
            gemm_issue(smb, st, t, AH, AL, BH, BL, m0, n0, kn);
        CPA_COMMIT();
    }

    #pragma unroll
    for (int i = 0; i < 4; i++)
        #pragma unroll
        for (int j = 0; j < 2; j++)
            wmma::store_matrix_sync(C + (size_t)(m0 + wm*64 + i*16) * 1024 + n0 + wn*32 + j*16,
                                    c[i][j], 1024, wmma::mem_row_major);
}

__global__ __launch_bounds__(256,2) void proj_k()
{
    const int x = blockIdx.x;
    const bf16 *AH, *AL;
    if      (x < 4)  { AH = g_xqH; AL = g_xqL; }
    else if (x < 6)  { AH = g_xkH; AL = g_xkL; }
    else             { AH = g_xvH; AL = g_xvL; }
    gemm_body(AH, AL, g_wH, g_wL, g_proj, blockIdx.y * 128, x * 128);
}

__global__ __launch_bounds__(256,2) void gemm_wo_k(float* __restrict__ C)
{
    gemm_body(g_attH, g_attL, g_woH, g_woL, C, blockIdx.y * 128, blockIdx.x * 128);
}

// ---------------- combine: rank contraction + rotary + scales -> fp16 ----------------
__global__ __launch_bounds__(256) void combine_kernel()
{
    const int m = blockIdx.x;
    const int b = m / Sn, s = m % Sn;
    const int t = threadIdx.x;

    __shared__ float rowp[1024];
    __shared__ float sCos[32], sSin[32];

    ((float4*)rowp)[t] = ((const float4*)(g_proj + (size_t)m * 1024))[t];
    if (t < 32) {
        float inv = expf(-((float)(2*t) / 64.f) * logf(10000.0f));
        float fr  = (float)s * inv;
        sCos[t] = cosf(fr);
        sSin[t] = sinf(fr);
    }
    __syncthreads();

    const float qscale = (1.0f / QR) * (1.0f / (float)DKn);

    for (int pi = t; pi < Hn*DKn/2; pi += 256) {
        const int h = pi >> 5, dp = pi & 31, d0 = dp * 2;
        const size_t ob = ((size_t)(b*Hn + h) * Sn + s) * 64 + d0;

        float qv[2], kv[2], vv[2];
        #pragma unroll
        for (int e = 0; e < 2; e++) {
            const int d = d0 + e, dl = d & 31;
            const float cc = sCos[dl], sn = sSin[dl];
            float r1 = 0.f, r2 = 0.f;
            #pragma unroll
            for (int r = 0; r < QR; r++) {
                const float a = rowp[h*QR + r];
                r1 += a * rowp[128 + r*64 + dl];
                r2 += a * rowp[128 + r*64 + dl + 32];
            }
            qv[e] = ((d < 32) ? (r1*cc + r2*sn) : (-r1*sn + r2*cc)) * qscale;

            r1 = 0.f; r2 = 0.f;
            #pragma unroll
            for (int r = 0; r < RK; r++) {
                const float a = rowp[512 + h*RK + r];
                r1 += a * rowp[640 + r*64 + dl];
                r2 += a * rowp[640 + r*64 + dl + 32];
            }
            kv[e] = ((d < 32) ? (r1*cc + r2*sn) : (-r1*sn + r2*cc)) * 0.5f;

            float vs = 0.f;
            #pragma unroll
            for (int r = 0; r < RK; r++)
                vs += rowp[768 + h*RK + r] * rowp[896 + r*64 + d];
            vv[e] = vs * 0.5f;
        }
        *(__half2*)(g_qh16 + ob) = __floats2half2_rn(qv[0], qv[1]);
        *(__half2*)(g_kh16 + ob) = __floats2half2_rn(kv[0], kv[1]);
        *(__half2*)(g_vh16 + ob) = __floats2half2_rn(vv[0], vv[1]);
    }
}

// ---------------- flash attention: plain fp16, Br=128, Bc=64, 2-stage cp.async, 2 CTAs/SM ----------------
#define F_K 0
#define F_V (64*72)
#define F_STG (2*64*72)          // 9216 halves = 18432 bytes per stage
#define FSMEM (2*F_STG*2)        // 36864 bytes

__global__ __launch_bounds__(256,2) void flash_mma()
{
    extern __shared__ __align__(16) char fsm[];
    __half* smb = (__half*)fsm;

    const int qt = (gridDim.x - 1) - blockIdx.x;   // heavy tiles first
    const int h = blockIdx.y, b = blockIdx.z;
    const int q0 = qt * 128;

    const size_t hb = (size_t)(b*Hn + h) * Sn * 64;
    const __half* Qg = g_qh16 + hb;
    const __half* Kg = g_kh16 + hb;
    const __half* Vg = g_vh16 + hb;

    const int t = threadIdx.x, w = t >> 5, lane = t & 31;
    const int sub = lane >> 3, r8 = lane & 7;

    // stage Q into buffer 0 region (exactly one stage = 128*72 halves)
    {
        const int row = t >> 1, half = (t & 1) * 32;
        const uint4* sh = (const uint4*)(Qg + (size_t)(q0 + row) * 64 + half);
        uint4* dh = (uint4*)(smb + row*72 + half);
        #pragma unroll
        for (int i = 0; i < 4; i++) dh[i] = sh[i];
    }
    __syncthreads();

    // persistent Q fragments (fp16)
    unsigned qa[4][4];
    {
        const unsigned qoff = ((w*16 + (sub & 1)*8 + r8) * 72 + (sub >> 1) * 8);
        #pragma unroll
        for (int ks = 0; ks < 4; ks++)
            ldsm4(qa[ks], sm_u32(smb + qoff + ks*16));
    }
    __syncthreads();   // Q consumed -> smem reusable for KV stages

    float o[8][4];
    #pragma unroll
    for (int g = 0; g < 8; g++)
        #pragma unroll
        for (int e = 0; e < 4; e++) o[g][e] = 0.f;
    float m0s = -CUDART_INF_F, m1s = -CUDART_INF_F, l0s = 0.f, l1s = 0.f;

    const int nk = 2*qt + 2;
    const int krow = t >> 2, kcoff = (t & 3) * 16;

    // K/V tile load into stage buf (kt&1)
    auto issue = [&](int kt) {
        const size_t so = (size_t)(kt*64 + krow) * 64 + kcoff;
        const unsigned sb = sm_u32(smb) + ((kt & 1)*F_STG + krow*72 + kcoff) * 2;
        CPA16(sb + F_K*2,      Kg + so);
        CPA16(sb + F_K*2 + 16, Kg + so + 8);
        CPA16(sb + F_V*2,      Vg + so);
        CPA16(sb + F_V*2 + 16, Vg + so + 8);
    };

    issue(0); CPA_COMMIT();

    for (int kt = 0; kt < nk; kt++) {
        const int k0 = kt * 64;
        if (kt + 1 < nk) { issue(kt + 1); CPA_COMMIT(); CPA_WAIT1(); }
        else             { CPA_WAIT0(); }
        __syncthreads();           // tile kt visible

        const __half* Ksm = smb + (kt & 1)*F_STG + F_K;
        const __half* Vsm = smb + (kt & 1)*F_STG + F_V;

        if (k0 <= q0 + w*16 + 15) {
            float s[8][4];
            #pragma unroll
            for (int g = 0; g < 8; g++)
                #pragma unroll
                for (int e = 0; e < 4; e++) s[g][e] = 0.f;

            // S = Q K^T
            #pragma unroll
            for (int ks = 0; ks < 4; ks++) {
                #pragma unroll
                for (int jp = 0; jp < 4; jp++) {
                    const unsigned koff = ((jp*16 + (sub>>1)*8 + r8) * 72 + ks*16 + (sub & 1)*8);
                    unsigned bh[4];
                    ldsm4(bh, sm_u32(Ksm + koff));
                    mma16816h(s[2*jp],   qa[ks], bh);
                    mma16816h(s[2*jp+1], qa[ks], bh + 2);
                }
            }

            // causal mask (diagonal-adjacent tiles only)
            if (kt >= 2*qt) {
                const int row0 = q0 + w*16 + (lane >> 2);
                #pragma unroll
                for (int g = 0; g < 8; g++) {
                    const int col = k0 + g*8 + ((lane & 3) << 1);
                    if (col     > row0)     s[g][0] = -CUDART_INF_F;
                    if (col + 1 > row0)     s[g][1] = -CUDART_INF_F;
                    if (col     > row0 + 8) s[g][2] = -CUDART_INF_F;
                    if (col + 1 > row0 + 8) s[g][3] = -CUDART_INF_F;
                }
            }

            // online softmax (rows r0, r0+8)
            float ml0 = -CUDART_INF_F, ml1 = -CUDART_INF_F;
            #pragma unroll
            for (int g = 0; g < 8; g++) {
                ml0 = fmaxf(ml0, fmaxf(s[g][0], s[g][1]));
                ml1 = fmaxf(ml1, fmaxf(s[g][2], s[g][3]));
            }
            ml0 = fmaxf(ml0, __shfl_xor_sync(0xffffffffu, ml0, 1));
            ml0 = fmaxf(ml0, __shfl_xor_sync(0xffffffffu, ml0, 2));
            ml1 = fmaxf(ml1, __shfl_xor_sync(0xffffffffu, ml1, 1));
            ml1 = fmaxf(ml1, __shfl_xor_sync(0xffffffffu, ml1, 2));
            const float mn0 = fmaxf(m0s, ml0), mn1 = fmaxf(m1s, ml1);
            const float a0 = __expf(m0s - mn0), a1 = __expf(m1s - mn1);
            m0s = mn0; m1s = mn1;
            float ps0 = 0.f, ps1 = 0.f;
            #pragma unroll
            for (int g = 0; g < 8; g++) {
                s[g][0] = __expf(s[g][0] - mn0); ps0 += s[g][0];
                s[g][1] = __expf(s[g][1] - mn0); ps0 += s[g][1];
                s[g][2] = __expf(s[g][2] - mn1); ps1 += s[g][2];
                s[g][3] = __expf(s[g][3] - mn1); ps1 += s[g][3];
            }
            ps0 += __shfl_xor_sync(0xffffffffu, ps0, 1);
            ps0 += __shfl_xor_sync(0xffffffffu, ps0, 2);
            ps1 += __shfl_xor_sync(0xffffffffu, ps1, 1);
            ps1 += __shfl_xor_sync(0xffffffffu, ps1, 2);
            l0s = l0s * a0 + ps0;
            l1s = l1s * a1 + ps1;
            #pragma unroll
            for (int g = 0; g < 8; g++) {
                o[g][0] *= a0; o[g][1] *= a0;
                o[g][2] *= a1; o[g][3] *= a1;
            }

            // U += P V (P packed fp16 from accumulators)
            #pragma unroll
            for (int ksv = 0; ksv < 4; ksv++) {
                const int gA = 2*ksv, gB = gA + 1;
                unsigned pah[4] = { pack_h(s[gA][0], s[gA][1]), pack_h(s[gA][2], s[gA][3]),
                                    pack_h(s[gB][0], s[gB][1]), pack_h(s[gB][2], s[gB][3]) };
                #pragma unroll
                for (int jp = 0; jp < 4; jp++) {
                    const unsigned voff = ((ksv*16 + (sub & 1)*8 + r8) * 72 + (2*jp + (sub >> 1)) * 8);
                    unsigned vh[4];
                    ldsm4t(vh, sm_u32(Vsm + voff));
                    mma16816h(o[2*jp],   pah, vh);
                    mma16816h(o[2*jp+1], pah, vh + 2);
                }
            }
        }
        __syncthreads();           // all reads of buf (kt&1) done before re-issue
    }

    // epilogue: normalize, split to bf16 hi/lo for Wo GEMM
    const float il0 = 1.0f / l0s, il1 = 1.0f / l1s;
    const int row0 = q0 + w*16 + (lane >> 2);
    #pragma unroll
    for (int g = 0; g < 8; g++) {
        const size_t cb = (size_t)h*64 + g*8 + ((lane & 3) << 1);
        {
            float x0 = o[g][0] * il0, x1 = o[g][1] * il0;
            bf16 h0,l0,h1,l1;
            split2(x0,h0,l0); split2(x1,h1,l1);
            __nv_bfloat162 hh; hh.x=h0; hh.y=h1;
            __nv_bfloat162 ll; ll.x=l0; ll.y=l1;
            const size_t off = (size_t)(b*Sn + row0) * 1024 + cb;
            *(__nv_bfloat162*)(g_attH + off) = hh;
            *(__nv_bfloat162*)(g_attL + off) = ll;
        }
        {
            float x0 = o[g][2] * il1, x1 = o[g][3] * il1;
            bf16 h0,l0,h1,l1;
            split2(x0,h0,l0); split2(x1,h1,l1);
            __nv_bfloat162 hh; hh.x=h0; hh.y=h1;
            __nv_bfloat162 ll; ll.x=l0; ll.y=l1;
            const size_t off = (size_t)(b*Sn + row0 + 8) * 1024 + cb;
            *(__nv_bfloat162*)(g_attH + off) = hh;
            *(__nv_bfloat162*)(g_attL + off) = ll;
        }
    }
}

// ---------------- launch ----------------
extern "C" void kernel_launch(void* const* d_in, const int* in_sizes, int n_in,
                              void* d_out, int out_size)
{
    const float* q    = (const float*)d_in[0];
    const float* k    = (const float*)d_in[1];
    const float* v    = (const float*)d_in[2];
    const float* W_Aq = (const float*)d_in[4];
    const float* W_Ak = (const float*)d_in[5];
    const float* W_Av = (const float*)d_in[6];
    const float* W_Bq = (const float*)d_in[7];
    const float* W_Bk = (const float*)d_in[8];
    const float* W_Bv = (const float*)d_in[9];
    const float* Wo   = (const float*)d_in[10];
    float* out = (float*)d_out;

    bf16 *pqH,*pqL,*pkH,*pkL,*pvH,*pvL,*pwoH,*pwoL;
    cudaGetSymbolAddress((void**)&pqH,  g_xqH); cudaGetSymbolAddress((void**)&pqL,  g_xqL);
    cudaGetSymbolAddress((void**)&pkH,  g_xkH); cudaGetSymbolAddress((void**)&pkL,  g_xkL);
    cudaGetSymbolAddress((void**)&pvH,  g_xvH); cudaGetSymbolAddress((void**)&pvL,  g_xvL);
    cudaGetSymbolAddress((void**)&pwoH, g_woH); cudaGetSymbolAddress((void**)&pwoL, g_woL);

    cudaFuncSetAttribute(proj_k,    cudaFuncAttributeMaxDynamicSharedMemorySize, GSMEM);
    cudaFuncSetAttribute(gemm_wo_k, cudaFuncAttributeMaxDynamicSharedMemorySize, GSMEM);
    cudaFuncSetAttribute(flash_mma, cudaFuncAttributeMaxDynamicSharedMemorySize, FSMEM);

    split_kernel<<<Mrows*Dm/4/256, 256>>>(q,  pqH,  pqL,  Mrows*Dm/4);
    split_kernel<<<Mrows*Dm/4/256, 256>>>(k,  pkH,  pkL,  Mrows*Dm/4);
    split_kernel<<<Mrows*Dm/4/256, 256>>>(v,  pvH,  pvL,  Mrows*Dm/4);
    split_kernel<<<Dm*Dm/4/256,    256>>>(Wo, pwoH, pwoL, Dm*Dm/4);
    wpack_kernel<<<Dm*Dm/256, 256>>>(W_Aq, W_Bq, W_Ak, W_Bk, W_Av, W_Bv);

    proj_k<<<dim3(8, Mrows/128), 256, GSMEM>>>();

    combine_kernel<<<Mrows, 256>>>();

    flash_mma<<<dim3(Sn/128, Hn, Bn), 256, FSMEM>>>();

    gemm_wo_k<<<dim3(8, Mrows/128), 256, GSMEM>>>(out);
}

// round 9
// speedup vs baseline: 11.8311x; 1.4329x over previous
#include <cuda_runtime.h>
#include <cuda_bf16.h>
#include <cuda_fp16.h>
#include <math_constants.h>
#include <mma.h>
#include <cstddef>
#include <cstdint>

using namespace nvcuda;

#define Bn   2
#define Sn   2048
#define Hn   16
#define DKn  64
#define Dm   1024
#define QR   6
#define RK   2
#define Mrows (Bn*Sn)

// ---------------- global scratch ----------------
__device__ __half g_xq16[Mrows*Dm], g_xk16[Mrows*Dm], g_xv16[Mrows*Dm];
__device__ __half g_wH [Dm*Dm], g_wL [Dm*Dm];     // packed proj weights [k][n-packed], fp16 hi/lo
__device__ __half g_woH[Dm*Dm], g_woL[Dm*Dm];     // Wo [k][n], fp16 hi/lo
__device__ float g_proj[Mrows*Dm];
__device__ __half g_qh16[Bn*Hn*Sn*DKn];
__device__ __half g_kh16[Bn*Hn*Sn*DKn];
__device__ __half g_vh16[Bn*Hn*Sn*DKn];
__device__ __half g_att16[Mrows*Dm];

// ---------------- helpers ----------------
__device__ __forceinline__ void split2h(float x, __half& h, __half& l)
{
    h = __float2half_rn(x);
    l = __float2half_rn(x - __half2float(h));
}
__device__ __forceinline__ unsigned sm_u32(const void* p)
{
    return (unsigned)__cvta_generic_to_shared(p);
}
__device__ __forceinline__ void ldsm4(unsigned r[4], unsigned a)
{
    asm volatile("ldmatrix.sync.aligned.m8n8.x4.shared.b16 {%0,%1,%2,%3}, [%4];"
        : "=r"(r[0]), "=r"(r[1]), "=r"(r[2]), "=r"(r[3]) : "r"(a));
}
__device__ __forceinline__ void ldsm4t(unsigned r[4], unsigned a)
{
    asm volatile("ldmatrix.sync.aligned.m8n8.x4.trans.shared.b16 {%0,%1,%2,%3}, [%4];"
        : "=r"(r[0]), "=r"(r[1]), "=r"(r[2]), "=r"(r[3]) : "r"(a));
}
__device__ __forceinline__ void mma16816h(float c[4], const unsigned a[4], const unsigned b[2])
{
    asm volatile(
        "mma.sync.aligned.m16n8k16.row.col.f32.f16.f16.f32 "
        "{%0,%1,%2,%3},{%4,%5,%6,%7},{%8,%9},{%0,%1,%2,%3};"
        : "+f"(c[0]), "+f"(c[1]), "+f"(c[2]), "+f"(c[3])
        : "r"(a[0]), "r"(a[1]), "r"(a[2]), "r"(a[3]), "r"(b[0]), "r"(b[1]));
}
__device__ __forceinline__ unsigned pack_h(float lo, float hi)
{
    unsigned r;
    asm("cvt.rn.f16x2.f32 %0, %1, %2;" : "=r"(r) : "f"(hi), "f"(lo));
    return r;
}
#define CPA16(dst, src) \
    asm volatile("cp.async.cg.shared.global [%0], [%1], 16;" :: "r"(dst), "l"(src))
#define CPA_COMMIT() asm volatile("cp.async.commit_group;")
#define CPA_WAIT1()  asm volatile("cp.async.wait_group 1;")
#define CPA_WAIT0()  asm volatile("cp.async.wait_group 0;")

// ---------------- prep kernels ----------------
__global__ __launch_bounds__(256) void cvt_kernel(
    const float* __restrict__ src, __half* __restrict__ dst, int n4)
{
    int i = blockIdx.x * 256 + threadIdx.x;
    if (i >= n4) return;
    float4 f = ((const float4*)src)[i];
    __half2 a = __floats2half2_rn(f.x, f.y);
    __half2 b = __floats2half2_rn(f.z, f.w);
    ((__half2*)dst)[i*2]   = a;
    ((__half2*)dst)[i*2+1] = b;
}

__global__ __launch_bounds__(256) void wo_split_kernel(const float* __restrict__ Wo)
{
    int i = blockIdx.x * 256 + threadIdx.x;
    split2h(Wo[i], g_woH[i], g_woL[i]);
}

// pack weights into [1024][1024]: Aq@0(96/128) Bq@128(384) Ak@512(32/128) Bk@640 Av@768(32/128) Bv@896
__global__ __launch_bounds__(256) void wpack_kernel(
    const float* __restrict__ WAq, const float* __restrict__ WBq,
    const float* __restrict__ WAk, const float* __restrict__ WBk,
    const float* __restrict__ WAv, const float* __restrict__ WBv)
{
    int i = blockIdx.x * 256 + threadIdx.x;
    int row = i >> 10, c = i & 1023;
    const float* src; int lc, N;
    if      (c < 128) { src = WAq; lc = c;       N = 96;  }
    else if (c < 512) { src = WBq; lc = c - 128; N = 384; }
    else if (c < 640) { src = WAk; lc = c - 512; N = 32;  }
    else if (c < 768) { src = WBk; lc = c - 640; N = 128; }
    else if (c < 896) { src = WAv; lc = c - 768; N = 32;  }
    else              { src = WBv; lc = c - 896; N = 128; }
    float v = (lc < N) ? src[(size_t)row * N + lc] : 0.f;
    split2h(v, g_wH[i], g_wL[i]);
}

// ---------------- 2-MMA GEMM: A plain fp16, W split fp16 hi/lo ----------------
// CTA 128x128, warp 64x32, BK=16, 2-stage cp.async, 2 CTAs/SM
#define GA 0
#define GB_H (128*24)
#define GB_L (128*24 + 16*136)
#define G_STG (128*24 + 2*16*136)   // 7424 halves / stage
#define GSMEM (2*G_STG*2)           // 29696 bytes

using HFA = wmma::fragment<wmma::matrix_a,16,16,16,__half,wmma::row_major>;
using HFB = wmma::fragment<wmma::matrix_b,16,16,16,__half,wmma::row_major>;
using HFC = wmma::fragment<wmma::accumulator,16,16,16,float>;

__device__ __forceinline__ void gemm_issue(
    __half* smbase, int stage, int t,
    const __half* A, const __half* BH, const __half* BL,
    int m0, int n0, int k0)
{
    unsigned s0 = sm_u32(smbase) + stage * G_STG * 2;
    {
        const int ar = t >> 1, ac = (t & 1) * 8;   // 128 rows x 16 cols
        const size_t go = (size_t)(m0 + ar) * 1024 + k0 + ac;
        CPA16(s0 + (GA + ar*24 + ac) * 2, A + go);
    }
    {
        const int kr = t >> 4, nc = (t & 15) * 8;  // 16 rows x 128 cols
        const size_t go = (size_t)(k0 + kr) * 1024 + n0 + nc;
        unsigned d = s0 + (kr*136 + nc) * 2;
        CPA16(d + GB_H*2, BH + go);
        CPA16(d + GB_L*2, BL + go);
    }
}

__device__ __forceinline__ void gemm_body(
    const __half* __restrict__ A,
    const __half* __restrict__ BH, const __half* __restrict__ BL,
    float* __restrict__ C, int m0, int n0)
{
    extern __shared__ __align__(16) char gsm[];
    __half* smb = (__half*)gsm;

    const int t = threadIdx.x, wid = t >> 5;
    const int wm = wid >> 2, wn = wid & 3;     // 2 x 4 warps, warp tile 64x32

    HFC c[4][2];
    #pragma unroll
    for (int i = 0; i < 4; i++)
        #pragma unroll
        for (int j = 0; j < 2; j++)
            wmma::fill_fragment(c[i][j], 0.f);

    gemm_issue(smb, 0, t, A, BH, BL, m0, n0, 0);
    CPA_COMMIT();
    gemm_issue(smb, 1, t, A, BH, BL, m0, n0, 16);
    CPA_COMMIT();

    for (int it = 0; it < 64; it++) {
        CPA_WAIT1();
        __syncthreads();
        const int st = it & 1;
        const __half* As  = smb + st*G_STG + GA;
        const __half* BHs = smb + st*G_STG + GB_H;
        const __half* BLs = smb + st*G_STG + GB_L;

        HFB bh[2], bl[2];
        #pragma unroll
        for (int j = 0; j < 2; j++) {
            wmma::load_matrix_sync(bh[j], BHs + wn*32 + j*16, 136);
            wmma::load_matrix_sync(bl[j], BLs + wn*32 + j*16, 136);
        }
        #pragma unroll
        for (int i = 0; i < 4; i++) {
            HFA ah;
            wmma::load_matrix_sync(ah, As + (wm*64 + i*16)*24, 24);
            #pragma unroll
            for (int j = 0; j < 2; j++) {
                wmma::mma_sync(c[i][j], ah, bh[j], c[i][j]);
                wmma::mma_sync(c[i][j], ah, bl[j], c[i][j]);
            }
        }
        __syncthreads();
        const int kn = (it + 2) * 16;
        if (kn < 1024)
            gemm_issue(smb, st, t, A, BH, BL, m0, n0, kn);
        CPA_COMMIT();
    }

    #pragma unroll
    for (int i = 0; i < 4; i++)
        #pragma unroll
        for (int j = 0; j < 2; j++)
            wmma::store_matrix_sync(C + (size_t)(m0 + wm*64 + i*16) * 1024 + n0 + wn*32 + j*16,
                                    c[i][j], 1024, wmma::mem_row_major);
}

__global__ __launch_bounds__(256,2) void proj_k()
{
    const int x = blockIdx.x;            // n-tile of 128
    const __half* A;
    if      (x < 4)  A = g_xq16;
    else if (x < 6)  A = g_xk16;
    else             A = g_xv16;
    gemm_body(A, g_wH, g_wL, g_proj, blockIdx.y * 128, x * 128);
}

__global__ __launch_bounds__(256,2) void gemm_wo_k(float* __restrict__ C)
{
    gemm_body(g_att16, g_woH, g_woL, C, blockIdx.y * 128, blockIdx.x * 128);
}

// ---------------- combine: rank contraction + rotary + scales -> fp16 ----------------
__global__ __launch_bounds__(256) void combine_kernel()
{
    const int m = blockIdx.x;
    const int b = m / Sn, s = m % Sn;
    const int t = threadIdx.x;

    __shared__ float rowp[1024];
    __shared__ float sCos[32], sSin[32];

    ((float4*)rowp)[t] = ((const float4*)(g_proj + (size_t)m * 1024))[t];
    if (t < 32) {
        float inv = expf(-((float)(2*t) / 64.f) * logf(10000.0f));
        float fr  = (float)s * inv;
        sCos[t] = cosf(fr);
        sSin[t] = sinf(fr);
    }
    __syncthreads();

    const float qscale = (1.0f / QR) * (1.0f / (float)DKn);

    for (int pi = t; pi < Hn*DKn/2; pi += 256) {
        const int h = pi >> 5, dp = pi & 31, d0 = dp * 2;
        const size_t ob = ((size_t)(b*Hn + h) * Sn + s) * 64 + d0;

        float qv[2], kv[2], vv[2];
        #pragma unroll
        for (int e = 0; e < 2; e++) {
            const int d = d0 + e, dl = d & 31;
            const float cc = sCos[dl], sn = sSin[dl];
            float r1 = 0.f, r2 = 0.f;
            #pragma unroll
            for (int r = 0; r < QR; r++) {
                const float a = rowp[h*QR + r];
                r1 += a * rowp[128 + r*64 + dl];
                r2 += a * rowp[128 + r*64 + dl + 32];
            }
            qv[e] = ((d < 32) ? (r1*cc + r2*sn) : (-r1*sn + r2*cc)) * qscale;

            r1 = 0.f; r2 = 0.f;
            #pragma unroll
            for (int r = 0; r < RK; r++) {
                const float a = rowp[512 + h*RK + r];
                r1 += a * rowp[640 + r*64 + dl];
                r2 += a * rowp[640 + r*64 + dl + 32];
            }
            kv[e] = ((d < 32) ? (r1*cc + r2*sn) : (-r1*sn + r2*cc)) * 0.5f;

            float vs = 0.f;
            #pragma unroll
            for (int r = 0; r < RK; r++)
                vs += rowp[768 + h*RK + r] * rowp[896 + r*64 + d];
            vv[e] = vs * 0.5f;
        }
        *(__half2*)(g_qh16 + ob) = __floats2half2_rn(qv[0], qv[1]);
        *(__half2*)(g_kh16 + ob) = __floats2half2_rn(kv[0], kv[1]);
        *(__half2*)(g_vh16 + ob) = __floats2half2_rn(vv[0], vv[1]);
    }
}

// ---------------- flash attention: plain fp16, Br=128, Bc=64, 2-stage cp.async, 2 CTAs/SM ----------------
#define F_K 0
#define F_V (64*72)
#define F_STG (2*64*72)
#define FSMEM (2*F_STG*2)

__global__ __launch_bounds__(256,2) void flash_mma()
{
    extern __shared__ __align__(16) char fsm[];
    __half* smb = (__half*)fsm;

    const int qt = (gridDim.x - 1) - blockIdx.x;   // heavy tiles first
    const int h = blockIdx.y, b = blockIdx.z;
    const int q0 = qt * 128;

    const size_t hb = (size_t)(b*Hn + h) * Sn * 64;
    const __half* Qg = g_qh16 + hb;
    const __half* Kg = g_kh16 + hb;
    const __half* Vg = g_vh16 + hb;

    const int t = threadIdx.x, w = t >> 5, lane = t & 31;
    const int sub = lane >> 3, r8 = lane & 7;

    // stage Q into buffer 0 region
    {
        const int row = t >> 1, half = (t & 1) * 32;
        const uint4* sh = (const uint4*)(Qg + (size_t)(q0 + row) * 64 + half);
        uint4* dh = (uint4*)(smb + row*72 + half);
        #pragma unroll
        for (int i = 0; i < 4; i++) dh[i] = sh[i];
    }
    __syncthreads();

    // persistent Q fragments (fp16)
    unsigned qa[4][4];
    {
        const unsigned qoff = ((w*16 + (sub & 1)*8 + r8) * 72 + (sub >> 1) * 8);
        #pragma unroll
        for (int ks = 0; ks < 4; ks++)
            ldsm4(qa[ks], sm_u32(smb + qoff + ks*16));
    }
    __syncthreads();   // Q consumed -> smem reusable for KV stages

    float o[8][4];
    #pragma unroll
    for (int g = 0; g < 8; g++)
        #pragma unroll
        for (int e = 0; e < 4; e++) o[g][e] = 0.f;
    float m0s = -CUDART_INF_F, m1s = -CUDART_INF_F, l0s = 0.f, l1s = 0.f;

    const int nk = 2*qt + 2;
    const int krow = t >> 2, kcoff = (t & 3) * 16;

    auto issue = [&](int kt) {
        const size_t so = (size_t)(kt*64 + krow) * 64 + kcoff;
        const unsigned sb = sm_u32(smb) + ((kt & 1)*F_STG + krow*72 + kcoff) * 2;
        CPA16(sb + F_K*2,      Kg + so);
        CPA16(sb + F_K*2 + 16, Kg + so + 8);
        CPA16(sb + F_V*2,      Vg + so);
        CPA16(sb + F_V*2 + 16, Vg + so + 8);
    };

    issue(0); CPA_COMMIT();

    for (int kt = 0; kt < nk; kt++) {
        const int k0 = kt * 64;
        if (kt + 1 < nk) { issue(kt + 1); CPA_COMMIT(); CPA_WAIT1(); }
        else             { CPA_WAIT0(); }
        __syncthreads();

        const __half* Ksm = smb + (kt & 1)*F_STG + F_K;
        const __half* Vsm = smb + (kt & 1)*F_STG + F_V;

        if (k0 <= q0 + w*16 + 15) {
            float s[8][4];
            #pragma unroll
            for (int g = 0; g < 8; g++)
                #pragma unroll
                for (int e = 0; e < 4; e++) s[g][e] = 0.f;

            // S = Q K^T
            #pragma unroll
            for (int ks = 0; ks < 4; ks++) {
                #pragma unroll
                for (int jp = 0; jp < 4; jp++) {
                    const unsigned koff = ((jp*16 + (sub>>1)*8 + r8) * 72 + ks*16 + (sub & 1)*8);
                    unsigned bh[4];
                    ldsm4(bh, sm_u32(Ksm + koff));
                    mma16816h(s[2*jp],   qa[ks], bh);
                    mma16816h(s[2*jp+1], qa[ks], bh + 2);
                }
            }

            // causal mask (diagonal-adjacent tiles only)
            if (kt >= 2*qt) {
                const int row0 = q0 + w*16 + (lane >> 2);
                #pragma unroll
                for (int g = 0; g < 8; g++) {
                    const int col = k0 + g*8 + ((lane & 3) << 1);
                    if (col     > row0)     s[g][0] = -CUDART_INF_F;
                    if (col + 1 > row0)     s[g][1] = -CUDART_INF_F;
                    if (col     > row0 + 8) s[g][2] = -CUDART_INF_F;
                    if (col + 1 > row0 + 8) s[g][3] = -CUDART_INF_F;
                }
            }

            // online softmax (rows r0, r0+8)
            float ml0 = -CUDART_INF_F, ml1 = -CUDART_INF_F;
            #pragma unroll
            for (int g = 0; g < 8; g++) {
                ml0 = fmaxf(ml0, fmaxf(s[g][0], s[g][1]));
                ml1 = fmaxf(ml1, fmaxf(s[g][2], s[g][3]));
            }
            ml0 = fmaxf(ml0, __shfl_xor_sync(0xffffffffu, ml0, 1));
            ml0 = fmaxf(ml0, __shfl_xor_sync(0xffffffffu, ml0, 2));
            ml1 = fmaxf(ml1, __shfl_xor_sync(0xffffffffu, ml1, 1));
            ml1 = fmaxf(ml1, __shfl_xor_sync(0xffffffffu, ml1, 2));
            const float mn0 = fmaxf(m0s, ml0), mn1 = fmaxf(m1s, ml1);
            const float a0 = __expf(m0s - mn0), a1 = __expf(m1s - mn1);
            m0s = mn0; m1s = mn1;
            float ps0 = 0.f, ps1 = 0.f;
            #pragma unroll
            for (int g = 0; g < 8; g++) {
                s[g][0] = __expf(s[g][0] - mn0); ps0 += s[g][0];
                s[g][1] = __expf(s[g][1] - mn0); ps0 += s[g][1];
                s[g][2] = __expf(s[g][2] - mn1); ps1 += s[g][2];
                s[g][3] = __expf(s[g][3] - mn1); ps1 += s[g][3];
            }
            ps0 += __shfl_xor_sync(0xffffffffu, ps0, 1);
            ps0 += __shfl_xor_sync(0xffffffffu, ps0, 2);
            ps1 += __shfl_xor_sync(0xffffffffu, ps1, 1);
            ps1 += __shfl_xor_sync(0xffffffffu, ps1, 2);
            l0s = l0s * a0 + ps0;
            l1s = l1s * a1 + ps1;
            #pragma unroll
            for (int g = 0; g < 8; g++) {
                o[g][0] *= a0; o[g][1] *= a0;
                o[g][2] *= a1; o[g][3] *= a1;
            }

            // U += P V
            #pragma unroll
            for (int ksv = 0; ksv < 4; ksv++) {
                const int gA = 2*ksv, gB = gA + 1;
                unsigned pah[4] = { pack_h(s[gA][0], s[gA][1]), pack_h(s[gA][2], s[gA][3]),
                                    pack_h(s[gB][0], s[gB][1]), pack_h(s[gB][2], s[gB][3]) };
                #pragma unroll
                for (int jp = 0; jp < 4; jp++) {
                    const unsigned voff = ((ksv*16 + (sub & 1)*8 + r8) * 72 + (2*jp + (sub >> 1)) * 8);
                    unsigned vh[4];
                    ldsm4t(vh, sm_u32(Vsm + voff));
                    mma16816h(o[2*jp],   pah, vh);
                    mma16816h(o[2*jp+1], pah, vh + 2);
                }
            }
        }
        __syncthreads();
    }

    // epilogue: normalize, store plain fp16
    const float il0 = 1.0f / l0s, il1 = 1.0f / l1s;
    const int row0 = q0 + w*16 + (lane >> 2);
    #pragma unroll
    for (int g = 0; g < 8; g++) {
        const size_t cb = (size_t)h*64 + g*8 + ((lane & 3) << 1);
        {
            const size_t off = (size_t)(b*Sn + row0) * 1024 + cb;
            *(__half2*)(g_att16 + off) = __floats2half2_rn(o[g][0] * il0, o[g][1] * il0);
        }
        {
            const size_t off = (size_t)(b*Sn + row0 + 8) * 1024 + cb;
            *(__half2*)(g_att16 + off) = __floats2half2_rn(o[g][2] * il1, o[g][3] * il1);
        }
    }
}

// ---------------- launch ----------------
extern "C" void kernel_launch(void* const* d_in, const int* in_sizes, int n_in,
                              void* d_out, int out_size)
{
    const float* q    = (const float*)d_in[0];
    const float* k    = (const float*)d_in[1];
    const float* v    = (const float*)d_in[2];
    const float* W_Aq = (const float*)d_in[4];
    const float* W_Ak = (const float*)d_in[5];
    const float* W_Av = (const float*)d_in[6];
    const float* W_Bq = (const float*)d_in[7];
    const float* W_Bk = (const float*)d_in[8];
    const float* W_Bv = (const float*)d_in[9];
    const float* Wo   = (const float*)d_in[10];
    float* out = (float*)d_out;

    __half *pq16, *pk16, *pv16;
    cudaGetSymbolAddress((void**)&pq16, g_xq16);
    cudaGetSymbolAddress((void**)&pk16, g_xk16);
    cudaGetSymbolAddress((void**)&pv16, g_xv16);

    cudaFuncSetAttribute(proj_k,    cudaFuncAttributeMaxDynamicSharedMemorySize, GSMEM);
    cudaFuncSetAttribute(gemm_wo_k, cudaFuncAttributeMaxDynamicSharedMemorySize, GSMEM);
    cudaFuncSetAttribute(flash_mma, cudaFuncAttributeMaxDynamicSharedMemorySize, FSMEM);

    cvt_kernel<<<Mrows*Dm/4/256, 256>>>(q, pq16, Mrows*Dm/4);
    cvt_kernel<<<Mrows*Dm/4/256, 256>>>(k, pk16, Mrows*Dm/4);
    cvt_kernel<<<Mrows*Dm/4/256, 256>>>(v, pv16, Mrows*Dm/4);
    wo_split_kernel<<<Dm*Dm/256, 256>>>(Wo);
    wpack_kernel<<<Dm*Dm/256, 256>>>(W_Aq, W_Bq, W_Ak, W_Bk, W_Av, W_Bv);

    proj_k<<<dim3(8, Mrows/128), 256, GSMEM>>>();

    combine_kernel<<<Mrows, 256>>>();

    flash_mma<<<dim3(Sn/128, Hn, Bn), 256, FSMEM>>>();

    gemm_wo_k<<<dim3(8, Mrows/128), 256, GSMEM>>>(out);
}

// round 10
// speedup vs baseline: 13.9916x; 1.1826x over previous
#include <cuda_runtime.h>
#include <cuda_fp16.h>
#include <math_constants.h>
#include <mma.h>
#include <cstddef>
#include <cstdint>

using namespace nvcuda;

#define Bn   2
#define Sn   2048
#define Hn   16
#define DKn  64
#define Dm   1024
#define QR   6
#define RK   2
#define Mrows (Bn*Sn)

// ---------------- global scratch ----------------
__device__ __half g_xq16[Mrows*Dm], g_xk16[Mrows*Dm], g_xv16[Mrows*Dm];
__device__ __half g_w16 [Dm*Dm];                 // packed proj weights [k][n-packed], fp16
__device__ __half g_wo16[Dm*Dm];                 // Wo [k][n], fp16
__device__ float g_proj[Mrows*Dm];
__device__ __half g_qh16[Bn*Hn*Sn*DKn];
__device__ __half g_kh16[Bn*Hn*Sn*DKn];
__device__ __half g_vh16[Bn*Hn*Sn*DKn];
__device__ __half g_att16[Mrows*Dm];

// ---------------- helpers ----------------
__device__ __forceinline__ unsigned sm_u32(const void* p)
{
    return (unsigned)__cvta_generic_to_shared(p);
}
__device__ __forceinline__ void ldsm4(unsigned r[4], unsigned a)
{
    asm volatile("ldmatrix.sync.aligned.m8n8.x4.shared.b16 {%0,%1,%2,%3}, [%4];"
        : "=r"(r[0]), "=r"(r[1]), "=r"(r[2]), "=r"(r[3]) : "r"(a));
}
__device__ __forceinline__ void ldsm4t(unsigned r[4], unsigned a)
{
    asm volatile("ldmatrix.sync.aligned.m8n8.x4.trans.shared.b16 {%0,%1,%2,%3}, [%4];"
        : "=r"(r[0]), "=r"(r[1]), "=r"(r[2]), "=r"(r[3]) : "r"(a));
}
__device__ __forceinline__ void mma16816h(float c[4], const unsigned a[4], const unsigned b[2])
{
    asm volatile(
        "mma.sync.aligned.m16n8k16.row.col.f32.f16.f16.f32 "
        "{%0,%1,%2,%3},{%4,%5,%6,%7},{%8,%9},{%0,%1,%2,%3};"
        : "+f"(c[0]), "+f"(c[1]), "+f"(c[2]), "+f"(c[3])
        : "r"(a[0]), "r"(a[1]), "r"(a[2]), "r"(a[3]), "r"(b[0]), "r"(b[1]));
}
__device__ __forceinline__ unsigned pack_h(float lo, float hi)
{
    unsigned r;
    asm("cvt.rn.f16x2.f32 %0, %1, %2;" : "=r"(r) : "f"(hi), "f"(lo));
    return r;
}
#define CPA16(dst, src) \
    asm volatile("cp.async.cg.shared.global [%0], [%1], 16;" :: "r"(dst), "l"(src))
#define CPA_COMMIT() asm volatile("cp.async.commit_group;")
#define CPA_WAIT1()  asm volatile("cp.async.wait_group 1;")
#define CPA_WAIT0()  asm volatile("cp.async.wait_group 0;")

// ---------------- prep kernels ----------------
__global__ __launch_bounds__(256) void cvt_kernel(
    const float* __restrict__ src, __half* __restrict__ dst, int n4)
{
    int i = blockIdx.x * 256 + threadIdx.x;
    if (i >= n4) return;
    float4 f = ((const float4*)src)[i];
    ((__half2*)dst)[i*2]   = __floats2half2_rn(f.x, f.y);
    ((__half2*)dst)[i*2+1] = __floats2half2_rn(f.z, f.w);
}

// pack weights into [1024][1024]: Aq@0(96/128) Bq@128(384) Ak@512(32/128) Bk@640 Av@768(32/128) Bv@896
__global__ __launch_bounds__(256) void wpack_kernel(
    const float* __restrict__ WAq, const float* __restrict__ WBq,
    const float* __restrict__ WAk, const float* __restrict__ WBk,
    const float* __restrict__ WAv, const float* __restrict__ WBv)
{
    int i = blockIdx.x * 256 + threadIdx.x;
    int row = i >> 10, c = i & 1023;
    const float* src; int lc, N;
    if      (c < 128) { src = WAq; lc = c;       N = 96;  }
    else if (c < 512) { src = WBq; lc = c - 128; N = 384; }
    else if (c < 640) { src = WAk; lc = c - 512; N = 32;  }
    else if (c < 768) { src = WBk; lc = c - 640; N = 128; }
    else if (c < 896) { src = WAv; lc = c - 768; N = 32;  }
    else              { src = WBv; lc = c - 896; N = 128; }
    float v = (lc < N) ? src[(size_t)row * N + lc] : 0.f;
    g_w16[i] = __float2half_rn(v);
}

// ---------------- plain-fp16 GEMM: CTA 128x128, warp 64x32, BK=16, 2-stage, 2 CTAs/SM ----------------
#define GA 0
#define GB (128*24)
#define G_STG (128*24 + 16*136)   // 5248 halves / stage
#define GSMEM (2*G_STG*2)         // 20992 bytes

using HFA = wmma::fragment<wmma::matrix_a,16,16,16,__half,wmma::row_major>;
using HFB = wmma::fragment<wmma::matrix_b,16,16,16,__half,wmma::row_major>;
using HFC = wmma::fragment<wmma::accumulator,16,16,16,float>;

__device__ __forceinline__ void gemm_issue(
    __half* smbase, int stage, int t,
    const __half* A, const __half* B,
    int m0, int n0, int k0)
{
    unsigned s0 = sm_u32(smbase) + stage * G_STG * 2;
    {
        const int ar = t >> 1, ac = (t & 1) * 8;   // 128 rows x 16 cols
        CPA16(s0 + (GA + ar*24 + ac) * 2, A + (size_t)(m0 + ar) * 1024 + k0 + ac);
    }
    {
        const int kr = t >> 4, nc = (t & 15) * 8;  // 16 rows x 128 cols
        CPA16(s0 + (GB + kr*136 + nc) * 2, B + (size_t)(k0 + kr) * 1024 + n0 + nc);
    }
}

__device__ __forceinline__ void gemm_body(
    const __half* __restrict__ A, const __half* __restrict__ B,
    float* __restrict__ C, int m0, int n0)
{
    extern __shared__ __align__(16) char gsm[];
    __half* smb = (__half*)gsm;

    const int t = threadIdx.x, wid = t >> 5;
    const int wm = wid >> 2, wn = wid & 3;     // 2 x 4 warps, warp tile 64x32

    HFC c[4][2];
    #pragma unroll
    for (int i = 0; i < 4; i++)
        #pragma unroll
        for (int j = 0; j < 2; j++)
            wmma::fill_fragment(c[i][j], 0.f);

    gemm_issue(smb, 0, t, A, B, m0, n0, 0);
    CPA_COMMIT();
    gemm_issue(smb, 1, t, A, B, m0, n0, 16);
    CPA_COMMIT();

    for (int it = 0; it < 64; it++) {
        CPA_WAIT1();
        __syncthreads();
        const int st = it & 1;
        const __half* As = smb + st*G_STG + GA;
        const __half* Bs = smb + st*G_STG + GB;

        HFB bfr[2];
        #pragma unroll
        for (int j = 0; j < 2; j++)
            wmma::load_matrix_sync(bfr[j], Bs + wn*32 + j*16, 136);
        #pragma unroll
        for (int i = 0; i < 4; i++) {
            HFA ah;
            wmma::load_matrix_sync(ah, As + (wm*64 + i*16)*24, 24);
            #pragma unroll
            for (int j = 0; j < 2; j++)
                wmma::mma_sync(c[i][j], ah, bfr[j], c[i][j]);
        }
        __syncthreads();
        const int kn = (it + 2) * 16;
        if (kn < 1024)
            gemm_issue(smb, st, t, A, B, m0, n0, kn);
        CPA_COMMIT();
    }

    #pragma unroll
    for (int i = 0; i < 4; i++)
        #pragma unroll
        for (int j = 0; j < 2; j++)
            wmma::store_matrix_sync(C + (size_t)(m0 + wm*64 + i*16) * 1024 + n0 + wn*32 + j*16,
                                    c[i][j], 1024, wmma::mem_row_major);
}

__global__ __launch_bounds__(256,2) void proj_k()
{
    const int x = blockIdx.x;            // n-tile of 128
    const __half* A;
    if      (x < 4)  A = g_xq16;
    else if (x < 6)  A = g_xk16;
    else             A = g_xv16;
    gemm_body(A, g_w16, g_proj, blockIdx.y * 128, x * 128);
}

__global__ __launch_bounds__(256,2) void gemm_wo_k(float* __restrict__ C)
{
    gemm_body(g_att16, g_wo16, C, blockIdx.y * 128, blockIdx.x * 128);
}

// ---------------- combine: rank contraction + rotary + scales -> fp16 ----------------
__global__ __launch_bounds__(256) void combine_kernel()
{
    const int m = blockIdx.x;
    const int b = m / Sn, s = m % Sn;
    const int t = threadIdx.x;

    __shared__ float rowp[1024];
    __shared__ float sCos[32], sSin[32];

    ((float4*)rowp)[t] = ((const float4*)(g_proj + (size_t)m * 1024))[t];
    if (t < 32) {
        float inv = expf(-((float)(2*t) / 64.f) * logf(10000.0f));
        float fr  = (float)s * inv;
        sCos[t] = cosf(fr);
        sSin[t] = sinf(fr);
    }
    __syncthreads();

    const float qscale = (1.0f / QR) * (1.0f / (float)DKn);

    for (int pi = t; pi < Hn*DKn/2; pi += 256) {
        const int h = pi >> 5, dp = pi & 31, d0 = dp * 2;
        const size_t ob = ((size_t)(b*Hn + h) * Sn + s) * 64 + d0;

        float qv[2], kv[2], vv[2];
        #pragma unroll
        for (int e = 0; e < 2; e++) {
            const int d = d0 + e, dl = d & 31;
            const float cc = sCos[dl], sn = sSin[dl];
            float r1 = 0.f, r2 = 0.f;
            #pragma unroll
            for (int r = 0; r < QR; r++) {
                const float a = rowp[h*QR + r];
                r1 += a * rowp[128 + r*64 + dl];
                r2 += a * rowp[128 + r*64 + dl + 32];
            }
            qv[e] = ((d < 32) ? (r1*cc + r2*sn) : (-r1*sn + r2*cc)) * qscale;

            r1 = 0.f; r2 = 0.f;
            #pragma unroll
            for (int r = 0; r < RK; r++) {
                const float a = rowp[512 + h*RK + r];
                r1 += a * rowp[640 + r*64 + dl];
                r2 += a * rowp[640 + r*64 + dl + 32];
            }
            kv[e] = ((d < 32) ? (r1*cc + r2*sn) : (-r1*sn + r2*cc)) * 0.5f;

            float vs = 0.f;
            #pragma unroll
            for (int r = 0; r < RK; r++)
                vs += rowp[768 + h*RK + r] * rowp[896 + r*64 + d];
            vv[e] = vs * 0.5f;
        }
        *(__half2*)(g_qh16 + ob) = __floats2half2_rn(qv[0], qv[1]);
        *(__half2*)(g_kh16 + ob) = __floats2half2_rn(kv[0], kv[1]);
        *(__half2*)(g_vh16 + ob) = __floats2half2_rn(vv[0], vv[1]);
    }
}

// ---------------- flash attention: plain fp16, Br=128, Bc=64, 2-stage cp.async, 2 CTAs/SM ----------------
#define F_K 0
#define F_V (64*72)
#define F_STG (2*64*72)
#define FSMEM (2*F_STG*2)

__global__ __launch_bounds__(256,2) void flash_mma()
{
    extern __shared__ __align__(16) char fsm[];
    __half* smb = (__half*)fsm;

    const int qt = (gridDim.x - 1) - blockIdx.x;   // heavy tiles first
    const int h = blockIdx.y, b = blockIdx.z;
    const int q0 = qt * 128;

    const size_t hb = (size_t)(b*Hn + h) * Sn * 64;
    const __half* Qg = g_qh16 + hb;
    const __half* Kg = g_kh16 + hb;
    const __half* Vg = g_vh16 + hb;

    const int t = threadIdx.x, w = t >> 5, lane = t & 31;
    const int sub = lane >> 3, r8 = lane & 7;

    // stage Q into buffer 0 region
    {
        const int row = t >> 1, half = (t & 1) * 32;
        const uint4* sh = (const uint4*)(Qg + (size_t)(q0 + row) * 64 + half);
        uint4* dh = (uint4*)(smb + row*72 + half);
        #pragma unroll
        for (int i = 0; i < 4; i++) dh[i] = sh[i];
    }
    __syncthreads();

    // persistent Q fragments (fp16)
    unsigned qa[4][4];
    {
        const unsigned qoff = ((w*16 + (sub & 1)*8 + r8) * 72 + (sub >> 1) * 8);
        #pragma unroll
        for (int ks = 0; ks < 4; ks++)
            ldsm4(qa[ks], sm_u32(smb + qoff + ks*16));
    }
    __syncthreads();   // Q consumed -> smem reusable for KV stages

    float o[8][4];
    #pragma unroll
    for (int g = 0; g < 8; g++)
        #pragma unroll
        for (int e = 0; e < 4; e++) o[g][e] = 0.f;
    float m0s = -CUDART_INF_F, m1s = -CUDART_INF_F, l0s = 0.f, l1s = 0.f;

    const int nk = 2*qt + 2;
    const int krow = t >> 2, kcoff = (t & 3) * 16;

    auto issue = [&](int kt) {
        const size_t so = (size_t)(kt*64 + krow) * 64 + kcoff;
        const unsigned sb = sm_u32(smb) + ((kt & 1)*F_STG + krow*72 + kcoff) * 2;
        CPA16(sb + F_K*2,      Kg + so);
        CPA16(sb + F_K*2 + 16, Kg + so + 8);
        CPA16(sb + F_V*2,      Vg + so);
        CPA16(sb + F_V*2 + 16, Vg + so + 8);
    };

    issue(0); CPA_COMMIT();

    for (int kt = 0; kt < nk; kt++) {
        const int k0 = kt * 64;
        if (kt + 1 < nk) { issue(kt + 1); CPA_COMMIT(); CPA_WAIT1(); }
        else             { CPA_WAIT0(); }
        __syncthreads();

        const __half* Ksm = smb + (kt & 1)*F_STG + F_K;
        const __half* Vsm = smb + (kt & 1)*F_STG + F_V;

        if (k0 <= q0 + w*16 + 15) {
            float s[8][4];
            #pragma unroll
            for (int g = 0; g < 8; g++)
                #pragma unroll
                for (int e = 0; e < 4; e++) s[g][e] = 0.f;

            // S = Q K^T
            #pragma unroll
            for (int ks = 0; ks < 4; ks++) {
                #pragma unroll
                for (int jp = 0; jp < 4; jp++) {
                    const unsigned koff = ((jp*16 + (sub>>1)*8 + r8) * 72 + ks*16 + (sub & 1)*8);
                    unsigned bh[4];
                    ldsm4(bh, sm_u32(Ksm + koff));
                    mma16816h(s[2*jp],   qa[ks], bh);
                    mma16816h(s[2*jp+1], qa[ks], bh + 2);
                }
            }

            // causal mask (diagonal-adjacent tiles only)
            if (kt >= 2*qt) {
                const int row0 = q0 + w*16 + (lane >> 2);
                #pragma unroll
                for (int g = 0; g < 8; g++) {
                    const int col = k0 + g*8 + ((lane & 3) << 1);
                    if (col     > row0)     s[g][0] = -CUDART_INF_F;
                    if (col + 1 > row0)     s[g][1] = -CUDART_INF_F;
                    if (col     > row0 + 8) s[g][2] = -CUDART_INF_F;
                    if (col + 1 > row0 + 8) s[g][3] = -CUDART_INF_F;
                }
            }

            // online softmax (rows r0, r0+8)
            float ml0 = -CUDART_INF_F, ml1 = -CUDART_INF_F;
            #pragma unroll
            for (int g = 0; g < 8; g++) {
                ml0 = fmaxf(ml0, fmaxf(s[g][0], s[g][1]));
                ml1 = fmaxf(ml1, fmaxf(s[g][2], s[g][3]));
            }
            ml0 = fmaxf(ml0, __shfl_xor_sync(0xffffffffu, ml0, 1));
            ml0 = fmaxf(ml0, __shfl_xor_sync(0xffffffffu, ml0, 2));
            ml1 = fmaxf(ml1, __shfl_xor_sync(0xffffffffu, ml1, 1));
            ml1 = fmaxf(ml1, __shfl_xor_sync(0xffffffffu, ml1, 2));
            const float mn0 = fmaxf(m0s, ml0), mn1 = fmaxf(m1s, ml1);
            const float a0 = __expf(m0s - mn0), a1 = __expf(m1s - mn1);
            m0s = mn0; m1s = mn1;
            float ps0 = 0.f, ps1 = 0.f;
            #pragma unroll
            for (int g = 0; g < 8; g++) {
                s[g][0] = __expf(s[g][0] - mn0); ps0 += s[g][0];
                s[g][1] = __expf(s[g][1] - mn0); ps0 += s[g][1];
                s[g][2] = __expf(s[g][2] - mn1); ps1 += s[g][2];
                s[g][3] = __expf(s[g][3] - mn1); ps1 += s[g][3];
            }
            ps0 += __shfl_xor_sync(0xffffffffu, ps0, 1);
            ps0 += __shfl_xor_sync(0xffffffffu, ps0, 2);
            ps1 += __shfl_xor_sync(0xffffffffu, ps1, 1);
            ps1 += __shfl_xor_sync(0xffffffffu, ps1, 2);
            l0s = l0s * a0 + ps0;
            l1s = l1s * a1 + ps1;
            #pragma unroll
            for (int g = 0; g < 8; g++) {
                o[g][0] *= a0; o[g][1] *= a0;
                o[g][2] *= a1; o[g][3] *= a1;
            }

            // U += P V
            #pragma unroll
            for (int ksv = 0; ksv < 4; ksv++) {
                const int gA = 2*ksv, gB = gA + 1;
                unsigned pah[4] = { pack_h(s[gA][0], s[gA][1]), pack_h(s[gA][2], s[gA][3]),
                                    pack_h(s[gB][0], s[gB][1]), pack_h(s[gB][2], s[gB][3]) };
                #pragma unroll
                for (int jp = 0; jp < 4; jp++) {
                    const unsigned voff = ((ksv*16 + (sub & 1)*8 + r8) * 72 + (2*jp + (sub >> 1)) * 8);
                    unsigned vh[4];
                    ldsm4t(vh, sm_u32(Vsm + voff));
                    mma16816h(o[2*jp],   pah, vh);
                    mma16816h(o[2*jp+1], pah, vh + 2);
                }
            }
        }
        __syncthreads();
    }

    // epilogue: normalize, store plain fp16
    const float il0 = 1.0f / l0s, il1 = 1.0f / l1s;
    const int row0 = q0 + w*16 + (lane >> 2);
    #pragma unroll
    for (int g = 0; g < 8; g++) {
        const size_t cb = (size_t)h*64 + g*8 + ((lane & 3) << 1);
        {
            const size_t off = (size_t)(b*Sn + row0) * 1024 + cb;
            *(__half2*)(g_att16 + off) = __floats2half2_rn(o[g][0] * il0, o[g][1] * il0);
        }
        {
            const size_t off = (size_t)(b*Sn + row0 + 8) * 1024 + cb;
            *(__half2*)(g_att16 + off) = __floats2half2_rn(o[g][2] * il1, o[g][3] * il1);
        }
    }
}

// ---------------- launch ----------------
extern "C" void kernel_launch(void* const* d_in, const int* in_sizes, int n_in,
                              void* d_out, int out_size)
{
    const float* q    = (const float*)d_in[0];
    const float* k    = (const float*)d_in[1];
    const float* v    = (const float*)d_in[2];
    const float* W_Aq = (const float*)d_in[4];
    const float* W_Ak = (const float*)d_in[5];
    const float* W_Av = (const float*)d_in[6];
    const float* W_Bq = (const float*)d_in[7];
    const float* W_Bk = (const float*)d_in[8];
    const float* W_Bv = (const float*)d_in[9];
    const float* Wo   = (const float*)d_in[10];
    float* out = (float*)d_out;

    __half *pq16, *pk16, *pv16, *pwo16;
    cudaGetSymbolAddress((void**)&pq16,  g_xq16);
    cudaGetSymbolAddress((void**)&pk16,  g_xk16);
    cudaGetSymbolAddress((void**)&pv16,  g_xv16);
    cudaGetSymbolAddress((void**)&pwo16, g_wo16);

    cudaFuncSetAttribute(proj_k,    cudaFuncAttributeMaxDynamicSharedMemorySize, GSMEM);
    cudaFuncSetAttribute(gemm_wo_k, cudaFuncAttributeMaxDynamicSharedMemorySize, GSMEM);
    cudaFuncSetAttribute(flash_mma, cudaFuncAttributeMaxDynamicSharedMemorySize, FSMEM);

    cvt_kernel<<<Mrows*Dm/4/256, 256>>>(q,  pq16,  Mrows*Dm/4);
    cvt_kernel<<<Mrows*Dm/4/256, 256>>>(k,  pk16,  Mrows*Dm/4);
    cvt_kernel<<<Mrows*Dm/4/256, 256>>>(v,  pv16,  Mrows*Dm/4);
    cvt_kernel<<<Dm*Dm/4/256,    256>>>(Wo, pwo16, Dm*Dm/4);
    wpack_kernel<<<Dm*Dm/256, 256>>>(W_Aq, W_Bq, W_Ak, W_Bk, W_Av, W_Bv);

    proj_k<<<dim3(8, Mrows/128), 256, GSMEM>>>();

    combine_kernel<<<Mrows, 256>>>();

    flash_mma<<<dim3(Sn/128, Hn, Bn), 256, FSMEM>>>();

    gemm_wo_k<<<dim3(8, Mrows/128), 256, GSMEM>>>(out);
}

// round 11
// speedup vs baseline: 14.5379x; 1.0390x over previous
#include <cuda_runtime.h>
#include <cuda_fp16.h>
#include <math_constants.h>
#include <mma.h>
#include <cstddef>
#include <cstdint>

using namespace nvcuda;

#define Bn   2
#define Sn   2048
#define Hn   16
#define DKn  64
#define Dm   1024
#define QR   6
#define RK   2
#define Mrows (Bn*Sn)

// ---------------- global scratch ----------------
__device__ __half g_xq16[Mrows*Dm], g_xk16[Mrows*Dm], g_xv16[Mrows*Dm];
__device__ __half g_w16 [Dm*Dm];                 // packed proj weights [k][n-packed], fp16
__device__ __half g_wo16[Dm*Dm];                 // Wo [k][n], fp16
__device__ float g_proj[Mrows*Dm];
__device__ __half g_qh16[Bn*Hn*Sn*DKn];
__device__ __half g_kh16[Bn*Hn*Sn*DKn];
__device__ __half g_vh16[Bn*Hn*Sn*DKn];
__device__ __half g_att16[Mrows*Dm];

// ---------------- helpers ----------------
__device__ __forceinline__ unsigned sm_u32(const void* p)
{
    return (unsigned)__cvta_generic_to_shared(p);
}
__device__ __forceinline__ void ldsm4(unsigned r[4], unsigned a)
{
    asm volatile("ldmatrix.sync.aligned.m8n8.x4.shared.b16 {%0,%1,%2,%3}, [%4];"
        : "=r"(r[0]), "=r"(r[1]), "=r"(r[2]), "=r"(r[3]) : "r"(a));
}
__device__ __forceinline__ void ldsm4t(unsigned r[4], unsigned a)
{
    asm volatile("ldmatrix.sync.aligned.m8n8.x4.trans.shared.b16 {%0,%1,%2,%3}, [%4];"
        : "=r"(r[0]), "=r"(r[1]), "=r"(r[2]), "=r"(r[3]) : "r"(a));
}
__device__ __forceinline__ void mma16816h(float c[4], const unsigned a[4], const unsigned b[2])
{
    asm volatile(
        "mma.sync.aligned.m16n8k16.row.col.f32.f16.f16.f32 "
        "{%0,%1,%2,%3},{%4,%5,%6,%7},{%8,%9},{%0,%1,%2,%3};"
        : "+f"(c[0]), "+f"(c[1]), "+f"(c[2]), "+f"(c[3])
        : "r"(a[0]), "r"(a[1]), "r"(a[2]), "r"(a[3]), "r"(b[0]), "r"(b[1]));
}
__device__ __forceinline__ unsigned pack_h(float lo, float hi)
{
    unsigned r;
    asm("cvt.rn.f16x2.f32 %0, %1, %2;" : "=r"(r) : "f"(hi), "f"(lo));
    return r;
}
#define CPA16(dst, src) \
    asm volatile("cp.async.cg.shared.global [%0], [%1], 16;" :: "r"(dst), "l"(src))
#define CPA_COMMIT() asm volatile("cp.async.commit_group;")
#define CPA_WAIT1()  asm volatile("cp.async.wait_group 1;")
#define CPA_WAIT0()  asm volatile("cp.async.wait_group 0;")

// ---------------- prep kernels ----------------
// fused fp32->fp16 convert for q, k, v, Wo (regions of float4 work)
#define CVT_QKV (Mrows*Dm/4)      // 1M float4 each
#define CVT_WO  (Dm*Dm/4)         // 256K float4
#define CVT_TOT (3*CVT_QKV + CVT_WO)

__global__ __launch_bounds__(256) void cvt_all(
    const float* __restrict__ q, const float* __restrict__ k,
    const float* __restrict__ v, const float* __restrict__ wo)
{
    int i = blockIdx.x * 256 + threadIdx.x;
    if (i >= CVT_TOT) return;
    const float* src; __half* dst; int li;
    if      (i < CVT_QKV)     { src = q;  dst = g_xq16; li = i; }
    else if (i < 2*CVT_QKV)   { src = k;  dst = g_xk16; li = i - CVT_QKV; }
    else if (i < 3*CVT_QKV)   { src = v;  dst = g_xv16; li = i - 2*CVT_QKV; }
    else                      { src = wo; dst = g_wo16; li = i - 3*CVT_QKV; }
    float4 f = ((const float4*)src)[li];
    ((__half2*)dst)[li*2]   = __floats2half2_rn(f.x, f.y);
    ((__half2*)dst)[li*2+1] = __floats2half2_rn(f.z, f.w);
}

// pack weights into [1024][1024]: Aq@0(96/128) Bq@128(384) Ak@512(32/128) Bk@640 Av@768(32/128) Bv@896
__global__ __launch_bounds__(256) void wpack_kernel(
    const float* __restrict__ WAq, const float* __restrict__ WBq,
    const float* __restrict__ WAk, const float* __restrict__ WBk,
    const float* __restrict__ WAv, const float* __restrict__ WBv)
{
    int i = blockIdx.x * 256 + threadIdx.x;
    int row = i >> 10, c = i & 1023;
    const float* src; int lc, N;
    if      (c < 128) { src = WAq; lc = c;       N = 96;  }
    else if (c < 512) { src = WBq; lc = c - 128; N = 384; }
    else if (c < 640) { src = WAk; lc = c - 512; N = 32;  }
    else if (c < 768) { src = WBk; lc = c - 640; N = 128; }
    else if (c < 896) { src = WAv; lc = c - 768; N = 32;  }
    else              { src = WBv; lc = c - 896; N = 128; }
    float v = (lc < N) ? src[(size_t)row * N + lc] : 0.f;
    g_w16[i] = __float2half_rn(v);
}

// ---------------- plain-fp16 GEMM: CTA 128x128, warp 64x32, BK=32, 3-stage, 1 sync/iter ----------------
#define GA 0
#define GB (128*40)
#define G_STG (128*40 + 32*136)   // 9472 halves / stage
#define GSMEM (3*G_STG*2)         // 56832 bytes

using HFA = wmma::fragment<wmma::matrix_a,16,16,16,__half,wmma::row_major>;
using HFB = wmma::fragment<wmma::matrix_b,16,16,16,__half,wmma::row_major>;
using HFC = wmma::fragment<wmma::accumulator,16,16,16,float>;

__device__ __forceinline__ void gemm_issue(
    __half* smbase, int stage, int t,
    const __half* A, const __half* B,
    int m0, int n0, int k0)
{
    unsigned s0 = sm_u32(smbase) + stage * G_STG * 2;
    #pragma unroll
    for (int rep = 0; rep < 2; rep++) {
        const int id = t + rep * 256;              // A: 128 rows x 32 cols = 512 chunks
        const int ar = id >> 2, ac = (id & 3) * 8;
        CPA16(s0 + (GA + ar*40 + ac) * 2, A + (size_t)(m0 + ar) * 1024 + k0 + ac);
    }
    #pragma unroll
    for (int rep = 0; rep < 2; rep++) {
        const int id = t + rep * 256;              // B: 32 rows x 128 cols = 512 chunks
        const int kr = id >> 4, nc = (id & 15) * 8;
        CPA16(s0 + (GB + kr*136 + nc) * 2, B + (size_t)(k0 + kr) * 1024 + n0 + nc);
    }
}

__device__ __forceinline__ void gemm_body(
    const __half* __restrict__ A, const __half* __restrict__ B,
    float* __restrict__ C, int m0, int n0)
{
    extern __shared__ __align__(16) char gsm[];
    __half* smb = (__half*)gsm;

    const int t = threadIdx.x, wid = t >> 5;
    const int wm = wid >> 2, wn = wid & 3;     // 2 x 4 warps, warp tile 64x32

    HFC c[4][2];
    #pragma unroll
    for (int i = 0; i < 4; i++)
        #pragma unroll
        for (int j = 0; j < 2; j++)
            wmma::fill_fragment(c[i][j], 0.f);

    gemm_issue(smb, 0, t, A, B, m0, n0, 0);
    CPA_COMMIT();
    gemm_issue(smb, 1, t, A, B, m0, n0, 32);
    CPA_COMMIT();

    for (int it = 0; it < 32; it++) {
        CPA_WAIT1();               // stage it%3 data arrived
        __syncthreads();           // also: all warps done computing stage (it-1)%3

        if (it + 2 < 32) {         // issue into buffer (it+2)%3 == (it-1)%3 (free now)
            gemm_issue(smb, (it + 2) % 3, t, A, B, m0, n0, (it + 2) * 32);
            CPA_COMMIT();
        }

        const __half* As = smb + (it % 3)*G_STG + GA;
        const __half* Bs = smb + (it % 3)*G_STG + GB;
        #pragma unroll
        for (int ks = 0; ks < 2; ks++) {
            HFB bfr[2];
            #pragma unroll
            for (int j = 0; j < 2; j++)
                wmma::load_matrix_sync(bfr[j], Bs + (ks*16)*136 + wn*32 + j*16, 136);
            #pragma unroll
            for (int i = 0; i < 4; i++) {
                HFA ah;
                wmma::load_matrix_sync(ah, As + (wm*64 + i*16)*40 + ks*16, 40);
                #pragma unroll
                for (int j = 0; j < 2; j++)
                    wmma::mma_sync(c[i][j], ah, bfr[j], c[i][j]);
            }
        }
    }

    #pragma unroll
    for (int i = 0; i < 4; i++)
        #pragma unroll
        for (int j = 0; j < 2; j++)
            wmma::store_matrix_sync(C + (size_t)(m0 + wm*64 + i*16) * 1024 + n0 + wn*32 + j*16,
                                    c[i][j], 1024, wmma::mem_row_major);
}

__global__ __launch_bounds__(256,2) void proj_k()
{
    const int x = blockIdx.x;            // n-tile of 128
    const __half* A;
    if      (x < 4)  A = g_xq16;
    else if (x < 6)  A = g_xk16;
    else             A = g_xv16;
    gemm_body(A, g_w16, g_proj, blockIdx.y * 128, x * 128);
}

__global__ __launch_bounds__(256,2) void gemm_wo_k(float* __restrict__ C)
{
    gemm_body(g_att16, g_wo16, C, blockIdx.y * 128, blockIdx.x * 128);
}

// ---------------- combine: rank contraction + rotary + scales -> fp16 ----------------
__global__ __launch_bounds__(256) void combine_kernel()
{
    const int m = blockIdx.x;
    const int b = m / Sn, s = m % Sn;
    const int t = threadIdx.x;

    __shared__ float rowp[1024];
    __shared__ float sCos[32], sSin[32];

    ((float4*)rowp)[t] = ((const float4*)(g_proj + (size_t)m * 1024))[t];
    if (t < 32) {
        float inv = expf(-((float)(2*t) / 64.f) * logf(10000.0f));
        float fr  = (float)s * inv;
        sCos[t] = cosf(fr);
        sSin[t] = sinf(fr);
    }
    __syncthreads();

    const float qscale = (1.0f / QR) * (1.0f / (float)DKn);

    for (int pi = t; pi < Hn*DKn/2; pi += 256) {
        const int h = pi >> 5, dp = pi & 31, d0 = dp * 2;
        const size_t ob = ((size_t)(b*Hn + h) * Sn + s) * 64 + d0;

        float qv[2], kv[2], vv[2];
        #pragma unroll
        for (int e = 0; e < 2; e++) {
            const int d = d0 + e, dl = d & 31;
            const float cc = sCos[dl], sn = sSin[dl];
            float r1 = 0.f, r2 = 0.f;
            #pragma unroll
            for (int r = 0; r < QR; r++) {
                const float a = rowp[h*QR + r];
                r1 += a * rowp[128 + r*64 + dl];
                r2 += a * rowp[128 + r*64 + dl + 32];
            }
            qv[e] = ((d < 32) ? (r1*cc + r2*sn) : (-r1*sn + r2*cc)) * qscale;

            r1 = 0.f; r2 = 0.f;
            #pragma unroll
            for (int r = 0; r < RK; r++) {
                const float a = rowp[512 + h*RK + r];
                r1 += a * rowp[640 + r*64 + dl];
                r2 += a * rowp[640 + r*64 + dl + 32];
            }
            kv[e] = ((d < 32) ? (r1*cc + r2*sn) : (-r1*sn + r2*cc)) * 0.5f;

            float vs = 0.f;
            #pragma unroll
            for (int r = 0; r < RK; r++)
                vs += rowp[768 + h*RK + r] * rowp[896 + r*64 + d];
            vv[e] = vs * 0.5f;
        }
        *(__half2*)(g_qh16 + ob) = __floats2half2_rn(qv[0], qv[1]);
        *(__half2*)(g_kh16 + ob) = __floats2half2_rn(kv[0], kv[1]);
        *(__half2*)(g_vh16 + ob) = __floats2half2_rn(vv[0], vv[1]);
    }
}

// ---------------- flash attention: plain fp16, Br=128, Bc=64, 2-stage cp.async, 2 CTAs/SM ----------------
#define F_K 0
#define F_V (64*72)
#define F_STG (2*64*72)
#define FSMEM (2*F_STG*2)

__global__ __launch_bounds__(256,2) void flash_mma()
{
    extern __shared__ __align__(16) char fsm[];
    __half* smb = (__half*)fsm;

    const int qt = (gridDim.x - 1) - blockIdx.x;   // heavy tiles first
    const int h = blockIdx.y, b = blockIdx.z;
    const int q0 = qt * 128;

    const size_t hb = (size_t)(b*Hn + h) * Sn * 64;
    const __half* Qg = g_qh16 + hb;
    const __half* Kg = g_kh16 + hb;
    const __half* Vg = g_vh16 + hb;

    const int t = threadIdx.x, w = t >> 5, lane = t & 31;
    const int sub = lane >> 3, r8 = lane & 7;

    // stage Q into buffer 0 region
    {
        const int row = t >> 1, half = (t & 1) * 32;
        const uint4* sh = (const uint4*)(Qg + (size_t)(q0 + row) * 64 + half);
        uint4* dh = (uint4*)(smb + row*72 + half);
        #pragma unroll
        for (int i = 0; i < 4; i++) dh[i] = sh[i];
    }
    __syncthreads();

    // persistent Q fragments (fp16)
    unsigned qa[4][4];
    {
        const unsigned qoff = ((w*16 + (sub & 1)*8 + r8) * 72 + (sub >> 1) * 8);
        #pragma unroll
        for (int ks = 0; ks < 4; ks++)
            ldsm4(qa[ks], sm_u32(smb + qoff + ks*16));
    }
    __syncthreads();   // Q consumed -> smem reusable for KV stages

    float o[8][4];
    #pragma unroll
    for (int g = 0; g < 8; g++)
        #pragma unroll
        for (int e = 0; e < 4; e++) o[g][e] = 0.f;
    float m0s = -CUDART_INF_F, m1s = -CUDART_INF_F, l0s = 0.f, l1s = 0.f;

    const int nk = 2*qt + 2;
    const int krow = t >> 2, kcoff = (t & 3) * 16;

    auto issue = [&](int kt) {
        const size_t so = (size_t)(kt*64 + krow) * 64 + kcoff;
        const unsigned sb = sm_u32(smb) + ((kt & 1)*F_STG + krow*72 + kcoff) * 2;
        CPA16(sb + F_K*2,      Kg + so);
        CPA16(sb + F_K*2 + 16, Kg + so + 8);
        CPA16(sb + F_V*2,      Vg + so);
        CPA16(sb + F_V*2 + 16, Vg + so + 8);
    };

    issue(0); CPA_COMMIT();

    for (int kt = 0; kt < nk; kt++) {
        const int k0 = kt * 64;
        if (kt + 1 < nk) { issue(kt + 1); CPA_COMMIT(); CPA_WAIT1(); }
        else             { CPA_WAIT0(); }
        __syncthreads();

        const __half* Ksm = smb + (kt & 1)*F_STG + F_K;
        const __half* Vsm = smb + (kt & 1)*F_STG + F_V;

        if (k0 <= q0 + w*16 + 15) {
            float s[8][4];
            #pragma unroll
            for (int g = 0; g < 8; g++)
                #pragma unroll
                for (int e = 0; e < 4; e++) s[g][e] = 0.f;

            // S = Q K^T
            #pragma unroll
            for (int ks = 0; ks < 4; ks++) {
                #pragma unroll
                for (int jp = 0; jp < 4; jp++) {
                    const unsigned koff = ((jp*16 + (sub>>1)*8 + r8) * 72 + ks*16 + (sub & 1)*8);
                    unsigned bh[4];
                    ldsm4(bh, sm_u32(Ksm + koff));
                    mma16816h(s[2*jp],   qa[ks], bh);
                    mma16816h(s[2*jp+1], qa[ks], bh + 2);
                }
            }

            // causal mask (diagonal-adjacent tiles only)
            if (kt >= 2*qt) {
                const int row0 = q0 + w*16 + (lane >> 2);
                #pragma unroll
                for (int g = 0; g < 8; g++) {
                    const int col = k0 + g*8 + ((lane & 3) << 1);
                    if (col     > row0)     s[g][0] = -CUDART_INF_F;
                    if (col + 1 > row0)     s[g][1] = -CUDART_INF_F;
                    if (col     > row0 + 8) s[g][2] = -CUDART_INF_F;
                    if (col + 1 > row0 + 8) s[g][3] = -CUDART_INF_F;
                }
            }

            // online softmax (rows r0, r0+8)
            float ml0 = -CUDART_INF_F, ml1 = -CUDART_INF_F;
            #pragma unroll
            for (int g = 0; g < 8; g++) {
                ml0 = fmaxf(ml0, fmaxf(s[g][0], s[g][1]));
                ml1 = fmaxf(ml1, fmaxf(s[g][2], s[g][3]));
            }
            ml0 = fmaxf(ml0, __shfl_xor_sync(0xffffffffu, ml0, 1));
            ml0 = fmaxf(ml0, __shfl_xor_sync(0xffffffffu, ml0, 2));
            ml1 = fmaxf(ml1, __shfl_xor_sync(0xffffffffu, ml1, 1));
            ml1 = fmaxf(ml1, __shfl_xor_sync(0xffffffffu, ml1, 2));
            const float mn0 = fmaxf(m0s, ml0), mn1 = fmaxf(m1s, ml1);
            const float a0 = __expf(m0s - mn0), a1 = __expf(m1s - mn1);
            m0s = mn0; m1s = mn1;
            float ps0 = 0.f, ps1 = 0.f;
            #pragma unroll
            for (int g = 0; g < 8; g++) {
                s[g][0] = __expf(s[g][0] - mn0); ps0 += s[g][0];
                s[g][1] = __expf(s[g][1] - mn0); ps0 += s[g][1];
                s[g][2] = __expf(s[g][2] - mn1); ps1 += s[g][2];
                s[g][3] = __expf(s[g][3] - mn1); ps1 += s[g][3];
            }
            ps0 += __shfl_xor_sync(0xffffffffu, ps0, 1);
            ps0 += __shfl_xor_sync(0xffffffffu, ps0, 2);
            ps1 += __shfl_xor_sync(0xffffffffu, ps1, 1);
            ps1 += __shfl_xor_sync(0xffffffffu, ps1, 2);
            l0s = l0s * a0 + ps0;
            l1s = l1s * a1 + ps1;
            #pragma unroll
            for (int g = 0; g < 8; g++) {
                o[g][0] *= a0; o[g][1] *= a0;
                o[g][2] *= a1; o[g][3] *= a1;
            }

            // U += P V
            #pragma unroll
            for (int ksv = 0; ksv < 4; ksv++) {
                const int gA = 2*ksv, gB = gA + 1;
                unsigned pah[4] = { pack_h(s[gA][0], s[gA][1]), pack_h(s[gA][2], s[gA][3]),
                                    pack_h(s[gB][0], s[gB][1]), pack_h(s[gB][2], s[gB][3]) };
                #pragma unroll
                for (int jp = 0; jp < 4; jp++) {
                    const unsigned voff = ((ksv*16 + (sub & 1)*8 + r8) * 72 + (2*jp + (sub >> 1)) * 8);
                    unsigned vh[4];
                    ldsm4t(vh, sm_u32(Vsm + voff));
                    mma16816h(o[2*jp],   pah, vh);
                    mma16816h(o[2*jp+1], pah, vh + 2);
                }
            }
        }
        __syncthreads();
    }

    // epilogue: normalize, store plain fp16
    const float il0 = 1.0f / l0s, il1 = 1.0f / l1s;
    const int row0 = q0 + w*16 + (lane >> 2);
    #pragma unroll
    for (int g = 0; g < 8; g++) {
        const size_t cb = (size_t)h*64 + g*8 + ((lane & 3) << 1);
        {
            const size_t off = (size_t)(b*Sn + row0) * 1024 + cb;
            *(__half2*)(g_att16 + off) = __floats2half2_rn(o[g][0] * il0, o[g][1] * il0);
        }
        {
            const size_t off = (size_t)(b*Sn + row0 + 8) * 1024 + cb;
            *(__half2*)(g_att16 + off) = __floats2half2_rn(o[g][2] * il1, o[g][3] * il1);
        }
    }
}

// ---------------- launch ----------------
extern "C" void kernel_launch(void* const* d_in, const int* in_sizes, int n_in,
                              void* d_out, int out_size)
{
    const float* q    = (const float*)d_in[0];
    const float* k    = (const float*)d_in[1];
    const float* v    = (const float*)d_in[2];
    const float* W_Aq = (const float*)d_in[4];
    const float* W_Ak = (const float*)d_in[5];
    const float* W_Av = (const float*)d_in[6];
    const float* W_Bq = (const float*)d_in[7];
    const float* W_Bk = (const float*)d_in[8];
    const float* W_Bv = (const float*)d_in[9];
    const float* Wo   = (const float*)d_in[10];
    float* out = (float*)d_out;

    cudaFuncSetAttribute(proj_k,    cudaFuncAttributeMaxDynamicSharedMemorySize, GSMEM);
    cudaFuncSetAttribute(gemm_wo_k, cudaFuncAttributeMaxDynamicSharedMemorySize, GSMEM);
    cudaFuncSetAttribute(flash_mma, cudaFuncAttributeMaxDynamicSharedMemorySize, FSMEM);

    cvt_all<<<(CVT_TOT + 255)/256, 256>>>(q, k, v, Wo);
    wpack_kernel<<<Dm*Dm/256, 256>>>(W_Aq, W_Bq, W_Ak, W_Bk, W_Av, W_Bv);

    proj_k<<<dim3(8, Mrows/128), 256, GSMEM>>>();

    combine_kernel<<<Mrows, 256>>>();

    flash_mma<<<dim3(Sn/128, Hn, Bn), 256, FSMEM>>>();

    gemm_wo_k<<<dim3(8, Mrows/128), 256, GSMEM>>>(out);
}

// round 12
// speedup vs baseline: 14.7176x; 1.0124x over previous
#include <cuda_runtime.h>
#include <cuda_fp16.h>
#include <math_constants.h>
#include <mma.h>
#include <cstddef>
#include <cstdint>

using namespace nvcuda;

#define Bn   2
#define Sn   2048
#define Hn   16
#define DKn  64
#define Dm   1024
#define QR   6
#define RK   2
#define Mrows (Bn*Sn)

// ---------------- global scratch ----------------
__device__ __half g_xq16[Mrows*Dm], g_xk16[Mrows*Dm], g_xv16[Mrows*Dm];
__device__ __half g_w16 [Dm*Dm];                 // packed proj weights [k][n-packed], fp16
__device__ __half g_wo16[Dm*Dm];                 // Wo [k][n], fp16
__device__ __half g_proj16[Mrows*Dm];            // packed projection outputs, fp16
__device__ __half g_qh16[Bn*Hn*Sn*DKn];
__device__ __half g_kh16[Bn*Hn*Sn*DKn];
__device__ __half g_vh16[Bn*Hn*Sn*DKn];
__device__ __half g_att16[Mrows*Dm];

// ---------------- helpers ----------------
__device__ __forceinline__ unsigned sm_u32(const void* p)
{
    return (unsigned)__cvta_generic_to_shared(p);
}
__device__ __forceinline__ void ldsm4(unsigned r[4], unsigned a)
{
    asm volatile("ldmatrix.sync.aligned.m8n8.x4.shared.b16 {%0,%1,%2,%3}, [%4];"
        : "=r"(r[0]), "=r"(r[1]), "=r"(r[2]), "=r"(r[3]) : "r"(a));
}
__device__ __forceinline__ void ldsm4t(unsigned r[4], unsigned a)
{
    asm volatile("ldmatrix.sync.aligned.m8n8.x4.trans.shared.b16 {%0,%1,%2,%3}, [%4];"
        : "=r"(r[0]), "=r"(r[1]), "=r"(r[2]), "=r"(r[3]) : "r"(a));
}
__device__ __forceinline__ void mma16816h(float c[4], const unsigned a[4], const unsigned b[2])
{
    asm volatile(
        "mma.sync.aligned.m16n8k16.row.col.f32.f16.f16.f32 "
        "{%0,%1,%2,%3},{%4,%5,%6,%7},{%8,%9},{%0,%1,%2,%3};"
        : "+f"(c[0]), "+f"(c[1]), "+f"(c[2]), "+f"(c[3])
        : "r"(a[0]), "r"(a[1]), "r"(a[2]), "r"(a[3]), "r"(b[0]), "r"(b[1]));
}
__device__ __forceinline__ unsigned pack_h(float lo, float hi)
{
    unsigned r;
    asm("cvt.rn.f16x2.f32 %0, %1, %2;" : "=r"(r) : "f"(hi), "f"(lo));
    return r;
}
#define CPA16(dst, src) \
    asm volatile("cp.async.cg.shared.global [%0], [%1], 16;" :: "r"(dst), "l"(src))
#define CPA_COMMIT() asm volatile("cp.async.commit_group;")
#define CPA_WAIT1()  asm volatile("cp.async.wait_group 1;")
#define CPA_WAIT0()  asm volatile("cp.async.wait_group 0;")

// ---------------- fused prep kernel ----------------
// regions (in work items):
//  [0, 3*CVT_QKV)            : q/k/v convert, float4 granularity
//  [.., +CVT_WO)             : Wo convert, float4 granularity
//  [.., +Dm*Dm)              : packed proj weight build, scalar granularity
#define CVT_QKV (Mrows*Dm/4)
#define CVT_WO  (Dm*Dm/4)
#define PREP_CVT (3*CVT_QKV + CVT_WO)
#define PREP_TOT (PREP_CVT + Dm*Dm)

__global__ __launch_bounds__(256) void prep_all(
    const float* __restrict__ q, const float* __restrict__ k,
    const float* __restrict__ v, const float* __restrict__ wo,
    const float* __restrict__ WAq, const float* __restrict__ WBq,
    const float* __restrict__ WAk, const float* __restrict__ WBk,
    const float* __restrict__ WAv, const float* __restrict__ WBv)
{
    int i = blockIdx.x * 256 + threadIdx.x;
    if (i >= PREP_TOT) return;
    if (i < PREP_CVT) {
        const float* src; __half* dst; int li;
        if      (i < CVT_QKV)   { src = q;  dst = g_xq16; li = i; }
        else if (i < 2*CVT_QKV) { src = k;  dst = g_xk16; li = i - CVT_QKV; }
        else if (i < 3*CVT_QKV) { src = v;  dst = g_xv16; li = i - 2*CVT_QKV; }
        else                    { src = wo; dst = g_wo16; li = i - 3*CVT_QKV; }
        float4 f = ((const float4*)src)[li];
        ((__half2*)dst)[li*2]   = __floats2half2_rn(f.x, f.y);
        ((__half2*)dst)[li*2+1] = __floats2half2_rn(f.z, f.w);
    } else {
        int j = i - PREP_CVT;
        int row = j >> 10, c = j & 1023;
        const float* src; int lc, N;
        if      (c < 128) { src = WAq; lc = c;       N = 96;  }
        else if (c < 512) { src = WBq; lc = c - 128; N = 384; }
        else if (c < 640) { src = WAk; lc = c - 512; N = 32;  }
        else if (c < 768) { src = WBk; lc = c - 640; N = 128; }
        else if (c < 896) { src = WAv; lc = c - 768; N = 32;  }
        else              { src = WBv; lc = c - 896; N = 128; }
        float val = (lc < N) ? src[(size_t)row * N + lc] : 0.f;
        g_w16[j] = __float2half_rn(val);
    }
}

// ---------------- plain-fp16 GEMM: CTA 128x128, warp 64x32, BK=32, 3-stage, 1 sync/iter ----------------
#define GA 0
#define GB (128*40)
#define G_STG (128*40 + 32*136)   // 9472 halves / stage
#define GSMEM (3*G_STG*2)         // 56832 bytes

using HFA = wmma::fragment<wmma::matrix_a,16,16,16,__half,wmma::row_major>;
using HFB = wmma::fragment<wmma::matrix_b,16,16,16,__half,wmma::row_major>;
using HFC = wmma::fragment<wmma::accumulator,16,16,16,float>;

__device__ __forceinline__ void gemm_issue(
    __half* smbase, int stage, int t,
    const __half* A, const __half* B,
    int m0, int n0, int k0)
{
    unsigned s0 = sm_u32(smbase) + stage * G_STG * 2;
    #pragma unroll
    for (int rep = 0; rep < 2; rep++) {
        const int id = t + rep * 256;
        const int ar = id >> 2, ac = (id & 3) * 8;
        CPA16(s0 + (GA + ar*40 + ac) * 2, A + (size_t)(m0 + ar) * 1024 + k0 + ac);
    }
    #pragma unroll
    for (int rep = 0; rep < 2; rep++) {
        const int id = t + rep * 256;
        const int kr = id >> 4, nc = (id & 15) * 8;
        CPA16(s0 + (GB + kr*136 + nc) * 2, B + (size_t)(k0 + kr) * 1024 + n0 + nc);
    }
}

// mainloop producing register accumulators; epilogue handled by caller
template <typename EPI>
__device__ __forceinline__ void gemm_main(
    const __half* __restrict__ A, const __half* __restrict__ B,
    int m0, int n0, EPI epi)
{
    extern __shared__ __align__(16) char gsm[];
    __half* smb = (__half*)gsm;

    const int t = threadIdx.x, wid = t >> 5;
    const int wm = wid >> 2, wn = wid & 3;     // 2 x 4 warps, warp tile 64x32

    HFC c[4][2];
    #pragma unroll
    for (int i = 0; i < 4; i++)
        #pragma unroll
        for (int j = 0; j < 2; j++)
            wmma::fill_fragment(c[i][j], 0.f);

    gemm_issue(smb, 0, t, A, B, m0, n0, 0);
    CPA_COMMIT();
    gemm_issue(smb, 1, t, A, B, m0, n0, 32);
    CPA_COMMIT();

    for (int it = 0; it < 32; it++) {
        CPA_WAIT1();
        __syncthreads();

        if (it + 2 < 32) {
            gemm_issue(smb, (it + 2) % 3, t, A, B, m0, n0, (it + 2) * 32);
            CPA_COMMIT();
        }

        const __half* As = smb + (it % 3)*G_STG + GA;
        const __half* Bs = smb + (it % 3)*G_STG + GB;
        #pragma unroll
        for (int ks = 0; ks < 2; ks++) {
            HFB bfr[2];
            #pragma unroll
            for (int j = 0; j < 2; j++)
                wmma::load_matrix_sync(bfr[j], Bs + (ks*16)*136 + wn*32 + j*16, 136);
            #pragma unroll
            for (int i = 0; i < 4; i++) {
                HFA ah;
                wmma::load_matrix_sync(ah, As + (wm*64 + i*16)*40 + ks*16, 40);
                #pragma unroll
                for (int j = 0; j < 2; j++)
                    wmma::mma_sync(c[i][j], ah, bfr[j], c[i][j]);
            }
        }
    }
    CPA_WAIT0();
    __syncthreads();     // stage buffers now reusable as scratch by epilogue
    epi(c, smb, wm, wn, m0, n0);
}

__global__ __launch_bounds__(256,2) void proj_k()
{
    const int x = blockIdx.x;
    const __half* A;
    if      (x < 4)  A = g_xq16;
    else if (x < 6)  A = g_xk16;
    else             A = g_xv16;

    gemm_main(A, g_w16, blockIdx.y * 128, x * 128,
        [](HFC (&c)[4][2], __half* smb, int wm, int wn, int m0, int n0) {
            // fp16 epilogue: bounce each 16x16 fragment through per-warp smem
            const int wid = (threadIdx.x >> 5), lane = threadIdx.x & 31;
            float* sw = (float*)smb + wid * 336;          // 16x20 floats + pad
            const int row = lane >> 1, cb4 = (lane & 1) * 8;
            #pragma unroll
            for (int i = 0; i < 4; i++)
                #pragma unroll
                for (int j = 0; j < 2; j++) {
                    wmma::store_matrix_sync(sw, c[i][j], 20, wmma::mem_row_major);
                    __syncwarp();
                    float4 f0 = *(float4*)(sw + row*20 + cb4);
                    float4 f1 = *(float4*)(sw + row*20 + cb4 + 4);
                    __half2 h[4] = {
                        __floats2half2_rn(f0.x, f0.y), __floats2half2_rn(f0.z, f0.w),
                        __floats2half2_rn(f1.x, f1.y), __floats2half2_rn(f1.z, f1.w) };
                    *(uint4*)(g_proj16 + (size_t)(m0 + wm*64 + i*16 + row) * 1024
                              + n0 + wn*32 + j*16 + cb4) = *(uint4*)h;
                    __syncwarp();
                }
        });
}

__global__ __launch_bounds__(256,2) void gemm_wo_k(float* __restrict__ C)
{
    gemm_main(g_att16, g_wo16, blockIdx.y * 128, blockIdx.x * 128,
        [C](HFC (&c)[4][2], __half*, int wm, int wn, int m0, int n0) {
            #pragma unroll
            for (int i = 0; i < 4; i++)
                #pragma unroll
                for (int j = 0; j < 2; j++)
                    wmma::store_matrix_sync(C + (size_t)(m0 + wm*64 + i*16) * 1024
                                            + n0 + wn*32 + j*16,
                                            c[i][j], 1024, wmma::mem_row_major);
        });
}

// ---------------- combine: rank contraction + rotary + scales -> fp16 ----------------
__global__ __launch_bounds__(256) void combine_kernel()
{
    const int m = blockIdx.x;
    const int b = m / Sn, s = m % Sn;
    const int t = threadIdx.x;

    __shared__ float rowp[1024];
    __shared__ float sCos[32], sSin[32];

    {
        // load 1024 halves (2KB) and widen to fp32 smem
        const uint2 hv = ((const uint2*)(g_proj16 + (size_t)m * 1024))[t];
        __half2 h0 = *(const __half2*)&hv.x;
        __half2 h1 = *(const __half2*)&hv.y;
        float2 f0 = __half22float2(h0), f1 = __half22float2(h1);
        rowp[t*4+0] = f0.x; rowp[t*4+1] = f0.y;
        rowp[t*4+2] = f1.x; rowp[t*4+3] = f1.y;
    }
    if (t < 32) {
        float inv = expf(-((float)(2*t) / 64.f) * logf(10000.0f));
        float fr  = (float)s * inv;
        sCos[t] = cosf(fr);
        sSin[t] = sinf(fr);
    }
    __syncthreads();

    const float qscale = (1.0f / QR) * (1.0f / (float)DKn);

    for (int pi = t; pi < Hn*DKn/2; pi += 256) {
        const int h = pi >> 5, dp = pi & 31, d0 = dp * 2;
        const size_t ob = ((size_t)(b*Hn + h) * Sn + s) * 64 + d0;

        float qv[2], kv[2], vv[2];
        #pragma unroll
        for (int e = 0; e < 2; e++) {
            const int d = d0 + e, dl = d & 31;
            const float cc = sCos[dl], sn = sSin[dl];
            float r1 = 0.f, r2 = 0.f;
            #pragma unroll
            for (int r = 0; r < QR; r++) {
                const float a = rowp[h*QR + r];
                r1 += a * rowp[128 + r*64 + dl];
                r2 += a * rowp[128 + r*64 + dl + 32];
            }
            qv[e] = ((d < 32) ? (r1*cc + r2*sn) : (-r1*sn + r2*cc)) * qscale;

            r1 = 0.f; r2 = 0.f;
            #pragma unroll
            for (int r = 0; r < RK; r++) {
                const float a = rowp[512 + h*RK + r];
                r1 += a * rowp[640 + r*64 + dl];
                r2 += a * rowp[640 + r*64 + dl + 32];
            }
            kv[e] = ((d < 32) ? (r1*cc + r2*sn) : (-r1*sn + r2*cc)) * 0.5f;

            float vs = 0.f;
            #pragma unroll
            for (int r = 0; r < RK; r++)
                vs += rowp[768 + h*RK + r] * rowp[896 + r*64 + d];
            vv[e] = vs * 0.5f;
        }
        *(__half2*)(g_qh16 + ob) = __floats2half2_rn(qv[0], qv[1]);
        *(__half2*)(g_kh16 + ob) = __floats2half2_rn(kv[0], kv[1]);
        *(__half2*)(g_vh16 + ob) = __floats2half2_rn(vv[0], vv[1]);
    }
}

// ---------------- flash attention: plain fp16, Br=128, Bc=64, 2-stage cp.async, 2 CTAs/SM ----------------
#define F_K 0
#define F_V (64*72)
#define F_STG (2*64*72)
#define FSMEM (2*F_STG*2)

__global__ __launch_bounds__(256,2) void flash_mma()
{
    extern __shared__ __align__(16) char fsm[];
    __half* smb = (__half*)fsm;

    const int qt = (gridDim.x - 1) - blockIdx.x;   // heavy tiles first
    const int h = blockIdx.y, b = blockIdx.z;
    const int q0 = qt * 128;

    const size_t hb = (size_t)(b*Hn + h) * Sn * 64;
    const __half* Qg = g_qh16 + hb;
    const __half* Kg = g_kh16 + hb;
    const __half* Vg = g_vh16 + hb;

    const int t = threadIdx.x, w = t >> 5, lane = t & 31;
    const int sub = lane >> 3, r8 = lane & 7;

    // stage Q into buffer 0 region
    {
        const int row = t >> 1, half = (t & 1) * 32;
        const uint4* sh = (const uint4*)(Qg + (size_t)(q0 + row) * 64 + half);
        uint4* dh = (uint4*)(smb + row*72 + half);
        #pragma unroll
        for (int i = 0; i < 4; i++) dh[i] = sh[i];
    }
    __syncthreads();

    // persistent Q fragments (fp16)
    unsigned qa[4][4];
    {
        const unsigned qoff = ((w*16 + (sub & 1)*8 + r8) * 72 + (sub >> 1) * 8);
        #pragma unroll
        for (int ks = 0; ks < 4; ks++)
            ldsm4(qa[ks], sm_u32(smb + qoff + ks*16));
    }
    __syncthreads();   // Q consumed -> smem reusable for KV stages

    float o[8][4];
    #pragma unroll
    for (int g = 0; g < 8; g++)
        #pragma unroll
        for (int e = 0; e < 4; e++) o[g][e] = 0.f;
    float m0s = -CUDART_INF_F, m1s = -CUDART_INF_F, l0s = 0.f, l1s = 0.f;

    const int nk = 2*qt + 2;
    const int krow = t >> 2, kcoff = (t & 3) * 16;

    auto issue = [&](int kt) {
        const size_t so = (size_t)(kt*64 + krow) * 64 + kcoff;
        const unsigned sb = sm_u32(smb) + ((kt & 1)*F_STG + krow*72 + kcoff) * 2;
        CPA16(sb + F_K*2,      Kg + so);
        CPA16(sb + F_K*2 + 16, Kg + so + 8);
        CPA16(sb + F_V*2,      Vg + so);
        CPA16(sb + F_V*2 + 16, Vg + so + 8);
    };

    issue(0); CPA_COMMIT();

    for (int kt = 0; kt < nk; kt++) {
        const int k0 = kt * 64;
        if (kt + 1 < nk) { issue(kt + 1); CPA_COMMIT(); CPA_WAIT1(); }
        else             { CPA_WAIT0(); }
        __syncthreads();

        const __half* Ksm = smb + (kt & 1)*F_STG + F_K;
        const __half* Vsm = smb + (kt & 1)*F_STG + F_V;

        if (k0 <= q0 + w*16 + 15) {
            float s[8][4];
            #pragma unroll
            for (int g = 0; g < 8; g++)
                #pragma unroll
                for (int e = 0; e < 4; e++) s[g][e] = 0.f;

            // S = Q K^T
            #pragma unroll
            for (int ks = 0; ks < 4; ks++) {
                #pragma unroll
                for (int jp = 0; jp < 4; jp++) {
                    const unsigned koff = ((jp*16 + (sub>>1)*8 + r8) * 72 + ks*16 + (sub & 1)*8);
                    unsigned bh[4];
                    ldsm4(bh, sm_u32(Ksm + koff));
                    mma16816h(s[2*jp],   qa[ks], bh);
                    mma16816h(s[2*jp+1], qa[ks], bh + 2);
                }
            }

            // causal mask (diagonal-adjacent tiles only)
            if (kt >= 2*qt) {
                const int row0 = q0 + w*16 + (lane >> 2);
                #pragma unroll
                for (int g = 0; g < 8; g++) {
                    const int col = k0 + g*8 + ((lane & 3) << 1);
                    if (col     > row0)     s[g][0] = -CUDART_INF_F;
                    if (col + 1 > row0)     s[g][1] = -CUDART_INF_F;
                    if (col     > row0 + 8) s[g][2] = -CUDART_INF_F;
                    if (col + 1 > row0 + 8) s[g][3] = -CUDART_INF_F;
                }
            }

            // online softmax (rows r0, r0+8)
            float ml0 = -CUDART_INF_F, ml1 = -CUDART_INF_F;
            #pragma unroll
            for (int g = 0; g < 8; g++) {
                ml0 = fmaxf(ml0, fmaxf(s[g][0], s[g][1]));
                ml1 = fmaxf(ml1, fmaxf(s[g][2], s[g][3]));
            }
            ml0 = fmaxf(ml0, __shfl_xor_sync(0xffffffffu, ml0, 1));
            ml0 = fmaxf(ml0, __shfl_xor_sync(0xffffffffu, ml0, 2));
            ml1 = fmaxf(ml1, __shfl_xor_sync(0xffffffffu, ml1, 1));
            ml1 = fmaxf(ml1, __shfl_xor_sync(0xffffffffu, ml1, 2));
            const float mn0 = fmaxf(m0s, ml0), mn1 = fmaxf(m1s, ml1);
            const float a0 = __expf(m0s - mn0), a1 = __expf(m1s - mn1);
            m0s = mn0; m1s = mn1;
            float ps0 = 0.f, ps1 = 0.f;
            #pragma unroll
            for (int g = 0; g < 8; g++) {
                s[g][0] = __expf(s[g][0] - mn0); ps0 += s[g][0];
                s[g][1] = __expf(s[g][1] - mn0); ps0 += s[g][1];
                s[g][2] = __expf(s[g][2] - mn1); ps1 += s[g][2];
                s[g][3] = __expf(s[g][3] - mn1); ps1 += s[g][3];
            }
            ps0 += __shfl_xor_sync(0xffffffffu, ps0, 1);
            ps0 += __shfl_xor_sync(0xffffffffu, ps0, 2);
            ps1 += __shfl_xor_sync(0xffffffffu, ps1, 1);
            ps1 += __shfl_xor_sync(0xffffffffu, ps1, 2);
            l0s = l0s * a0 + ps0;
            l1s = l1s * a1 + ps1;
            #pragma unroll
            for (int g = 0; g < 8; g++) {
                o[g][0] *= a0; o[g][1] *= a0;
                o[g][2] *= a1; o[g][3] *= a1;
            }

            // U += P V
            #pragma unroll
            for (int ksv = 0; ksv < 4; ksv++) {
                const int gA = 2*ksv, gB = gA + 1;
                unsigned pah[4] = { pack_h(s[gA][0], s[gA][1]), pack_h(s[gA][2], s[gA][3]),
                                    pack_h(s[gB][0], s[gB][1]), pack_h(s[gB][2], s[gB][3]) };
                #pragma unroll
                for (int jp = 0; jp < 4; jp++) {
                    const unsigned voff = ((ksv*16 + (sub & 1)*8 + r8) * 72 + (2*jp + (sub >> 1)) * 8);
                    unsigned vh[4];
                    ldsm4t(vh, sm_u32(Vsm + voff));
                    mma16816h(o[2*jp],   pah, vh);
                    mma16816h(o[2*jp+1], pah, vh + 2);
                }
            }
        }
        __syncthreads();
    }

    // epilogue: normalize, store plain fp16
    const float il0 = 1.0f / l0s, il1 = 1.0f / l1s;
    const int row0 = q0 + w*16 + (lane >> 2);
    #pragma unroll
    for (int g = 0; g < 8; g++) {
        const size_t cb = (size_t)h*64 + g*8 + ((lane & 3) << 1);
        {
            const size_t off = (size_t)(b*Sn + row0) * 1024 + cb;
            *(__half2*)(g_att16 + off) = __floats2half2_rn(o[g][0] * il0, o[g][1] * il0);
        }
        {
            const size_t off = (size_t)(b*Sn + row0 + 8) * 1024 + cb;
            *(__half2*)(g_att16 + off) = __floats2half2_rn(o[g][2] * il1, o[g][3] * il1);
        }
    }
}

// ---------------- launch ----------------
extern "C" void kernel_launch(void* const* d_in, const int* in_sizes, int n_in,
                              void* d_out, int out_size)
{
    const float* q    = (const float*)d_in[0];
    const float* k    = (const float*)d_in[1];
    const float* v    = (const float*)d_in[2];
    const float* W_Aq = (const float*)d_in[4];
    const float* W_Ak = (const float*)d_in[5];
    const float* W_Av = (const float*)d_in[6];
    const float* W_Bq = (const float*)d_in[7];
    const float* W_Bk = (const float*)d_in[8];
    const float* W_Bv = (const float*)d_in[9];
    const float* Wo   = (const float*)d_in[10];
    float* out = (float*)d_out;

    cudaFuncSetAttribute(proj_k,    cudaFuncAttributeMaxDynamicSharedMemorySize, GSMEM);
    cudaFuncSetAttribute(gemm_wo_k, cudaFuncAttributeMaxDynamicSharedMemorySize, GSMEM);
    cudaFuncSetAttribute(flash_mma, cudaFuncAttributeMaxDynamicSharedMemorySize, FSMEM);

    prep_all<<<(PREP_TOT + 255)/256, 256>>>(q, k, v, Wo,
                                            W_Aq, W_Bq, W_Ak, W_Bk, W_Av, W_Bv);

    proj_k<<<dim3(8, Mrows/128), 256, GSMEM>>>();

    combine_kernel<<<Mrows, 256>>>();

    flash_mma<<<dim3(Sn/128, Hn, Bn), 256, FSMEM>>>();

    gemm_wo_k<<<dim3(8, Mrows/128), 256, GSMEM>>>(out);
}

// round 13
// speedup vs baseline: 15.1972x; 1.0326x over previous
#include <cuda_runtime.h>
#include <cuda_fp16.h>
#include <math_constants.h>
#include <mma.h>
#include <cstddef>
#include <cstdint>

using namespace nvcuda;

#define Bn   2
#define Sn   2048
#define Hn   16
#define DKn  64
#define Dm   1024
#define QR   6
#define RK   2
#define Mrows (Bn*Sn)

// ---------------- global scratch ----------------
__device__ __half g_xq16[Mrows*Dm], g_xk16[Mrows*Dm], g_xv16[Mrows*Dm];
__device__ __half g_w16 [Dm*Dm];                 // packed proj weights [k][n-packed], fp16
__device__ __half g_wo16[Dm*Dm];                 // Wo [k][n], fp16
__device__ __half g_proj16[Mrows*Dm];            // packed projection outputs, fp16
__device__ __half g_qh16[Bn*Hn*Sn*DKn];          // pre-scaled by 1/QR/DK * log2(e)
__device__ __half g_kh16[Bn*Hn*Sn*DKn];
__device__ __half g_vh16[Bn*Hn*Sn*DKn];
__device__ __half g_att16[Mrows*Dm];

// ---------------- helpers ----------------
__device__ __forceinline__ unsigned sm_u32(const void* p)
{
    return (unsigned)__cvta_generic_to_shared(p);
}
__device__ __forceinline__ void ldsm4(unsigned r[4], unsigned a)
{
    asm volatile("ldmatrix.sync.aligned.m8n8.x4.shared.b16 {%0,%1,%2,%3}, [%4];"
        : "=r"(r[0]), "=r"(r[1]), "=r"(r[2]), "=r"(r[3]) : "r"(a));
}
__device__ __forceinline__ void ldsm4t(unsigned r[4], unsigned a)
{
    asm volatile("ldmatrix.sync.aligned.m8n8.x4.trans.shared.b16 {%0,%1,%2,%3}, [%4];"
        : "=r"(r[0]), "=r"(r[1]), "=r"(r[2]), "=r"(r[3]) : "r"(a));
}
__device__ __forceinline__ void mma16816h(float c[4], const unsigned a[4], const unsigned b[2])
{
    asm volatile(
        "mma.sync.aligned.m16n8k16.row.col.f32.f16.f16.f32 "
        "{%0,%1,%2,%3},{%4,%5,%6,%7},{%8,%9},{%0,%1,%2,%3};"
        : "+f"(c[0]), "+f"(c[1]), "+f"(c[2]), "+f"(c[3])
        : "r"(a[0]), "r"(a[1]), "r"(a[2]), "r"(a[3]), "r"(b[0]), "r"(b[1]));
}
__device__ __forceinline__ unsigned pack_h(float lo, float hi)
{
    unsigned r;
    asm("cvt.rn.f16x2.f32 %0, %1, %2;" : "=r"(r) : "f"(hi), "f"(lo));
    return r;
}
__device__ __forceinline__ float ex2(float x)
{
    float r;
    asm("ex2.approx.ftz.f32 %0, %1;" : "=f"(r) : "f"(x));
    return r;
}
#define CPA16(dst, src) \
    asm volatile("cp.async.cg.shared.global [%0], [%1], 16;" :: "r"(dst), "l"(src))
#define CPA_COMMIT() asm volatile("cp.async.commit_group;")
#define CPA_WAIT1()  asm volatile("cp.async.wait_group 1;")
#define CPA_WAIT0()  asm volatile("cp.async.wait_group 0;")

// ---------------- fused prep kernel ----------------
#define CVT_QKV (Mrows*Dm/4)
#define CVT_WO  (Dm*Dm/4)
#define PREP_CVT (3*CVT_QKV + CVT_WO)
#define PREP_TOT (PREP_CVT + Dm*Dm)

__global__ __launch_bounds__(256) void prep_all(
    const float* __restrict__ q, const float* __restrict__ k,
    const float* __restrict__ v, const float* __restrict__ wo,
    const float* __restrict__ WAq, const float* __restrict__ WBq,
    const float* __restrict__ WAk, const float* __restrict__ WBk,
    const float* __restrict__ WAv, const float* __restrict__ WBv)
{
    int i = blockIdx.x * 256 + threadIdx.x;
    if (i >= PREP_TOT) return;
    if (i < PREP_CVT) {
        const float* src; __half* dst; int li;
        if      (i < CVT_QKV)   { src = q;  dst = g_xq16; li = i; }
        else if (i < 2*CVT_QKV) { src = k;  dst = g_xk16; li = i - CVT_QKV; }
        else if (i < 3*CVT_QKV) { src = v;  dst = g_xv16; li = i - 2*CVT_QKV; }
        else                    { src = wo; dst = g_wo16; li = i - 3*CVT_QKV; }
        float4 f = ((const float4*)src)[li];
        ((__half2*)dst)[li*2]   = __floats2half2_rn(f.x, f.y);
        ((__half2*)dst)[li*2+1] = __floats2half2_rn(f.z, f.w);
    } else {
        int j = i - PREP_CVT;
        int row = j >> 10, c = j & 1023;
        const float* src; int lc, N;
        if      (c < 128) { src = WAq; lc = c;       N = 96;  }
        else if (c < 512) { src = WBq; lc = c - 128; N = 384; }
        else if (c < 640) { src = WAk; lc = c - 512; N = 32;  }
        else if (c < 768) { src = WBk; lc = c - 640; N = 128; }
        else if (c < 896) { src = WAv; lc = c - 768; N = 32;  }
        else              { src = WBv; lc = c - 896; N = 128; }
        float val = (lc < N) ? src[(size_t)row * N + lc] : 0.f;
        g_w16[j] = __float2half_rn(val);
    }
}

// ---------------- plain-fp16 GEMM: CTA 128x128, warp 64x32, BK=32, 3-stage, 1 sync/iter ----------------
#define GA 0
#define GB (128*40)
#define G_STG (128*40 + 32*136)
#define GSMEM (3*G_STG*2)

using HFA = wmma::fragment<wmma::matrix_a,16,16,16,__half,wmma::row_major>;
using HFB = wmma::fragment<wmma::matrix_b,16,16,16,__half,wmma::row_major>;
using HFC = wmma::fragment<wmma::accumulator,16,16,16,float>;

__device__ __forceinline__ void gemm_issue(
    __half* smbase, int stage, int t,
    const __half* A, const __half* B,
    int m0, int n0, int k0)
{
    unsigned s0 = sm_u32(smbase) + stage * G_STG * 2;
    #pragma unroll
    for (int rep = 0; rep < 2; rep++) {
        const int id = t + rep * 256;
        const int ar = id >> 2, ac = (id & 3) * 8;
        CPA16(s0 + (GA + ar*40 + ac) * 2, A + (size_t)(m0 + ar) * 1024 + k0 + ac);
    }
    #pragma unroll
    for (int rep = 0; rep < 2; rep++) {
        const int id = t + rep * 256;
        const int kr = id >> 4, nc = (id & 15) * 8;
        CPA16(s0 + (GB + kr*136 + nc) * 2, B + (size_t)(k0 + kr) * 1024 + n0 + nc);
    }
}

template <typename EPI>
__device__ __forceinline__ void gemm_main(
    const __half* __restrict__ A, const __half* __restrict__ B,
    int m0, int n0, EPI epi)
{
    extern __shared__ __align__(16) char gsm[];
    __half* smb = (__half*)gsm;

    const int t = threadIdx.x, wid = t >> 5;
    const int wm = wid >> 2, wn = wid & 3;

    HFC c[4][2];
    #pragma unroll
    for (int i = 0; i < 4; i++)
        #pragma unroll
        for (int j = 0; j < 2; j++)
            wmma::fill_fragment(c[i][j], 0.f);

    gemm_issue(smb, 0, t, A, B, m0, n0, 0);
    CPA_COMMIT();
    gemm_issue(smb, 1, t, A, B, m0, n0, 32);
    CPA_COMMIT();

    for (int it = 0; it < 32; it++) {
        CPA_WAIT1();
        __syncthreads();

        if (it + 2 < 32) {
            gemm_issue(smb, (it + 2) % 3, t, A, B, m0, n0, (it + 2) * 32);
            CPA_COMMIT();
        }

        const __half* As = smb + (it % 3)*G_STG + GA;
        const __half* Bs = smb + (it % 3)*G_STG + GB;
        #pragma unroll
        for (int ks = 0; ks < 2; ks++) {
            HFB bfr[2];
            #pragma unroll
            for (int j = 0; j < 2; j++)
                wmma::load_matrix_sync(bfr[j], Bs + (ks*16)*136 + wn*32 + j*16, 136);
            #pragma unroll
            for (int i = 0; i < 4; i++) {
                HFA ah;
                wmma::load_matrix_sync(ah, As + (wm*64 + i*16)*40 + ks*16, 40);
                #pragma unroll
                for (int j = 0; j < 2; j++)
                    wmma::mma_sync(c[i][j], ah, bfr[j], c[i][j]);
            }
        }
    }
    CPA_WAIT0();
    __syncthreads();
    epi(c, smb, wm, wn, m0, n0);
}

__global__ __launch_bounds__(256,2) void proj_k()
{
    const int x = blockIdx.x;
    const __half* A;
    if      (x < 4)  A = g_xq16;
    else if (x < 6)  A = g_xk16;
    else             A = g_xv16;

    gemm_main(A, g_w16, blockIdx.y * 128, x * 128,
        [](HFC (&c)[4][2], __half* smb, int wm, int wn, int m0, int n0) {
            const int wid = (threadIdx.x >> 5), lane = threadIdx.x & 31;
            float* sw = (float*)smb + wid * 336;
            const int row = lane >> 1, cb4 = (lane & 1) * 8;
            #pragma unroll
            for (int i = 0; i < 4; i++)
                #pragma unroll
                for (int j = 0; j < 2; j++) {
                    wmma::store_matrix_sync(sw, c[i][j], 20, wmma::mem_row_major);
                    __syncwarp();
                    float4 f0 = *(float4*)(sw + row*20 + cb4);
                    float4 f1 = *(float4*)(sw + row*20 + cb4 + 4);
                    __half2 h[4] = {
                        __floats2half2_rn(f0.x, f0.y), __floats2half2_rn(f0.z, f0.w),
                        __floats2half2_rn(f1.x, f1.y), __floats2half2_rn(f1.z, f1.w) };
                    *(uint4*)(g_proj16 + (size_t)(m0 + wm*64 + i*16 + row) * 1024
                              + n0 + wn*32 + j*16 + cb4) = *(uint4*)h;
                    __syncwarp();
                }
        });
}

__global__ __launch_bounds__(256,2) void gemm_wo_k(float* __restrict__ C)
{
    gemm_main(g_att16, g_wo16, blockIdx.y * 128, blockIdx.x * 128,
        [C](HFC (&c)[4][2], __half*, int wm, int wn, int m0, int n0) {
            #pragma unroll
            for (int i = 0; i < 4; i++)
                #pragma unroll
                for (int j = 0; j < 2; j++)
                    wmma::store_matrix_sync(C + (size_t)(m0 + wm*64 + i*16) * 1024
                                            + n0 + wn*32 + j*16,
                                            c[i][j], 1024, wmma::mem_row_major);
        });
}

// ---------------- combine: rank contraction + rotary + scales -> fp16 ----------------
// q pre-scaled by 1/QR/DK * log2(e) so flash can use raw ex2.
__global__ __launch_bounds__(256) void combine_kernel()
{
    const int m = blockIdx.x;
    const int b = m / Sn, s = m % Sn;
    const int t = threadIdx.x;

    __shared__ float rowp[1024];
    __shared__ float sCos[32], sSin[32];

    {
        const uint2 hv = ((const uint2*)(g_proj16 + (size_t)m * 1024))[t];
        __half2 h0 = *(const __half2*)&hv.x;
        __half2 h1 = *(const __half2*)&hv.y;
        float2 f0 = __half22float2(h0), f1 = __half22float2(h1);
        rowp[t*4+0] = f0.x; rowp[t*4+1] = f0.y;
        rowp[t*4+2] = f1.x; rowp[t*4+3] = f1.y;
    }
    if (t < 32) {
        float inv = expf(-((float)(2*t) / 64.f) * logf(10000.0f));
        float fr  = (float)s * inv;
        sCos[t] = cosf(fr);
        sSin[t] = sinf(fr);
    }
    __syncthreads();

    const float qscale = (1.0f / QR) * (1.0f / (float)DKn) * 1.4426950408889634f;

    for (int pi = t; pi < Hn*DKn/2; pi += 256) {
        const int h = pi >> 5, dp = pi & 31, d0 = dp * 2;
        const size_t ob = ((size_t)(b*Hn + h) * Sn + s) * 64 + d0;

        float qv[2], kv[2], vv[2];
        #pragma unroll
        for (int e = 0; e < 2; e++) {
            const int d = d0 + e, dl = d & 31;
            const float cc = sCos[dl], sn = sSin[dl];
            float r1 = 0.f, r2 = 0.f;
            #pragma unroll
            for (int r = 0; r < QR; r++) {
                const float a = rowp[h*QR + r];
                r1 += a * rowp[128 + r*64 + dl];
                r2 += a * rowp[128 + r*64 + dl + 32];
            }
            qv[e] = ((d < 32) ? (r1*cc + r2*sn) : (-r1*sn + r2*cc)) * qscale;

            r1 = 0.f; r2 = 0.f;
            #pragma unroll
            for (int r = 0; r < RK; r++) {
                const float a = rowp[512 + h*RK + r];
                r1 += a * rowp[640 + r*64 + dl];
                r2 += a * rowp[640 + r*64 + dl + 32];
            }
            kv[e] = ((d < 32) ? (r1*cc + r2*sn) : (-r1*sn + r2*cc)) * 0.5f;

            float vs = 0.f;
            #pragma unroll
            for (int r = 0; r < RK; r++)
                vs += rowp[768 + h*RK + r] * rowp[896 + r*64 + d];
            vv[e] = vs * 0.5f;
        }
        *(__half2*)(g_qh16 + ob) = __floats2half2_rn(qv[0], qv[1]);
        *(__half2*)(g_kh16 + ob) = __floats2half2_rn(kv[0], kv[1]);
        *(__half2*)(g_vh16 + ob) = __floats2half2_rn(vv[0], vv[1]);
    }
}

// ---------------- flash attention: fp16, Br=128, Bc=64, 3-stage cp.async, 1 sync/tile ----------------
#define F_K 0
#define F_V (64*72)
#define F_STG (2*64*72)          // halves per stage
#define FSMEM (3*F_STG*2)        // 55296 bytes

__global__ __launch_bounds__(256,2) void flash_mma()
{
    extern __shared__ __align__(16) char fsm[];
    __half* smb = (__half*)fsm;

    const int qt = (gridDim.x - 1) - blockIdx.x;   // heavy tiles first
    const int h = blockIdx.y, b = blockIdx.z;
    const int q0 = qt * 128;

    const size_t hb = (size_t)(b*Hn + h) * Sn * 64;
    const __half* Qg = g_qh16 + hb;
    const __half* Kg = g_kh16 + hb;
    const __half* Vg = g_vh16 + hb;

    const int t = threadIdx.x, w = t >> 5, lane = t & 31;
    const int sub = lane >> 3, r8 = lane & 7;

    // stage Q into buffer 0 region
    {
        const int row = t >> 1, half = (t & 1) * 32;
        const uint4* sh = (const uint4*)(Qg + (size_t)(q0 + row) * 64 + half);
        uint4* dh = (uint4*)(smb + row*72 + half);
        #pragma unroll
        for (int i = 0; i < 4; i++) dh[i] = sh[i];
    }
    __syncthreads();

    // persistent Q fragments
    unsigned qa[4][4];
    {
        const unsigned qoff = ((w*16 + (sub & 1)*8 + r8) * 72 + (sub >> 1) * 8);
        #pragma unroll
        for (int ks = 0; ks < 4; ks++)
            ldsm4(qa[ks], sm_u32(smb + qoff + ks*16));
    }
    __syncthreads();   // Q consumed -> smem reusable for KV stages

    float o[8][4];
    #pragma unroll
    for (int g = 0; g < 8; g++)
        #pragma unroll
        for (int e = 0; e < 4; e++) o[g][e] = 0.f;
    float m0s = -CUDART_INF_F, m1s = -CUDART_INF_F, l0s = 0.f, l1s = 0.f;

    const int nk = 2*qt + 2;
    const int krow = t >> 2, kcoff = (t & 3) * 16;

    auto issue = [&](int kt) {
        const size_t so = (size_t)(kt*64 + krow) * 64 + kcoff;
        const unsigned sb = sm_u32(smb) + ((kt % 3)*F_STG + krow*72 + kcoff) * 2;
        CPA16(sb + F_K*2,      Kg + so);
        CPA16(sb + F_K*2 + 16, Kg + so + 8);
        CPA16(sb + F_V*2,      Vg + so);
        CPA16(sb + F_V*2 + 16, Vg + so + 8);
    };

    issue(0); CPA_COMMIT();
    if (nk > 1) { issue(1); CPA_COMMIT(); }

    for (int kt = 0; kt < nk; kt++) {
        const int k0 = kt * 64;
        CPA_WAIT1();               // group kt landed
        __syncthreads();           // + all warps done with tile kt-1

        if (kt + 2 < nk) { issue(kt + 2); CPA_COMMIT(); }

        const __half* Ksm = smb + (kt % 3)*F_STG + F_K;
        const __half* Vsm = smb + (kt % 3)*F_STG + F_V;

        if (k0 <= q0 + w*16 + 15) {
            float s[8][4];
            #pragma unroll
            for (int g = 0; g < 8; g++)
                #pragma unroll
                for (int e = 0; e < 4; e++) s[g][e] = 0.f;

            // S = Q K^T (scores already in log2 domain via Q pre-scale)
            #pragma unroll
            for (int ks = 0; ks < 4; ks++) {
                #pragma unroll
                for (int jp = 0; jp < 4; jp++) {
                    const unsigned koff = ((jp*16 + (sub>>1)*8 + r8) * 72 + ks*16 + (sub & 1)*8);
                    unsigned bh[4];
                    ldsm4(bh, sm_u32(Ksm + koff));
                    mma16816h(s[2*jp],   qa[ks], bh);
                    mma16816h(s[2*jp+1], qa[ks], bh + 2);
                }
            }

            // causal mask (diagonal-adjacent tiles only)
            if (kt >= 2*qt) {
                const int row0 = q0 + w*16 + (lane >> 2);
                #pragma unroll
                for (int g = 0; g < 8; g++) {
                    const int col = k0 + g*8 + ((lane & 3) << 1);
                    if (col     > row0)     s[g][0] = -CUDART_INF_F;
                    if (col + 1 > row0)     s[g][1] = -CUDART_INF_F;
                    if (col     > row0 + 8) s[g][2] = -CUDART_INF_F;
                    if (col + 1 > row0 + 8) s[g][3] = -CUDART_INF_F;
                }
            }

            // online softmax in log2 domain (rows r0, r0+8)
            float ml0 = -CUDART_INF_F, ml1 = -CUDART_INF_F;
            #pragma unroll
            for (int g = 0; g < 8; g++) {
                ml0 = fmaxf(ml0, fmaxf(s[g][0], s[g][1]));
                ml1 = fmaxf(ml1, fmaxf(s[g][2], s[g][3]));
            }
            ml0 = fmaxf(ml0, __shfl_xor_sync(0xffffffffu, ml0, 1));
            ml0 = fmaxf(ml0, __shfl_xor_sync(0xffffffffu, ml0, 2));
            ml1 = fmaxf(ml1, __shfl_xor_sync(0xffffffffu, ml1, 1));
            ml1 = fmaxf(ml1, __shfl_xor_sync(0xffffffffu, ml1, 2));
            const float mn0 = fmaxf(m0s, ml0), mn1 = fmaxf(m1s, ml1);
            const float a0 = ex2(m0s - mn0), a1 = ex2(m1s - mn1);
            m0s = mn0; m1s = mn1;
            float ps0 = 0.f, ps1 = 0.f;
            #pragma unroll
            for (int g = 0; g < 8; g++) {
                s[g][0] = ex2(s[g][0] - mn0); ps0 += s[g][0];
                s[g][1] = ex2(s[g][1] - mn0); ps0 += s[g][1];
                s[g][2] = ex2(s[g][2] - mn1); ps1 += s[g][2];
                s[g][3] = ex2(s[g][3] - mn1); ps1 += s[g][3];
            }
            ps0 += __shfl_xor_sync(0xffffffffu, ps0, 1);
            ps0 += __shfl_xor_sync(0xffffffffu, ps0, 2);
            ps1 += __shfl_xor_sync(0xffffffffu, ps1, 1);
            ps1 += __shfl_xor_sync(0xffffffffu, ps1, 2);
            l0s = l0s * a0 + ps0;
            l1s = l1s * a1 + ps1;
            #pragma unroll
            for (int g = 0; g < 8; g++) {
                o[g][0] *= a0; o[g][1] *= a0;
                o[g][2] *= a1; o[g][3] *= a1;
            }

            // U += P V
            #pragma unroll
            for (int ksv = 0; ksv < 4; ksv++) {
                const int gA = 2*ksv, gB = gA + 1;
                unsigned pah[4] = { pack_h(s[gA][0], s[gA][1]), pack_h(s[gA][2], s[gA][3]),
                                    pack_h(s[gB][0], s[gB][1]), pack_h(s[gB][2], s[gB][3]) };
                #pragma unroll
                for (int jp = 0; jp < 4; jp++) {
                    const unsigned voff = ((ksv*16 + (sub & 1)*8 + r8) * 72 + (2*jp + (sub >> 1)) * 8);
                    unsigned vh[4];
                    ldsm4t(vh, sm_u32(Vsm + voff));
                    mma16816h(o[2*jp],   pah, vh);
                    mma16816h(o[2*jp+1], pah, vh + 2);
                }
            }
        }
    }

    // epilogue: normalize, store fp16
    const float il0 = 1.0f / l0s, il1 = 1.0f / l1s;
    const int row0 = q0 + w*16 + (lane >> 2);
    #pragma unroll
    for (int g = 0; g < 8; g++) {
        const size_t cb = (size_t)h*64 + g*8 + ((lane & 3) << 1);
        {
            const size_t off = (size_t)(b*Sn + row0) * 1024 + cb;
            *(__half2*)(g_att16 + off) = __floats2half2_rn(o[g][0] * il0, o[g][1] * il0);
        }
        {
            const size_t off = (size_t)(b*Sn + row0 + 8) * 1024 + cb;
            *(__half2*)(g_att16 + off) = __floats2half2_rn(o[g][2] * il1, o[g][3] * il1);
        }
    }
}

// ---------------- launch ----------------
extern "C" void kernel_launch(void* const* d_in, const int* in_sizes, int n_in,
                              void* d_out, int out_size)
{
    const float* q    = (const float*)d_in[0];
    const float* k    = (const float*)d_in[1];
    const float* v    = (const float*)d_in[2];
    const float* W_Aq = (const float*)d_in[4];
    const float* W_Ak = (const float*)d_in[5];
    const float* W_Av = (const float*)d_in[6];
    const float* W_Bq = (const float*)d_in[7];
    const float* W_Bk = (const float*)d_in[8];
    const float* W_Bv = (const float*)d_in[9];
    const float* Wo   = (const float*)d_in[10];
    float* out = (float*)d_out;

    cudaFuncSetAttribute(proj_k,    cudaFuncAttributeMaxDynamicSharedMemorySize, GSMEM);
    cudaFuncSetAttribute(gemm_wo_k, cudaFuncAttributeMaxDynamicSharedMemorySize, GSMEM);
    cudaFuncSetAttribute(flash_mma, cudaFuncAttributeMaxDynamicSharedMemorySize, FSMEM);

    prep_all<<<(PREP_TOT + 255)/256, 256>>>(q, k, v, Wo,
                                            W_Aq, W_Bq, W_Ak, W_Bk, W_Av, W_Bv);

    proj_k<<<dim3(8, Mrows/128), 256, GSMEM>>>();

    combine_kernel<<<Mrows, 256>>>();

    flash_mma<<<dim3(Sn/128, Hn, Bn), 256, FSMEM>>>();

    gemm_wo_k<<<dim3(8, Mrows/128), 256, GSMEM>>>(out);
}